// round 5
// baseline (speedup 1.0000x reference)
#include <cuda_runtime.h>
#include <cstdint>

#define NN (768*768)
#define ST 36            // smem row stride (floats) for 32-wide K chunks

// ---------------- scratch -----------------------------------------------------
__device__ float g_xn[(size_t)NN * 128];   // LN(x), tf32-rounded, [r][d]
__device__ float g_A [(size_t)128 * NN];   // a transposed: [d][i*768+k]
__device__ float g_B [(size_t)128 * NN];   // b transposed: [d][j*768+k]
__device__ float g_T [(size_t)128 * NN];   // t transposed: [d][i*768+j]
__device__ float g_G [(size_t)NN * 128];   // sigmoid(xn @ g_out_w), [r][e]
__device__ float g_Wc[640 * 128];          // rows 0..511: interleaved (g,p); 512..639: g_out_w
__device__ float g_Pw[128 * 128];          // p_out_w tf32

// ---------------- helpers ------------------------------------------------------
__device__ __forceinline__ float tf32r(float x) {
    unsigned u;
    asm("cvt.rna.tf32.f32 %0, %1;" : "=r"(u) : "f"(x));
    return __uint_as_float(u);
}

__device__ __forceinline__ void mma8(float c[4], const unsigned a[4], const unsigned b[2]) {
    asm volatile(
        "mma.sync.aligned.m16n8k8.row.col.f32.tf32.tf32.f32 "
        "{%0,%1,%2,%3},{%4,%5,%6,%7},{%8,%9},{%0,%1,%2,%3};"
        : "+f"(c[0]), "+f"(c[1]), "+f"(c[2]), "+f"(c[3])
        : "r"(a[0]), "r"(a[1]), "r"(a[2]), "r"(a[3]), "r"(b[0]), "r"(b[1]));
}

__device__ __forceinline__ void cpa(void* s, const void* g) {
    unsigned sa = (unsigned)__cvta_generic_to_shared(s);
    asm volatile("cp.async.cg.shared.global [%0], [%1], 16;" :: "r"(sa), "l"(g));
}
__device__ __forceinline__ void cp_commit() { asm volatile("cp.async.commit_group;"); }
template<int Nw> __device__ __forceinline__ void cp_wait() {
    asm volatile("cp.async.wait_group %0;" :: "n"(Nw));
}

// 64x64 warp tile, one K-chunk of 32. sA rows = m (stride ST), sB rows = n (stride ST).
__device__ __forceinline__ void gemm64(const float* sA, const float* sB,
                                       float acc[4][8][4],
                                       int wm, int wn, int qr, int qc) {
#pragma unroll
    for (int k = 0; k < 32; k += 8) {
        unsigned af[4][4], bf[8][2];
#pragma unroll
        for (int mt = 0; mt < 4; mt++) {
            const float* p = sA + (wm + mt * 16 + qr) * ST + k + qc;
            af[mt][0] = __float_as_uint(p[0]);
            af[mt][1] = __float_as_uint(p[8 * ST]);
            af[mt][2] = __float_as_uint(p[4]);
            af[mt][3] = __float_as_uint(p[8 * ST + 4]);
        }
#pragma unroll
        for (int nt = 0; nt < 8; nt++) {
            const float* p = sB + (wn + nt * 8 + qr) * ST + k + qc;
            bf[nt][0] = __float_as_uint(p[0]);
            bf[nt][1] = __float_as_uint(p[4]);
        }
#pragma unroll
        for (int mt = 0; mt < 4; mt++)
#pragma unroll
            for (int nt = 0; nt < 8; nt++)
                mma8(acc[mt][nt], af[mt], bf[nt]);
    }
}

// ---------------- kernel 0: weight prep ----------------------------------------
__global__ void prep_w_kernel(const float* __restrict__ gin, const float* __restrict__ pin,
                              const float* __restrict__ gout, const float* __restrict__ pout) {
    int stride = gridDim.x * blockDim.x;
    for (int idx = blockIdx.x * blockDim.x + threadIdx.x; idx < 256 * 128; idx += stride) {
        int e = idx >> 7, d = idx & 127;
        g_Wc[(2 * e) * 128 + d]     = tf32r(gin[idx]);
        g_Wc[(2 * e + 1) * 128 + d] = tf32r(pin[idx]);
    }
    for (int idx = blockIdx.x * blockDim.x + threadIdx.x; idx < 128 * 128; idx += stride) {
        g_Wc[512 * 128 + idx] = tf32r(gout[idx]);
        g_Pw[idx]             = tf32r(pout[idx]);
    }
}

// ---------------- kernel 1: LayerNorm(x) -> g_xn --------------------------------
__global__ void __launch_bounds__(256) ln_in_kernel(const float* __restrict__ x,
                                                    const float* __restrict__ w,
                                                    const float* __restrict__ b) {
    int warp = threadIdx.x >> 5, lane = threadIdx.x & 31;
    size_t r = (size_t)blockIdx.x * 8 + warp;
    const float4 xv = ((const float4*)(x + r * 128))[lane];
    float s  = xv.x + xv.y + xv.z + xv.w;
    float s2 = xv.x * xv.x + xv.y * xv.y + xv.z * xv.z + xv.w * xv.w;
#pragma unroll
    for (int o = 16; o > 0; o >>= 1) {
        s  += __shfl_xor_sync(0xffffffffu, s,  o);
        s2 += __shfl_xor_sync(0xffffffffu, s2, o);
    }
    float m   = s * (1.0f / 128.0f);
    float var = s2 * (1.0f / 128.0f) - m * m;
    float inv = rsqrtf(var + 1e-5f);
    float4 wv = ((const float4*)w)[lane];
    float4 bv = ((const float4*)b)[lane];
    float4 o4;
    o4.x = tf32r((xv.x - m) * inv * wv.x + bv.x);
    o4.y = tf32r((xv.y - m) * inv * wv.y + bv.y);
    o4.z = tf32r((xv.z - m) * inv * wv.z + bv.z);
    o4.w = tf32r((xv.w - m) * inv * wv.w + bv.w);
    ((float4*)(g_xn + r * 128))[lane] = o4;
}

// ---------------- kernel 2: projections + gate + mask ---------------------------
// CTA tile 256 rows x 128 cols, warps 4x2 of 64x64, K=128 in 4 chunks, 3-stage pipe.
// ntile 0..3: interleaved (g,p) -> gated/masked/transposed into g_A/g_B.
// ntile 4   : g_out gate -> sigmoid -> g_G row-major.
#define PRJ_STG 13824                 // floats per stage: (256+128)*36
__global__ void __launch_bounds__(256, 1) proj_kernel(const float* __restrict__ mask) {
    extern __shared__ float sm[];
    float* msk = sm + 3 * PRJ_STG;
    int ntile = blockIdx.x;
    int rt = blockIdx.y;
    int i = rt / 3, k0 = (rt % 3) * 256;
    int tid = threadIdx.x;

    msk[tid] = mask[i * 768 + k0 + tid];

    const float* Abase = g_xn + (size_t)(i * 768 + k0) * 128;
    const float* Wbase = g_Wc + (size_t)ntile * 128 * 128;

    auto ld = [&](int s, int kc) {
        float* S = sm + s * PRJ_STG;
#pragma unroll
        for (int t = 0; t < 12; t++) {
            int idx = t * 256 + tid;
            int r = idx >> 3, c = (idx & 7) * 4;
            const float* g = (r < 256) ? Abase + (size_t)r * 128 + kc + c
                                       : Wbase + (size_t)(r - 256) * 128 + kc + c;
            cpa(&S[r * ST + c], g);
        }
    };

    int wid = tid >> 5, lane = tid & 31;
    int wm = (wid >> 1) * 64, wn = (wid & 1) * 64;
    int qr = lane >> 2, qc = lane & 3;
    float acc[4][8][4] = {};

    ld(0, 0);  cp_commit();
    ld(1, 32); cp_commit();
#pragma unroll 1
    for (int c = 0; c < 4; c++) {
        cp_wait<1>();
        __syncthreads();
        float* S = sm + (c % 3) * PRJ_STG;
        gemm64(S, S + 256 * ST, acc, wm, wn, qr, qc);
        int kn = (c + 2) * 32;
        if (kn < 128) ld((c + 2) % 3, kn);
        cp_commit();
    }

    if (ntile == 4) {
#pragma unroll
        for (int mt = 0; mt < 4; mt++)
#pragma unroll
            for (int nt = 0; nt < 8; nt++) {
                int rm0 = wm + mt * 16 + qr, rm1 = rm0 + 8;
                int cn = wn + nt * 8 + qc * 2;
                size_t r0 = (size_t)(i * 768 + k0 + rm0) * 128 + cn;
                size_t r1 = (size_t)(i * 768 + k0 + rm1) * 128 + cn;
                *(float2*)&g_G[r0] = make_float2(1.0f / (1.0f + __expf(-acc[mt][nt][0])),
                                                 1.0f / (1.0f + __expf(-acc[mt][nt][1])));
                *(float2*)&g_G[r1] = make_float2(1.0f / (1.0f + __expf(-acc[mt][nt][2])),
                                                 1.0f / (1.0f + __expf(-acc[mt][nt][3])));
            }
        return;
    }

    __syncthreads();                 // all warps done reading stage smem
    float* stg = sm;                 // [64 ch][264]
    bool isA = (ntile < 2);
#pragma unroll
    for (int mt = 0; mt < 4; mt++)
#pragma unroll
        for (int nt = 0; nt < 8; nt++) {
            int rm0 = wm + mt * 16 + qr, rm1 = rm0 + 8;
            int chl = (wn >> 1) + nt * 4 + qc;
            float v0 = acc[mt][nt][1] * (1.0f / (1.0f + __expf(-acc[mt][nt][0])));
            float v1 = acc[mt][nt][3] * (1.0f / (1.0f + __expf(-acc[mt][nt][2])));
            if (isA) { v0 *= msk[rm0]; v1 *= msk[rm1]; }
            stg[chl * 264 + rm0] = tf32r(v0);
            stg[chl * 264 + rm1] = tf32r(v1);
        }
    __syncthreads();

#pragma unroll
    for (int t = 0; t < 16; t++) {
        int idx = t * 256 + tid;          // 0..4095 float4s
        int chl = idx >> 6, k4 = idx & 63;
        float4 v = *(float4*)&stg[chl * 264 + k4 * 4];
        int ch = ntile * 64 + chl;
        float* dst = (ch < 128) ? (g_A + (size_t)ch * NN) : (g_B + (size_t)(ch - 128) * NN);
        *(float4*)&dst[i * 768 + k0 + k4 * 4] = v;
    }
}

// ---------------- kernel 3: batched einsum  t_d = A_d @ B_d^T --------------------
// CTA tile 128 x 256, warps 2x4 of 64x64, K=768 in 24 chunks, 3-stage pipe.
#define BG_STG 13824                  // floats per stage: (128+256)*36
__global__ void __launch_bounds__(256, 1) bgemm_kernel() {
    extern __shared__ float sm[];
    int jt = blockIdx.x, it = blockIdx.y, d = blockIdx.z;
    int tid = threadIdx.x;
    const float* Ab = g_A + (size_t)d * NN + (size_t)(it * 128) * 768;
    const float* Bb = g_B + (size_t)d * NN + (size_t)(jt * 256) * 768;

    auto ld = [&](int s, int kc) {
        float* S = sm + s * BG_STG;
#pragma unroll
        for (int t = 0; t < 12; t++) {
            int idx = t * 256 + tid;
            int r = idx >> 3, c = (idx & 7) * 4;
            const float* g = (r < 128) ? Ab + (size_t)r * 768 + kc + c
                                       : Bb + (size_t)(r - 128) * 768 + kc + c;
            cpa(&S[r * ST + c], g);
        }
    };

    int wid = tid >> 5, lane = tid & 31;
    int wm = (wid >> 2) * 64, wn = (wid & 3) * 64;
    int qr = lane >> 2, qc = lane & 3;
    float acc[4][8][4] = {};

    ld(0, 0);  cp_commit();
    ld(1, 32); cp_commit();
#pragma unroll 1
    for (int c = 0; c < 24; c++) {
        cp_wait<1>();
        __syncthreads();
        float* S = sm + (c % 3) * BG_STG;
        gemm64(S, S + 128 * ST, acc, wm, wn, qr, qc);
        int kn = (c + 2) * 32;
        if (kn < 768) ld((c + 2) % 3, kn);
        cp_commit();
    }

    float* outp = g_T + (size_t)d * NN;
#pragma unroll
    for (int mt = 0; mt < 4; mt++)
#pragma unroll
        for (int nt = 0; nt < 8; nt++) {
            int rm0 = it * 128 + wm + mt * 16 + qr;
            int cn  = jt * 256 + wn + nt * 8 + qc * 2;
            *(float2*)&outp[(size_t)rm0 * 768 + cn]       = make_float2(acc[mt][nt][0], acc[mt][nt][1]);
            *(float2*)&outp[(size_t)(rm0 + 8) * 768 + cn] = make_float2(acc[mt][nt][2], acc[mt][nt][3]);
        }
}

// ---------------- kernel 4: LN(t) over d + output projection + gate -------------
__global__ void __launch_bounds__(256, 2) final_kernel(const float* __restrict__ now_w,
                                                       const float* __restrict__ now_b,
                                                       float* __restrict__ out) {
    extern __shared__ float sm[];
    float* sT    = sm;            // 128 x 68
    float* sW    = sm + 8704;     // 128 x 132
    float* meanv = sm + 25600;    // 64
    float* invv  = sm + 25664;    // 64
    float* wln   = sm + 25728;    // 128
    float* bln   = sm + 25856;    // 128
    int rt = blockIdx.x;
    int i = rt / 12, j0 = (rt % 12) * 64;
    int tid = threadIdx.x;

    if (tid < 128) { wln[tid] = now_w[tid]; bln[tid] = now_b[tid]; }

    const float* Tg = g_T + (size_t)i * 768 + j0;
#pragma unroll
    for (int t = 0; t < 8; t++) {
        int idx = t * 256 + tid;
        int dd = idx >> 4, c4 = (idx & 15) * 4;
        cpa(&sT[dd * 68 + c4], &Tg[(size_t)dd * NN + c4]);
    }
#pragma unroll
    for (int t = 0; t < 16; t++) {
        int idx = t * 256 + tid;
        int r = idx >> 5, c4 = (idx & 31) * 4;
        cpa(&sW[r * 132 + c4], &g_Pw[r * 128 + c4]);
    }
    cp_commit();
    cp_wait<0>();
    __syncthreads();

    {
        int j = tid >> 2, h = tid & 3;
        float s = 0.0f, s2 = 0.0f;
#pragma unroll 4
        for (int dd = h * 32; dd < h * 32 + 32; dd++) {
            float v = sT[dd * 68 + j];
            s += v; s2 += v * v;
        }
        s  += __shfl_xor_sync(0xffffffffu, s,  1);
        s2 += __shfl_xor_sync(0xffffffffu, s2, 1);
        s  += __shfl_xor_sync(0xffffffffu, s,  2);
        s2 += __shfl_xor_sync(0xffffffffu, s2, 2);
        if (h == 0) {
            float m   = s * (1.0f / 128.0f);
            float var = s2 * (1.0f / 128.0f) - m * m;
            meanv[j] = m;
            invv[j]  = rsqrtf(var + 1e-5f);
        }
    }
    __syncthreads();

#pragma unroll
    for (int t = 0; t < 32; t++) {
        int idx = t * 256 + tid;
        int dd = idx >> 6, j = idx & 63;
        float v = sT[dd * 68 + j];
        sT[dd * 68 + j] = tf32r((v - meanv[j]) * invv[j] * wln[dd] + bln[dd]);
    }
    __syncthreads();

    int warp = tid >> 5, lane = tid & 31;
    int wm = (warp >> 2) * 32, wn = (warp & 3) * 32;
    int qr = lane >> 2, qc = lane & 3;
    float acc[2][4][4] = {};

#pragma unroll
    for (int k = 0; k < 128; k += 8) {
        unsigned af[2][4], bf[4][2];
#pragma unroll
        for (int mt = 0; mt < 2; mt++) {
            int r = wm + mt * 16 + qr;
            const float* p0 = sT + (k + qc) * 68 + r;
            const float* p1 = sT + (k + qc + 4) * 68 + r;
            af[mt][0] = __float_as_uint(p0[0]);
            af[mt][1] = __float_as_uint(p0[8]);
            af[mt][2] = __float_as_uint(p1[0]);
            af[mt][3] = __float_as_uint(p1[8]);
        }
#pragma unroll
        for (int nt = 0; nt < 4; nt++) {
            const float* p = sW + (wn + nt * 8 + qr) * 132 + k + qc;
            bf[nt][0] = __float_as_uint(p[0]);
            bf[nt][1] = __float_as_uint(p[4]);
        }
#pragma unroll
        for (int mt = 0; mt < 2; mt++)
#pragma unroll
            for (int nt = 0; nt < 4; nt++)
                mma8(acc[mt][nt], af[mt], bf[nt]);
    }

#pragma unroll
    for (int mt = 0; mt < 2; mt++)
#pragma unroll
        for (int nt = 0; nt < 4; nt++) {
            int rj = wm + mt * 16 + qr;
            int cn = wn + nt * 8 + qc * 2;
            size_t ro0 = (size_t)(i * 768 + j0 + rj) * 128 + cn;
            size_t ro1 = ro0 + 8 * 128;
            float2 gt0 = *(const float2*)&g_G[ro0];
            float2 gt1 = *(const float2*)&g_G[ro1];
            *(float2*)&out[ro0] = make_float2(gt0.x * acc[mt][nt][0], gt0.y * acc[mt][nt][1]);
            *(float2*)&out[ro1] = make_float2(gt1.x * acc[mt][nt][2], gt1.y * acc[mt][nt][3]);
        }
}

// ---------------- launch ---------------------------------------------------------
extern "C" void kernel_launch(void* const* d_in, const int* in_sizes, int n_in,
                              void* d_out, int out_size) {
    const float* x    = (const float*)d_in[0];
    const float* mask = (const float*)d_in[1];
    const float* niw  = (const float*)d_in[2];
    const float* nib  = (const float*)d_in[3];
    const float* giw  = (const float*)d_in[4];
    const float* piw  = (const float*)d_in[5];
    const float* now  = (const float*)d_in[6];
    const float* nob  = (const float*)d_in[7];
    const float* gow  = (const float*)d_in[8];
    const float* pwo  = (const float*)d_in[9];
    float* out = (float*)d_out;

    size_t sm_proj  = (size_t)(3 * PRJ_STG + 256) * 4;   // 166912 B
    size_t sm_bgemm = (size_t)(3 * BG_STG) * 4;          // 165888 B
    size_t sm_final = 25984 * 4;                         // 103936 B
    cudaFuncSetAttribute(proj_kernel,  cudaFuncAttributeMaxDynamicSharedMemorySize, (int)sm_proj);
    cudaFuncSetAttribute(bgemm_kernel, cudaFuncAttributeMaxDynamicSharedMemorySize, (int)sm_bgemm);
    cudaFuncSetAttribute(final_kernel, cudaFuncAttributeMaxDynamicSharedMemorySize, (int)sm_final);

    prep_w_kernel<<<64, 256>>>(giw, piw, gow, pwo);
    ln_in_kernel<<<NN / 8, 256>>>(x, niw, nib);
    proj_kernel<<<dim3(5, 2304), 256, sm_proj>>>(mask);
    bgemm_kernel<<<dim3(3, 6, 128), 256, sm_bgemm>>>();
    final_kernel<<<9216, 256, sm_final>>>(now, nob, out);
}

// round 6
// speedup vs baseline: 1.0699x; 1.0699x over previous
#include <cuda_runtime.h>
#include <cstdint>

#define NN (768*768)
#define ST 36            // smem row stride (floats) for 32-wide K chunks

// ---------------- scratch -----------------------------------------------------
__device__ float g_xn[(size_t)NN * 128];   // LN(x), tf32-rounded, [r][d]
__device__ float g_A [(size_t)128 * NN];   // a transposed: [d][i*768+k]
__device__ float g_B [(size_t)128 * NN];   // b transposed: [d][j*768+k]
__device__ float g_T [(size_t)128 * NN];   // t transposed: [d][i*768+j]
__device__ float g_G [(size_t)NN * 128];   // sigmoid(xn @ g_out_w), [r][e]
__device__ float g_Wc[640 * 128];          // rows 0..511: interleaved (g,p); 512..639: g_out_w
__device__ float g_Pw[128 * 128];          // p_out_w tf32

// ---------------- helpers ------------------------------------------------------
__device__ __forceinline__ float tf32r(float x) {
    unsigned u;
    asm("cvt.rna.tf32.f32 %0, %1;" : "=r"(u) : "f"(x));
    return __uint_as_float(u);
}

__device__ __forceinline__ void mma8(float c[4], const unsigned a[4], const unsigned b[2]) {
    asm volatile(
        "mma.sync.aligned.m16n8k8.row.col.f32.tf32.tf32.f32 "
        "{%0,%1,%2,%3},{%4,%5,%6,%7},{%8,%9},{%0,%1,%2,%3};"
        : "+f"(c[0]), "+f"(c[1]), "+f"(c[2]), "+f"(c[3])
        : "r"(a[0]), "r"(a[1]), "r"(a[2]), "r"(a[3]), "r"(b[0]), "r"(b[1]));
}

__device__ __forceinline__ void cpa(void* s, const void* g) {
    unsigned sa = (unsigned)__cvta_generic_to_shared(s);
    asm volatile("cp.async.cg.shared.global [%0], [%1], 16;" :: "r"(sa), "l"(g));
}
__device__ __forceinline__ void cp_commit() { asm volatile("cp.async.commit_group;"); }
template<int Nw> __device__ __forceinline__ void cp_wait() {
    asm volatile("cp.async.wait_group %0;" :: "n"(Nw));
}

// 64x64 warp tile, one K-chunk of 32. sA rows = m (stride ST), sB rows = n (stride ST).
__device__ __forceinline__ void gemm64(const float* sA, const float* sB,
                                       float acc[4][8][4],
                                       int wm, int wn, int qr, int qc) {
#pragma unroll
    for (int k = 0; k < 32; k += 8) {
        unsigned af[4][4], bf[8][2];
#pragma unroll
        for (int mt = 0; mt < 4; mt++) {
            const float* p = sA + (wm + mt * 16 + qr) * ST + k + qc;
            af[mt][0] = __float_as_uint(p[0]);
            af[mt][1] = __float_as_uint(p[8 * ST]);
            af[mt][2] = __float_as_uint(p[4]);
            af[mt][3] = __float_as_uint(p[8 * ST + 4]);
        }
#pragma unroll
        for (int nt = 0; nt < 8; nt++) {
            const float* p = sB + (wn + nt * 8 + qr) * ST + k + qc;
            bf[nt][0] = __float_as_uint(p[0]);
            bf[nt][1] = __float_as_uint(p[4]);
        }
#pragma unroll
        for (int mt = 0; mt < 4; mt++)
#pragma unroll
            for (int nt = 0; nt < 8; nt++)
                mma8(acc[mt][nt], af[mt], bf[nt]);
    }
}

// ---------------- kernel 0: weight prep ----------------------------------------
__global__ void prep_w_kernel(const float* __restrict__ gin, const float* __restrict__ pin,
                              const float* __restrict__ gout, const float* __restrict__ pout) {
    int stride = gridDim.x * blockDim.x;
    for (int idx = blockIdx.x * blockDim.x + threadIdx.x; idx < 256 * 128; idx += stride) {
        int e = idx >> 7, d = idx & 127;
        g_Wc[(2 * e) * 128 + d]     = tf32r(gin[idx]);
        g_Wc[(2 * e + 1) * 128 + d] = tf32r(pin[idx]);
    }
    for (int idx = blockIdx.x * blockDim.x + threadIdx.x; idx < 128 * 128; idx += stride) {
        g_Wc[512 * 128 + idx] = tf32r(gout[idx]);
        g_Pw[idx]             = tf32r(pout[idx]);
    }
}

// ---------------- kernel 1: LayerNorm(x) -> g_xn --------------------------------
__global__ void __launch_bounds__(256) ln_in_kernel(const float* __restrict__ x,
                                                    const float* __restrict__ w,
                                                    const float* __restrict__ b) {
    int warp = threadIdx.x >> 5, lane = threadIdx.x & 31;
    size_t r = (size_t)blockIdx.x * 8 + warp;
    const float4 xv = ((const float4*)(x + r * 128))[lane];
    float s  = xv.x + xv.y + xv.z + xv.w;
    float s2 = xv.x * xv.x + xv.y * xv.y + xv.z * xv.z + xv.w * xv.w;
#pragma unroll
    for (int o = 16; o > 0; o >>= 1) {
        s  += __shfl_xor_sync(0xffffffffu, s,  o);
        s2 += __shfl_xor_sync(0xffffffffu, s2, o);
    }
    float m   = s * (1.0f / 128.0f);
    float var = s2 * (1.0f / 128.0f) - m * m;
    float inv = rsqrtf(var + 1e-5f);
    float4 wv = ((const float4*)w)[lane];
    float4 bv = ((const float4*)b)[lane];
    float4 o4;
    o4.x = tf32r((xv.x - m) * inv * wv.x + bv.x);
    o4.y = tf32r((xv.y - m) * inv * wv.y + bv.y);
    o4.z = tf32r((xv.z - m) * inv * wv.z + bv.z);
    o4.w = tf32r((xv.w - m) * inv * wv.w + bv.w);
    ((float4*)(g_xn + r * 128))[lane] = o4;
}

// ---------------- kernel 2: projections + gate + mask ---------------------------
// CTA tile 128 rows x 128 cols, 4 warps of 64x64, K=128 in 4 chunks, 3-stage pipe,
// 2 CTAs/SM. ntile 0..3: interleaved (g,p) -> gated/masked/transposed into g_A/g_B.
// ntile 4: g_out gate -> sigmoid -> g_G row-major.
#define STG_F 9216                     // floats per stage: (128+128)*36
__global__ void __launch_bounds__(128, 2) proj_kernel(const float* __restrict__ mask) {
    extern __shared__ float sm[];
    float* msk = sm + 3 * STG_F;
    int ntile = blockIdx.x;
    int rt = blockIdx.y;
    int i = rt / 6, k0 = (rt % 6) * 128;
    int tid = threadIdx.x;

    msk[tid] = mask[i * 768 + k0 + tid];

    const float* Abase = g_xn + (size_t)(i * 768 + k0) * 128;
    const float* Wbase = g_Wc + (size_t)ntile * 128 * 128;

    auto ld = [&](int s, int kc) {
        float* S = sm + s * STG_F;
#pragma unroll
        for (int t = 0; t < 16; t++) {
            int idx = t * 128 + tid;
            int r = idx >> 3, c = (idx & 7) * 4;
            const float* g = (r < 128) ? Abase + (size_t)r * 128 + kc + c
                                       : Wbase + (size_t)(r - 128) * 128 + kc + c;
            cpa(&S[r * ST + c], g);
        }
    };

    int wid = tid >> 5, lane = tid & 31;
    int wm = (wid >> 1) * 64, wn = (wid & 1) * 64;
    int qr = lane >> 2, qc = lane & 3;
    float acc[4][8][4] = {};

    ld(0, 0);  cp_commit();
    ld(1, 32); cp_commit();
#pragma unroll 1
    for (int c = 0; c < 4; c++) {
        cp_wait<1>();
        __syncthreads();
        float* S = sm + (c % 3) * STG_F;
        gemm64(S, S + 128 * ST, acc, wm, wn, qr, qc);
        int kn = (c + 2) * 32;
        if (kn < 128) ld((c + 2) % 3, kn);
        cp_commit();
    }

    if (ntile == 4) {
#pragma unroll
        for (int mt = 0; mt < 4; mt++)
#pragma unroll
            for (int nt = 0; nt < 8; nt++) {
                int rm0 = wm + mt * 16 + qr, rm1 = rm0 + 8;
                int cn = wn + nt * 8 + qc * 2;
                size_t r0 = (size_t)(i * 768 + k0 + rm0) * 128 + cn;
                size_t r1 = (size_t)(i * 768 + k0 + rm1) * 128 + cn;
                *(float2*)&g_G[r0] = make_float2(1.0f / (1.0f + __expf(-acc[mt][nt][0])),
                                                 1.0f / (1.0f + __expf(-acc[mt][nt][1])));
                *(float2*)&g_G[r1] = make_float2(1.0f / (1.0f + __expf(-acc[mt][nt][2])),
                                                 1.0f / (1.0f + __expf(-acc[mt][nt][3])));
            }
        return;
    }

    __syncthreads();                 // all warps done reading stage smem
    float* stg = sm;                 // [64 ch][132]
    bool isA = (ntile < 2);
#pragma unroll
    for (int mt = 0; mt < 4; mt++)
#pragma unroll
        for (int nt = 0; nt < 8; nt++) {
            int rm0 = wm + mt * 16 + qr, rm1 = rm0 + 8;
            int chl = (wn >> 1) + nt * 4 + qc;
            float v0 = acc[mt][nt][1] * (1.0f / (1.0f + __expf(-acc[mt][nt][0])));
            float v1 = acc[mt][nt][3] * (1.0f / (1.0f + __expf(-acc[mt][nt][2])));
            if (isA) { v0 *= msk[rm0]; v1 *= msk[rm1]; }
            stg[chl * 132 + rm0] = tf32r(v0);
            stg[chl * 132 + rm1] = tf32r(v1);
        }
    __syncthreads();

#pragma unroll
    for (int t = 0; t < 16; t++) {
        int idx = t * 128 + tid;          // 0..2047 float4s
        int chl = idx >> 5, k4 = idx & 31;
        float4 v = *(float4*)&stg[chl * 132 + k4 * 4];
        int ch = ntile * 64 + chl;
        float* dst = (ch < 128) ? (g_A + (size_t)ch * NN) : (g_B + (size_t)(ch - 128) * NN);
        *(float4*)&dst[i * 768 + k0 + k4 * 4] = v;
    }
}

// ---------------- kernel 3: batched einsum  t_d = A_d @ B_d^T --------------------
// CTA tile 128 x 128, 4 warps of 64x64, K=768 in 24 chunks, 3-stage pipe, 2 CTAs/SM.
__global__ void __launch_bounds__(128, 2) bgemm_kernel() {
    extern __shared__ float sm[];
    int jt = blockIdx.x, it = blockIdx.y, d = blockIdx.z;
    int tid = threadIdx.x;
    const float* Ab = g_A + (size_t)d * NN + (size_t)(it * 128) * 768;
    const float* Bb = g_B + (size_t)d * NN + (size_t)(jt * 128) * 768;

    auto ld = [&](int s, int kc) {
        float* S = sm + s * STG_F;
#pragma unroll
        for (int t = 0; t < 16; t++) {
            int idx = t * 128 + tid;
            int r = idx >> 3, c = (idx & 7) * 4;
            const float* g = (r < 128) ? Ab + (size_t)r * 768 + kc + c
                                       : Bb + (size_t)(r - 128) * 768 + kc + c;
            cpa(&S[r * ST + c], g);
        }
    };

    int wid = tid >> 5, lane = tid & 31;
    int wm = (wid >> 1) * 64, wn = (wid & 1) * 64;
    int qr = lane >> 2, qc = lane & 3;
    float acc[4][8][4] = {};

    ld(0, 0);  cp_commit();
    ld(1, 32); cp_commit();
#pragma unroll 1
    for (int c = 0; c < 24; c++) {
        cp_wait<1>();
        __syncthreads();
        float* S = sm + (c % 3) * STG_F;
        gemm64(S, S + 128 * ST, acc, wm, wn, qr, qc);
        int kn = (c + 2) * 32;
        if (kn < 768) ld((c + 2) % 3, kn);
        cp_commit();
    }

    float* outp = g_T + (size_t)d * NN;
#pragma unroll
    for (int mt = 0; mt < 4; mt++)
#pragma unroll
        for (int nt = 0; nt < 8; nt++) {
            int rm0 = it * 128 + wm + mt * 16 + qr;
            int cn  = jt * 128 + wn + nt * 8 + qc * 2;
            *(float2*)&outp[(size_t)rm0 * 768 + cn]       = make_float2(acc[mt][nt][0], acc[mt][nt][1]);
            *(float2*)&outp[(size_t)(rm0 + 8) * 768 + cn] = make_float2(acc[mt][nt][2], acc[mt][nt][3]);
        }
}

// ---------------- kernel 4: LN(t) over d + output projection + gate -------------
__global__ void __launch_bounds__(256, 2) final_kernel(const float* __restrict__ now_w,
                                                       const float* __restrict__ now_b,
                                                       float* __restrict__ out) {
    extern __shared__ float sm[];
    float* sT    = sm;            // 128 x 68
    float* sW    = sm + 8704;     // 128 x 132
    float* meanv = sm + 25600;    // 64
    float* invv  = sm + 25664;    // 64
    float* wln   = sm + 25728;    // 128
    float* bln   = sm + 25856;    // 128
    int rt = blockIdx.x;
    int i = rt / 12, j0 = (rt % 12) * 64;
    int tid = threadIdx.x;

    if (tid < 128) { wln[tid] = now_w[tid]; bln[tid] = now_b[tid]; }

    const float* Tg = g_T + (size_t)i * 768 + j0;
#pragma unroll
    for (int t = 0; t < 8; t++) {
        int idx = t * 256 + tid;
        int dd = idx >> 4, c4 = (idx & 15) * 4;
        cpa(&sT[dd * 68 + c4], &Tg[(size_t)dd * NN + c4]);
    }
#pragma unroll
    for (int t = 0; t < 16; t++) {
        int idx = t * 256 + tid;
        int r = idx >> 5, c4 = (idx & 31) * 4;
        cpa(&sW[r * 132 + c4], &g_Pw[r * 128 + c4]);
    }
    cp_commit();
    cp_wait<0>();
    __syncthreads();

    {
        int j = tid >> 2, h = tid & 3;
        float s = 0.0f, s2 = 0.0f;
#pragma unroll 4
        for (int dd = h * 32; dd < h * 32 + 32; dd++) {
            float v = sT[dd * 68 + j];
            s += v; s2 += v * v;
        }
        s  += __shfl_xor_sync(0xffffffffu, s,  1);
        s2 += __shfl_xor_sync(0xffffffffu, s2, 1);
        s  += __shfl_xor_sync(0xffffffffu, s,  2);
        s2 += __shfl_xor_sync(0xffffffffu, s2, 2);
        if (h == 0) {
            float m   = s * (1.0f / 128.0f);
            float var = s2 * (1.0f / 128.0f) - m * m;
            meanv[j] = m;
            invv[j]  = rsqrtf(var + 1e-5f);
        }
    }
    __syncthreads();

#pragma unroll
    for (int t = 0; t < 32; t++) {
        int idx = t * 256 + tid;
        int dd = idx >> 6, j = idx & 63;
        float v = sT[dd * 68 + j];
        sT[dd * 68 + j] = tf32r((v - meanv[j]) * invv[j] * wln[dd] + bln[dd]);
    }
    __syncthreads();

    int warp = tid >> 5, lane = tid & 31;
    int wm = (warp >> 2) * 32, wn = (warp & 3) * 32;
    int qr = lane >> 2, qc = lane & 3;
    float acc[2][4][4] = {};

#pragma unroll
    for (int k = 0; k < 128; k += 8) {
        unsigned af[2][4], bf[4][2];
#pragma unroll
        for (int mt = 0; mt < 2; mt++) {
            int r = wm + mt * 16 + qr;
            const float* p0 = sT + (k + qc) * 68 + r;
            const float* p1 = sT + (k + qc + 4) * 68 + r;
            af[mt][0] = __float_as_uint(p0[0]);
            af[mt][1] = __float_as_uint(p0[8]);
            af[mt][2] = __float_as_uint(p1[0]);
            af[mt][3] = __float_as_uint(p1[8]);
        }
#pragma unroll
        for (int nt = 0; nt < 4; nt++) {
            const float* p = sW + (wn + nt * 8 + qr) * 132 + k + qc;
            bf[nt][0] = __float_as_uint(p[0]);
            bf[nt][1] = __float_as_uint(p[4]);
        }
#pragma unroll
        for (int mt = 0; mt < 2; mt++)
#pragma unroll
            for (int nt = 0; nt < 4; nt++)
                mma8(acc[mt][nt], af[mt], bf[nt]);
    }

#pragma unroll
    for (int mt = 0; mt < 2; mt++)
#pragma unroll
        for (int nt = 0; nt < 4; nt++) {
            int rj = wm + mt * 16 + qr;
            int cn = wn + nt * 8 + qc * 2;
            size_t ro0 = (size_t)(i * 768 + j0 + rj) * 128 + cn;
            size_t ro1 = ro0 + 8 * 128;
            float2 gt0 = *(const float2*)&g_G[ro0];
            float2 gt1 = *(const float2*)&g_G[ro1];
            *(float2*)&out[ro0] = make_float2(gt0.x * acc[mt][nt][0], gt0.y * acc[mt][nt][1]);
            *(float2*)&out[ro1] = make_float2(gt1.x * acc[mt][nt][2], gt1.y * acc[mt][nt][3]);
        }
}

// ---------------- launch ---------------------------------------------------------
extern "C" void kernel_launch(void* const* d_in, const int* in_sizes, int n_in,
                              void* d_out, int out_size) {
    const float* x    = (const float*)d_in[0];
    const float* mask = (const float*)d_in[1];
    const float* niw  = (const float*)d_in[2];
    const float* nib  = (const float*)d_in[3];
    const float* giw  = (const float*)d_in[4];
    const float* piw  = (const float*)d_in[5];
    const float* now  = (const float*)d_in[6];
    const float* nob  = (const float*)d_in[7];
    const float* gow  = (const float*)d_in[8];
    const float* pwo  = (const float*)d_in[9];
    float* out = (float*)d_out;

    size_t sm_proj  = (size_t)(3 * STG_F + 128) * 4;   // 111104 B
    size_t sm_bgemm = (size_t)(3 * STG_F) * 4;         // 110592 B
    size_t sm_final = 25984 * 4;                       // 103936 B
    cudaFuncSetAttribute(proj_kernel,  cudaFuncAttributeMaxDynamicSharedMemorySize, (int)sm_proj);
    cudaFuncSetAttribute(bgemm_kernel, cudaFuncAttributeMaxDynamicSharedMemorySize, (int)sm_bgemm);
    cudaFuncSetAttribute(final_kernel, cudaFuncAttributeMaxDynamicSharedMemorySize, (int)sm_final);

    prep_w_kernel<<<64, 256>>>(giw, piw, gow, pwo);
    ln_in_kernel<<<NN / 8, 256>>>(x, niw, nib);
    proj_kernel<<<dim3(5, 4608), 128, sm_proj>>>(mask);
    bgemm_kernel<<<dim3(6, 6, 128), 128, sm_bgemm>>>();
    final_kernel<<<9216, 256, sm_final>>>(now, nob, out);
}

// round 7
// speedup vs baseline: 1.1053x; 1.0331x over previous
#include <cuda_runtime.h>
#include <cstdint>

#define NN (768*768)
#define ST 36            // smem row stride (floats) for 32-wide K chunks
#define PCH 4608         // floats per 128x36 chunk buffer

// ---------------- scratch -----------------------------------------------------
__device__ float g_A [(size_t)128 * NN];   // a transposed: [d][i*768+k]
__device__ float g_B [(size_t)128 * NN];   // b transposed: [d][j*768+k]
__device__ float g_T [(size_t)128 * NN];   // t transposed: [d][i*768+j]
__device__ float g_G [(size_t)NN * 128];   // sigmoid(xn @ g_out_w), [r][e]
__device__ float g_Wc[640 * 128];          // rows 0..511: interleaved (g,p); 512..639: g_out_w
__device__ float g_Pw[128 * 128];          // p_out_w tf32

// ---------------- helpers ------------------------------------------------------
__device__ __forceinline__ float tf32r(float x) {
    unsigned u;
    asm("cvt.rna.tf32.f32 %0, %1;" : "=r"(u) : "f"(x));
    return __uint_as_float(u);
}

__device__ __forceinline__ void mma8(float c[4], const unsigned a[4], const unsigned b[2]) {
    asm volatile(
        "mma.sync.aligned.m16n8k8.row.col.f32.tf32.tf32.f32 "
        "{%0,%1,%2,%3},{%4,%5,%6,%7},{%8,%9},{%0,%1,%2,%3};"
        : "+f"(c[0]), "+f"(c[1]), "+f"(c[2]), "+f"(c[3])
        : "r"(a[0]), "r"(a[1]), "r"(a[2]), "r"(a[3]), "r"(b[0]), "r"(b[1]));
}

__device__ __forceinline__ void cpa(void* s, const void* g) {
    unsigned sa = (unsigned)__cvta_generic_to_shared(s);
    asm volatile("cp.async.cg.shared.global [%0], [%1], 16;" :: "r"(sa), "l"(g));
}
__device__ __forceinline__ void cp_commit() { asm volatile("cp.async.commit_group;"); }
template<int Nw> __device__ __forceinline__ void cp_wait() {
    asm volatile("cp.async.wait_group %0;" :: "n"(Nw));
}

// 64x64 warp tile, one K-chunk of 32 (bgemm).
__device__ __forceinline__ void gemm64(const float* sA, const float* sB,
                                       float acc[4][8][4],
                                       int wm, int wn, int qr, int qc) {
#pragma unroll
    for (int k = 0; k < 32; k += 8) {
        unsigned af[4][4], bf[8][2];
#pragma unroll
        for (int mt = 0; mt < 4; mt++) {
            const float* p = sA + (wm + mt * 16 + qr) * ST + k + qc;
            af[mt][0] = __float_as_uint(p[0]);
            af[mt][1] = __float_as_uint(p[8 * ST]);
            af[mt][2] = __float_as_uint(p[4]);
            af[mt][3] = __float_as_uint(p[8 * ST + 4]);
        }
#pragma unroll
        for (int nt = 0; nt < 8; nt++) {
            const float* p = sB + (wn + nt * 8 + qr) * ST + k + qc;
            bf[nt][0] = __float_as_uint(p[0]);
            bf[nt][1] = __float_as_uint(p[4]);
        }
#pragma unroll
        for (int mt = 0; mt < 4; mt++)
#pragma unroll
            for (int nt = 0; nt < 8; nt++)
                mma8(acc[mt][nt], af[mt], bf[nt]);
    }
}

// 64x32 warp tile, one K-chunk of 32 (proj).
__device__ __forceinline__ void gemm_c32(const float* sA, const float* sB,
                                         float acc[4][4][4],
                                         int wm, int wn, int qr, int qc) {
#pragma unroll
    for (int k = 0; k < 32; k += 8) {
        unsigned af[4][4], bf[4][2];
#pragma unroll
        for (int mt = 0; mt < 4; mt++) {
            const float* p = sA + (wm + mt * 16 + qr) * ST + k + qc;
            af[mt][0] = __float_as_uint(p[0]);
            af[mt][1] = __float_as_uint(p[8 * ST]);
            af[mt][2] = __float_as_uint(p[4]);
            af[mt][3] = __float_as_uint(p[8 * ST + 4]);
        }
#pragma unroll
        for (int nt = 0; nt < 4; nt++) {
            const float* p = sB + (wn + nt * 8 + qr) * ST + k + qc;
            bf[nt][0] = __float_as_uint(p[0]);
            bf[nt][1] = __float_as_uint(p[4]);
        }
#pragma unroll
        for (int mt = 0; mt < 4; mt++)
#pragma unroll
            for (int nt = 0; nt < 4; nt++)
                mma8(acc[mt][nt], af[mt], bf[nt]);
    }
}

// ---------------- kernel 0: weight prep ----------------------------------------
__global__ void prep_w_kernel(const float* __restrict__ gin, const float* __restrict__ pin,
                              const float* __restrict__ gout, const float* __restrict__ pout) {
    int stride = gridDim.x * blockDim.x;
    for (int idx = blockIdx.x * blockDim.x + threadIdx.x; idx < 256 * 128; idx += stride) {
        int e = idx >> 7, d = idx & 127;
        g_Wc[(2 * e) * 128 + d]     = tf32r(gin[idx]);
        g_Wc[(2 * e + 1) * 128 + d] = tf32r(pin[idx]);
    }
    for (int idx = blockIdx.x * blockDim.x + threadIdx.x; idx < 128 * 128; idx += stride) {
        g_Wc[512 * 128 + idx] = tf32r(gout[idx]);
        g_Pw[idx]             = tf32r(pout[idx]);
    }
}

// ---------------- kernel 1: fused LN(x) + projections + gate + mask -------------
// 256 thr, CTA tile 128x128, warps 2x4 of 64x32, 2 CTAs/SM.
// A: all 4 K-chunks of raw x prefetched up front (1 group), LN'd in smem.
// W: 2-stage streamed. ntile 0..3 -> g_A/g_B; ntile 4 -> g_G.
__global__ void __launch_bounds__(256, 2) proj_kernel(const float* __restrict__ x,
                                                      const float* __restrict__ mask,
                                                      const float* __restrict__ niw,
                                                      const float* __restrict__ nib) {
    extern __shared__ float sm[];
    float* msk = sm + 6 * PCH;         // 128
    float* wv  = msk + 128;            // 128
    float* bv  = wv + 128;             // 128
    int ntile = blockIdx.x;
    int rt = blockIdx.y;
    int i = rt / 6, k0 = (rt % 6) * 128;
    int tid = threadIdx.x;

    if (tid < 128) {
        msk[tid] = mask[i * 768 + k0 + tid];
        wv[tid]  = niw[tid];
        bv[tid]  = nib[tid];
    }

    const float* Xb = x + (size_t)(i * 768 + k0) * 128;
    const float* Wb = g_Wc + (size_t)ntile * 128 * 128;

    // A: all 4 chunks, one group
#pragma unroll
    for (int c = 0; c < 4; c++)
#pragma unroll
        for (int t = 0; t < 4; t++) {
            int idx = t * 256 + tid;
            int r = idx >> 3, cc = (idx & 7) * 4;
            cpa(sm + c * PCH + r * ST + cc, Xb + (size_t)r * 128 + c * 32 + cc);
        }
    cp_commit();
    // W chunks 0,1 (one group each)
#pragma unroll
    for (int s = 0; s < 2; s++) {
#pragma unroll
        for (int t = 0; t < 4; t++) {
            int idx = t * 256 + tid;
            int r = idx >> 3, cc = (idx & 7) * 4;
            cpa(sm + (4 + s) * PCH + r * ST + cc, Wb + (size_t)r * 128 + s * 32 + cc);
        }
        cp_commit();
    }

    cp_wait<2>();        // A group complete (W0/W1 may still be in flight)
    __syncthreads();

    // In-smem LayerNorm: 4 threads per row, k = 4*kk + h (conflict-free).
    {
        int h = tid & 3, q = tid >> 2;        // q: 0..63
#pragma unroll
        for (int pass = 0; pass < 2; pass++) {
            int r = pass * 64 + q;
            float s = 0.0f, s2 = 0.0f;
#pragma unroll
            for (int kk = 0; kk < 32; kk++) {
                int kg = 4 * kk + h;
                float v = sm[(kg >> 5) * PCH + r * ST + (kg & 31)];
                s += v; s2 += v * v;
            }
            s  += __shfl_xor_sync(0xffffffffu, s,  1);
            s2 += __shfl_xor_sync(0xffffffffu, s2, 1);
            s  += __shfl_xor_sync(0xffffffffu, s,  2);
            s2 += __shfl_xor_sync(0xffffffffu, s2, 2);
            float m   = s * (1.0f / 128.0f);
            float var = s2 * (1.0f / 128.0f) - m * m;
            float inv = rsqrtf(var + 1e-5f);
#pragma unroll
            for (int kk = 0; kk < 32; kk++) {
                int kg = 4 * kk + h;
                float* p = sm + (kg >> 5) * PCH + r * ST + (kg & 31);
                *p = tf32r((*p - m) * inv * wv[kg] + bv[kg]);
            }
        }
    }

    int warp = tid >> 5, lane = tid & 31;
    int wm = (warp >> 2) * 64, wn = (warp & 3) * 32;
    int qr = lane >> 2, qc = lane & 3;
    float acc[4][4][4] = {};

#pragma unroll 1
    for (int c = 0; c < 4; c++) {
        cp_wait<1>();
        __syncthreads();               // also publishes LN writes on c==0
        gemm_c32(sm + c * PCH, sm + (4 + (c & 1)) * PCH, acc, wm, wn, qr, qc);
        __syncthreads();               // all reads of PW(c&1) done before refill
        if (c < 2) {
#pragma unroll
            for (int t = 0; t < 4; t++) {
                int idx = t * 256 + tid;
                int r = idx >> 3, cc = (idx & 7) * 4;
                cpa(sm + (4 + (c & 1)) * PCH + r * ST + cc,
                    Wb + (size_t)r * 128 + (c + 2) * 32 + cc);
            }
        }
        cp_commit();
    }

    if (ntile == 4) {
#pragma unroll
        for (int mt = 0; mt < 4; mt++)
#pragma unroll
            for (int nt = 0; nt < 4; nt++) {
                int rm0 = wm + mt * 16 + qr, rm1 = rm0 + 8;
                int cn = wn + nt * 8 + qc * 2;
                size_t r0 = (size_t)(i * 768 + k0 + rm0) * 128 + cn;
                size_t r1 = (size_t)(i * 768 + k0 + rm1) * 128 + cn;
                *(float2*)&g_G[r0] = make_float2(1.0f / (1.0f + __expf(-acc[mt][nt][0])),
                                                 1.0f / (1.0f + __expf(-acc[mt][nt][1])));
                *(float2*)&g_G[r1] = make_float2(1.0f / (1.0f + __expf(-acc[mt][nt][2])),
                                                 1.0f / (1.0f + __expf(-acc[mt][nt][3])));
            }
        return;
    }

    // gated/masked epilogue, transpose through smem (reuse chunk buffers 0-1)
    float* stg = sm;                 // [64 ch][132]
    bool isA = (ntile < 2);
#pragma unroll
    for (int mt = 0; mt < 4; mt++)
#pragma unroll
        for (int nt = 0; nt < 4; nt++) {
            int rm0 = wm + mt * 16 + qr, rm1 = rm0 + 8;
            int chl = (wn >> 1) + nt * 4 + qc;
            float v0 = acc[mt][nt][1] * (1.0f / (1.0f + __expf(-acc[mt][nt][0])));
            float v1 = acc[mt][nt][3] * (1.0f / (1.0f + __expf(-acc[mt][nt][2])));
            if (isA) { v0 *= msk[rm0]; v1 *= msk[rm1]; }
            stg[chl * 132 + rm0] = tf32r(v0);
            stg[chl * 132 + rm1] = tf32r(v1);
        }
    __syncthreads();

#pragma unroll
    for (int t = 0; t < 8; t++) {
        int idx = t * 256 + tid;          // 0..2047 float4s
        int chl = idx >> 5, k4 = idx & 31;
        float4 v = *(float4*)&stg[chl * 132 + k4 * 4];
        int ch = ntile * 64 + chl;
        float* dst = (ch < 128) ? (g_A + (size_t)ch * NN) : (g_B + (size_t)(ch - 128) * NN);
        *(float4*)&dst[i * 768 + k0 + k4 * 4] = v;
    }
}

// ---------------- kernel 2: batched einsum  t_d = A_d @ B_d^T --------------------
// CTA tile 128 x 128, 4 warps of 64x64, K=768 in 24 chunks, 3-stage pipe, 2 CTAs/SM.
#define STG_F 9216
__global__ void __launch_bounds__(128, 2) bgemm_kernel() {
    extern __shared__ float sm[];
    int jt = blockIdx.x, it = blockIdx.y, d = blockIdx.z;
    int tid = threadIdx.x;
    const float* Ab = g_A + (size_t)d * NN + (size_t)(it * 128) * 768;
    const float* Bb = g_B + (size_t)d * NN + (size_t)(jt * 128) * 768;

    auto ld = [&](int s, int kc) {
        float* S = sm + s * STG_F;
#pragma unroll
        for (int t = 0; t < 16; t++) {
            int idx = t * 128 + tid;
            int r = idx >> 3, c = (idx & 7) * 4;
            const float* g = (r < 128) ? Ab + (size_t)r * 768 + kc + c
                                       : Bb + (size_t)(r - 128) * 768 + kc + c;
            cpa(&S[r * ST + c], g);
        }
    };

    int wid = tid >> 5, lane = tid & 31;
    int wm = (wid >> 1) * 64, wn = (wid & 1) * 64;
    int qr = lane >> 2, qc = lane & 3;
    float acc[4][8][4] = {};

    ld(0, 0);  cp_commit();
    ld(1, 32); cp_commit();
#pragma unroll 1
    for (int c = 0; c < 24; c++) {
        cp_wait<1>();
        __syncthreads();
        float* S = sm + (c % 3) * STG_F;
        gemm64(S, S + 128 * ST, acc, wm, wn, qr, qc);
        int kn = (c + 2) * 32;
        if (kn < 768) ld((c + 2) % 3, kn);
        cp_commit();
    }

    float* outp = g_T + (size_t)d * NN;
#pragma unroll
    for (int mt = 0; mt < 4; mt++)
#pragma unroll
        for (int nt = 0; nt < 8; nt++) {
            int rm0 = it * 128 + wm + mt * 16 + qr;
            int cn  = jt * 128 + wn + nt * 8 + qc * 2;
            *(float2*)&outp[(size_t)rm0 * 768 + cn]       = make_float2(acc[mt][nt][0], acc[mt][nt][1]);
            *(float2*)&outp[(size_t)(rm0 + 8) * 768 + cn] = make_float2(acc[mt][nt][2], acc[mt][nt][3]);
        }
}

// ---------------- kernel 3: LN(t) over d + output projection + gate -------------
__global__ void __launch_bounds__(256, 2) final_kernel(const float* __restrict__ now_w,
                                                       const float* __restrict__ now_b,
                                                       float* __restrict__ out) {
    extern __shared__ float sm[];
    float* sT    = sm;            // 128 x 68
    float* sW    = sm + 8704;     // 128 x 132
    float* meanv = sm + 25600;    // 64
    float* invv  = sm + 25664;    // 64
    float* wln   = sm + 25728;    // 128
    float* bln   = sm + 25856;    // 128
    int rt = blockIdx.x;
    int i = rt / 12, j0 = (rt % 12) * 64;
    int tid = threadIdx.x;

    if (tid < 128) { wln[tid] = now_w[tid]; bln[tid] = now_b[tid]; }

    const float* Tg = g_T + (size_t)i * 768 + j0;
#pragma unroll
    for (int t = 0; t < 8; t++) {
        int idx = t * 256 + tid;
        int dd = idx >> 4, c4 = (idx & 15) * 4;
        cpa(&sT[dd * 68 + c4], &Tg[(size_t)dd * NN + c4]);
    }
#pragma unroll
    for (int t = 0; t < 16; t++) {
        int idx = t * 256 + tid;
        int r = idx >> 5, c4 = (idx & 31) * 4;
        cpa(&sW[r * 132 + c4], &g_Pw[r * 128 + c4]);
    }
    cp_commit();
    cp_wait<0>();
    __syncthreads();

    {
        int j = tid >> 2, h = tid & 3;
        float s = 0.0f, s2 = 0.0f;
#pragma unroll 4
        for (int dd = h * 32; dd < h * 32 + 32; dd++) {
            float v = sT[dd * 68 + j];
            s += v; s2 += v * v;
        }
        s  += __shfl_xor_sync(0xffffffffu, s,  1);
        s2 += __shfl_xor_sync(0xffffffffu, s2, 1);
        s  += __shfl_xor_sync(0xffffffffu, s,  2);
        s2 += __shfl_xor_sync(0xffffffffu, s2, 2);
        if (h == 0) {
            float m   = s * (1.0f / 128.0f);
            float var = s2 * (1.0f / 128.0f) - m * m;
            meanv[j] = m;
            invv[j]  = rsqrtf(var + 1e-5f);
        }
    }
    __syncthreads();

#pragma unroll
    for (int t = 0; t < 32; t++) {
        int idx = t * 256 + tid;
        int dd = idx >> 6, j = idx & 63;
        float v = sT[dd * 68 + j];
        sT[dd * 68 + j] = tf32r((v - meanv[j]) * invv[j] * wln[dd] + bln[dd]);
    }
    __syncthreads();

    int warp = tid >> 5, lane = tid & 31;
    int wm = (warp >> 2) * 32, wn = (warp & 3) * 32;
    int qr = lane >> 2, qc = lane & 3;
    float acc[2][4][4] = {};

#pragma unroll
    for (int k = 0; k < 128; k += 8) {
        unsigned af[2][4], bf[4][2];
#pragma unroll
        for (int mt = 0; mt < 2; mt++) {
            int r = wm + mt * 16 + qr;
            const float* p0 = sT + (k + qc) * 68 + r;
            const float* p1 = sT + (k + qc + 4) * 68 + r;
            af[mt][0] = __float_as_uint(p0[0]);
            af[mt][1] = __float_as_uint(p0[8]);
            af[mt][2] = __float_as_uint(p1[0]);
            af[mt][3] = __float_as_uint(p1[8]);
        }
#pragma unroll
        for (int nt = 0; nt < 4; nt++) {
            const float* p = sW + (wn + nt * 8 + qr) * 132 + k + qc;
            bf[nt][0] = __float_as_uint(p[0]);
            bf[nt][1] = __float_as_uint(p[4]);
        }
#pragma unroll
        for (int mt = 0; mt < 2; mt++)
#pragma unroll
            for (int nt = 0; nt < 4; nt++)
                mma8(acc[mt][nt], af[mt], bf[nt]);
    }

#pragma unroll
    for (int mt = 0; mt < 2; mt++)
#pragma unroll
        for (int nt = 0; nt < 4; nt++) {
            int rj = wm + mt * 16 + qr;
            int cn = wn + nt * 8 + qc * 2;
            size_t ro0 = (size_t)(i * 768 + j0 + rj) * 128 + cn;
            size_t ro1 = ro0 + 8 * 128;
            float2 gt0 = *(const float2*)&g_G[ro0];
            float2 gt1 = *(const float2*)&g_G[ro1];
            *(float2*)&out[ro0] = make_float2(gt0.x * acc[mt][nt][0], gt0.y * acc[mt][nt][1]);
            *(float2*)&out[ro1] = make_float2(gt1.x * acc[mt][nt][2], gt1.y * acc[mt][nt][3]);
        }
}

// ---------------- launch ---------------------------------------------------------
extern "C" void kernel_launch(void* const* d_in, const int* in_sizes, int n_in,
                              void* d_out, int out_size) {
    const float* x    = (const float*)d_in[0];
    const float* mask = (const float*)d_in[1];
    const float* niw  = (const float*)d_in[2];
    const float* nib  = (const float*)d_in[3];
    const float* giw  = (const float*)d_in[4];
    const float* piw  = (const float*)d_in[5];
    const float* now  = (const float*)d_in[6];
    const float* nob  = (const float*)d_in[7];
    const float* gow  = (const float*)d_in[8];
    const float* pwo  = (const float*)d_in[9];
    float* out = (float*)d_out;

    size_t sm_proj  = (size_t)(6 * PCH + 384) * 4;     // 112128 B
    size_t sm_bgemm = (size_t)(3 * STG_F) * 4;         // 110592 B
    size_t sm_final = 25984 * 4;                       // 103936 B
    cudaFuncSetAttribute(proj_kernel,  cudaFuncAttributeMaxDynamicSharedMemorySize, (int)sm_proj);
    cudaFuncSetAttribute(bgemm_kernel, cudaFuncAttributeMaxDynamicSharedMemorySize, (int)sm_bgemm);
    cudaFuncSetAttribute(final_kernel, cudaFuncAttributeMaxDynamicSharedMemorySize, (int)sm_final);

    prep_w_kernel<<<64, 256>>>(giw, piw, gow, pwo);
    proj_kernel<<<dim3(5, 4608), 256, sm_proj>>>(x, mask, niw, nib);
    bgemm_kernel<<<dim3(6, 6, 128), 128, sm_bgemm>>>();
    final_kernel<<<9216, 256, sm_final>>>(now, nob, out);
}

// round 8
// speedup vs baseline: 1.2505x; 1.1314x over previous
#include <cuda_runtime.h>
#include <cstdint>

#define NN (768*768)
#define ST 36            // smem row stride (floats) for 32-wide K chunks
#define PCH 4608         // floats per 128x36 chunk buffer

// ---------------- scratch -----------------------------------------------------
__device__ float g_A [(size_t)128 * NN];   // a transposed: [d][i*768+k]
__device__ float g_B [(size_t)128 * NN];   // b transposed: [d][j*768+k]
__device__ float g_T [(size_t)128 * NN];   // t transposed: [d][i*768+j]
__device__ float g_G [(size_t)NN * 128];   // sigmoid(xn @ g_out_w), [r][e]
__device__ float g_Wc[640 * 128];          // rows 0..511: interleaved (g,p); 512..639: g_out_w
__device__ float g_Pw[128 * 128];          // W' = now_w[d]*p_out_w[e,d], tf32
__device__ float g_S [128];                // S[e] = sum_d now_w[d]*p_out_w[e,d]
__device__ float g_C [128];                // C[e] = sum_d now_b[d]*p_out_w[e,d]

// ---------------- helpers ------------------------------------------------------
__device__ __forceinline__ float tf32r(float x) {
    unsigned u;
    asm("cvt.rna.tf32.f32 %0, %1;" : "=r"(u) : "f"(x));
    return __uint_as_float(u);
}

__device__ __forceinline__ void mma8(float c[4], const unsigned a[4], const unsigned b[2]) {
    asm volatile(
        "mma.sync.aligned.m16n8k8.row.col.f32.tf32.tf32.f32 "
        "{%0,%1,%2,%3},{%4,%5,%6,%7},{%8,%9},{%0,%1,%2,%3};"
        : "+f"(c[0]), "+f"(c[1]), "+f"(c[2]), "+f"(c[3])
        : "r"(a[0]), "r"(a[1]), "r"(a[2]), "r"(a[3]), "r"(b[0]), "r"(b[1]));
}

__device__ __forceinline__ void cpa(void* s, const void* g) {
    unsigned sa = (unsigned)__cvta_generic_to_shared(s);
    asm volatile("cp.async.cg.shared.global [%0], [%1], 16;" :: "r"(sa), "l"(g));
}
__device__ __forceinline__ void cp_commit() { asm volatile("cp.async.commit_group;"); }
template<int Nw> __device__ __forceinline__ void cp_wait() {
    asm volatile("cp.async.wait_group %0;" :: "n"(Nw));
}

// 64x64 warp tile, one K-chunk of 32 (bgemm).
__device__ __forceinline__ void gemm64(const float* sA, const float* sB,
                                       float acc[4][8][4],
                                       int wm, int wn, int qr, int qc) {
#pragma unroll
    for (int k = 0; k < 32; k += 8) {
        unsigned af[4][4], bf[8][2];
#pragma unroll
        for (int mt = 0; mt < 4; mt++) {
            const float* p = sA + (wm + mt * 16 + qr) * ST + k + qc;
            af[mt][0] = __float_as_uint(p[0]);
            af[mt][1] = __float_as_uint(p[8 * ST]);
            af[mt][2] = __float_as_uint(p[4]);
            af[mt][3] = __float_as_uint(p[8 * ST + 4]);
        }
#pragma unroll
        for (int nt = 0; nt < 8; nt++) {
            const float* p = sB + (wn + nt * 8 + qr) * ST + k + qc;
            bf[nt][0] = __float_as_uint(p[0]);
            bf[nt][1] = __float_as_uint(p[4]);
        }
#pragma unroll
        for (int mt = 0; mt < 4; mt++)
#pragma unroll
            for (int nt = 0; nt < 8; nt++)
                mma8(acc[mt][nt], af[mt], bf[nt]);
    }
}

// 64x32 warp tile, one K-chunk of 32 (proj).
__device__ __forceinline__ void gemm_c32(const float* sA, const float* sB,
                                         float acc[4][4][4],
                                         int wm, int wn, int qr, int qc) {
#pragma unroll
    for (int k = 0; k < 32; k += 8) {
        unsigned af[4][4], bf[4][2];
#pragma unroll
        for (int mt = 0; mt < 4; mt++) {
            const float* p = sA + (wm + mt * 16 + qr) * ST + k + qc;
            af[mt][0] = __float_as_uint(p[0]);
            af[mt][1] = __float_as_uint(p[8 * ST]);
            af[mt][2] = __float_as_uint(p[4]);
            af[mt][3] = __float_as_uint(p[8 * ST + 4]);
        }
#pragma unroll
        for (int nt = 0; nt < 4; nt++) {
            const float* p = sB + (wn + nt * 8 + qr) * ST + k + qc;
            bf[nt][0] = __float_as_uint(p[0]);
            bf[nt][1] = __float_as_uint(p[4]);
        }
#pragma unroll
        for (int mt = 0; mt < 4; mt++)
#pragma unroll
            for (int nt = 0; nt < 4; nt++)
                mma8(acc[mt][nt], af[mt], bf[nt]);
    }
}

// ---------------- kernel 0: weight prep ----------------------------------------
__global__ void prep_w_kernel(const float* __restrict__ gin, const float* __restrict__ pin,
                              const float* __restrict__ gout, const float* __restrict__ pout,
                              const float* __restrict__ now, const float* __restrict__ nob) {
    int stride = gridDim.x * blockDim.x;
    int tid = threadIdx.x;
    for (int idx = blockIdx.x * blockDim.x + tid; idx < 256 * 128; idx += stride) {
        int e = idx >> 7, d = idx & 127;
        g_Wc[(2 * e) * 128 + d]     = tf32r(gin[idx]);
        g_Wc[(2 * e + 1) * 128 + d] = tf32r(pin[idx]);
    }
    for (int idx = blockIdx.x * blockDim.x + tid; idx < 128 * 128; idx += stride) {
        g_Wc[512 * 128 + idx] = tf32r(gout[idx]);
        g_Pw[idx]             = tf32r(pout[idx] * now[idx & 127]);   // W'
    }
    if (blockIdx.x == 0) {
        int e = tid >> 1, hh = tid & 1;
        float s = 0.0f, c = 0.0f;
        for (int d = hh * 64; d < hh * 64 + 64; d++) {
            float p = pout[e * 128 + d];
            s += now[d] * p;
            c += nob[d] * p;
        }
        s += __shfl_xor_sync(0xffffffffu, s, 1);
        c += __shfl_xor_sync(0xffffffffu, c, 1);
        if (hh == 0) { g_S[e] = s; g_C[e] = c; }
    }
}

// ---------------- kernel 1: fused LN(x) + all projections + gate + mask ----------
// 256 thr, 2 CTAs/SM. One block: LN once on a 128-row x tile (resident in smem),
// then 5 sequential 128x128 W-tiles (g,p interleaved x4, then g_out gate).
__global__ void __launch_bounds__(256, 2) proj_kernel(const float* __restrict__ x,
                                                      const float* __restrict__ mask,
                                                      const float* __restrict__ niw,
                                                      const float* __restrict__ nib) {
    extern __shared__ float sm[];
    float* WB  = sm + 4 * PCH;         // 2 x PCH W double-buffer (also epilogue staging)
    float* msk = sm + 6 * PCH;         // 128
    float* wv  = msk + 128;            // 128
    float* bv  = wv + 128;             // 128
    int rt = blockIdx.x;
    int i = rt / 6, k0 = (rt % 6) * 128;
    int tid = threadIdx.x;

    if (tid < 128) {
        msk[tid] = mask[i * 768 + k0 + tid];
        wv[tid]  = niw[tid];
        bv[tid]  = nib[tid];
    }

    const float* Xb = x + (size_t)(i * 768 + k0) * 128;

    auto ldW = [&](int buf, int w, int chunk) {
#pragma unroll
        for (int t = 0; t < 4; t++) {
            int idx = t * 256 + tid;
            int r = idx >> 3, cc = (idx & 7) * 4;
            cpa(WB + buf * PCH + r * ST + cc,
                g_Wc + (size_t)w * 16384 + (size_t)r * 128 + chunk * 32 + cc);
        }
    };

    // A: all 4 chunks, one group
#pragma unroll
    for (int c = 0; c < 4; c++)
#pragma unroll
        for (int t = 0; t < 4; t++) {
            int idx = t * 256 + tid;
            int r = idx >> 3, cc = (idx & 7) * 4;
            cpa(sm + c * PCH + r * ST + cc, Xb + (size_t)r * 128 + c * 32 + cc);
        }
    cp_commit();
    ldW(0, 0, 0); cp_commit();
    ldW(1, 0, 1); cp_commit();

    cp_wait<2>();        // A complete
    __syncthreads();

    // In-smem LayerNorm: 4 threads per row, k = 4*kk + h (conflict-free).
    {
        int h = tid & 3, q = tid >> 2;
#pragma unroll
        for (int pass = 0; pass < 2; pass++) {
            int r = pass * 64 + q;
            float s = 0.0f, s2 = 0.0f;
#pragma unroll
            for (int kk = 0; kk < 32; kk++) {
                int kg = 4 * kk + h;
                float v = sm[(kg >> 5) * PCH + r * ST + (kg & 31)];
                s += v; s2 += v * v;
            }
            s  += __shfl_xor_sync(0xffffffffu, s,  1);
            s2 += __shfl_xor_sync(0xffffffffu, s2, 1);
            s  += __shfl_xor_sync(0xffffffffu, s,  2);
            s2 += __shfl_xor_sync(0xffffffffu, s2, 2);
            float m   = s * (1.0f / 128.0f);
            float var = s2 * (1.0f / 128.0f) - m * m;
            float inv = rsqrtf(var + 1e-5f);
#pragma unroll
            for (int kk = 0; kk < 32; kk++) {
                int kg = 4 * kk + h;
                float* p = sm + (kg >> 5) * PCH + r * ST + (kg & 31);
                *p = tf32r((*p - m) * inv * wv[kg] + bv[kg]);
            }
        }
    }

    int warp = tid >> 5, lane = tid & 31;
    int wm = (warp >> 2) * 64, wn = (warp & 3) * 32;
    int qr = lane >> 2, qc = lane & 3;

#pragma unroll 1
    for (int w = 0; w < 5; w++) {
        float acc[4][4][4] = {};
#pragma unroll 1
        for (int c = 0; c < 4; c++) {
            cp_wait<1>();
            __syncthreads();            // publishes LN writes on first iter
            gemm_c32(sm + c * PCH, WB + (c & 1) * PCH, acc, wm, wn, qr, qc);
            __syncthreads();
            if (c < 2) ldW(c & 1, w, c + 2);
            cp_commit();
        }

        if (w == 4) {
            // gate: sigmoid -> g_G row-major
#pragma unroll
            for (int mt = 0; mt < 4; mt++)
#pragma unroll
                for (int nt = 0; nt < 4; nt++) {
                    int rm0 = wm + mt * 16 + qr, rm1 = rm0 + 8;
                    int cn = wn + nt * 8 + qc * 2;
                    size_t r0 = (size_t)(i * 768 + k0 + rm0) * 128 + cn;
                    size_t r1 = (size_t)(i * 768 + k0 + rm1) * 128 + cn;
                    *(float2*)&g_G[r0] = make_float2(1.0f / (1.0f + __expf(-acc[mt][nt][0])),
                                                     1.0f / (1.0f + __expf(-acc[mt][nt][1])));
                    *(float2*)&g_G[r1] = make_float2(1.0f / (1.0f + __expf(-acc[mt][nt][2])),
                                                     1.0f / (1.0f + __expf(-acc[mt][nt][3])));
                }
        } else {
            // gated/masked epilogue, transpose through W buffers (now free)
            float* stg = WB;          // [64 ch][132] = 8448 <= 2*PCH
            bool isA = (w < 2);
#pragma unroll
            for (int mt = 0; mt < 4; mt++)
#pragma unroll
                for (int nt = 0; nt < 4; nt++) {
                    int rm0 = wm + mt * 16 + qr, rm1 = rm0 + 8;
                    int chl = (wn >> 1) + nt * 4 + qc;
                    float v0 = acc[mt][nt][1] * (1.0f / (1.0f + __expf(-acc[mt][nt][0])));
                    float v1 = acc[mt][nt][3] * (1.0f / (1.0f + __expf(-acc[mt][nt][2])));
                    if (isA) { v0 *= msk[rm0]; v1 *= msk[rm1]; }
                    stg[chl * 132 + rm0] = tf32r(v0);
                    stg[chl * 132 + rm1] = tf32r(v1);
                }
            __syncthreads();

#pragma unroll
            for (int t = 0; t < 8; t++) {
                int idx = t * 256 + tid;
                int chl = idx >> 5, k4 = idx & 31;
                float4 v = *(float4*)&stg[chl * 132 + k4 * 4];
                int ch = w * 64 + chl;
                float* dst = (ch < 128) ? (g_A + (size_t)ch * NN)
                                        : (g_B + (size_t)(ch - 128) * NN);
                *(float4*)&dst[i * 768 + k0 + k4 * 4] = v;
            }
            __syncthreads();          // staging reads done before next W cpa

            ldW(0, w + 1, 0); cp_commit();
            ldW(1, w + 1, 1); cp_commit();
        }
    }
}

// ---------------- kernel 2: batched einsum  t_d = A_d @ B_d^T --------------------
#define STG_F 9216
__global__ void __launch_bounds__(128, 2) bgemm_kernel() {
    extern __shared__ float sm[];
    int jt = blockIdx.x, it = blockIdx.y, d = blockIdx.z;
    int tid = threadIdx.x;
    const float* Ab = g_A + (size_t)d * NN + (size_t)(it * 128) * 768;
    const float* Bb = g_B + (size_t)d * NN + (size_t)(jt * 128) * 768;

    auto ld = [&](int s, int kc) {
        float* S = sm + s * STG_F;
#pragma unroll
        for (int t = 0; t < 16; t++) {
            int idx = t * 128 + tid;
            int r = idx >> 3, c = (idx & 7) * 4;
            const float* g = (r < 128) ? Ab + (size_t)r * 768 + kc + c
                                       : Bb + (size_t)(r - 128) * 768 + kc + c;
            cpa(&S[r * ST + c], g);
        }
    };

    int wid = tid >> 5, lane = tid & 31;
    int wm = (wid >> 1) * 64, wn = (wid & 1) * 64;
    int qr = lane >> 2, qc = lane & 3;
    float acc[4][8][4] = {};

    ld(0, 0);  cp_commit();
    ld(1, 32); cp_commit();
#pragma unroll 1
    for (int c = 0; c < 24; c++) {
        cp_wait<1>();
        __syncthreads();
        float* S = sm + (c % 3) * STG_F;
        gemm64(S, S + 128 * ST, acc, wm, wn, qr, qc);
        int kn = (c + 2) * 32;
        if (kn < 768) ld((c + 2) % 3, kn);
        cp_commit();
    }

    float* outp = g_T + (size_t)d * NN;
#pragma unroll
    for (int mt = 0; mt < 4; mt++)
#pragma unroll
        for (int nt = 0; nt < 8; nt++) {
            int rm0 = it * 128 + wm + mt * 16 + qr;
            int cn  = jt * 128 + wn + nt * 8 + qc * 2;
            *(float2*)&outp[(size_t)rm0 * 768 + cn]       = make_float2(acc[mt][nt][0], acc[mt][nt][1]);
            *(float2*)&outp[(size_t)(rm0 + 8) * 768 + cn] = make_float2(acc[mt][nt][2], acc[mt][nt][3]);
        }
}

// ---------------- kernel 3: LN(t) folded into GEMM + gate ------------------------
// out[j][e] = gate * ( inv_j * (t @ W'^T)[j][e]  - inv_j*m_j*S[e] + C[e] )
// 64 j x 64 e per block, e-half fastest grid dim (t tile shared in L2), 3 CTAs/SM.
__global__ void __launch_bounds__(256, 3) final_kernel(float* __restrict__ out) {
    extern __shared__ float sm[];
    float* sT   = sm;               // 128 d x 72 (64 j used)
    float* sW   = sm + 9216;        // 64 e x 132
    float* sS   = sm + 17664;       // 64
    float* sC   = sm + 17728;       // 64
    float* smm  = sm + 17792;       // 64
    float* sinv = sm + 17856;       // 64
    float* sred = sm + 17920;       // 512
    int h  = blockIdx.x;            // e-half
    int jt = blockIdx.y;
    int i  = blockIdx.z;
    int j0 = jt * 64, e0 = h * 64;
    int tid = threadIdx.x;

    const float* Tg = g_T + (size_t)i * 768 + j0;
#pragma unroll
    for (int t = 0; t < 8; t++) {
        int idx = t * 256 + tid;
        int dd = idx >> 4, c4 = (idx & 15) * 4;
        cpa(&sT[dd * 72 + c4], &Tg[(size_t)dd * NN + c4]);
    }
#pragma unroll
    for (int t = 0; t < 8; t++) {
        int idx = t * 256 + tid;
        int r = idx >> 5, c4 = (idx & 31) * 4;
        cpa(&sW[r * 132 + c4], &g_Pw[(size_t)(e0 + r) * 128 + c4]);
    }
    if (tid < 64) { sS[tid] = g_S[e0 + tid]; sC[tid] = g_C[e0 + tid]; }
    cp_commit();
    cp_wait<0>();
    __syncthreads();

    // single pass: stats (raw) + tf32 rounding in place
    {
        int h2 = tid >> 6, j = tid & 63;
        float s = 0.0f, s2 = 0.0f;
#pragma unroll 8
        for (int kk = 0; kk < 32; kk++) {
            int dd = h2 * 32 + kk;
            float v = sT[dd * 72 + j];
            s += v; s2 += v * v;
            sT[dd * 72 + j] = tf32r(v);
        }
        sred[h2 * 64 + j] = s;
        sred[256 + h2 * 64 + j] = s2;
    }
    __syncthreads();
    if (tid < 64) {
        float s  = sred[tid] + sred[64 + tid] + sred[128 + tid] + sred[192 + tid];
        float s2 = sred[256 + tid] + sred[320 + tid] + sred[384 + tid] + sred[448 + tid];
        float m   = s * (1.0f / 128.0f);
        float var = s2 * (1.0f / 128.0f) - m * m;
        smm[tid]  = m;
        sinv[tid] = rsqrtf(var + 1e-5f);
    }
    __syncthreads();

    int warp = tid >> 5, lane = tid & 31;
    int wm = (warp >> 1) * 16, wn = (warp & 1) * 32;
    int qr = lane >> 2, qc = lane & 3;
    float acc[4][4] = {};

#pragma unroll
    for (int k = 0; k < 128; k += 8) {
        unsigned af[4], bf[4][2];
        {
            int r = wm + qr;
            const float* p0 = sT + (k + qc) * 72 + r;
            const float* p1 = sT + (k + qc + 4) * 72 + r;
            af[0] = __float_as_uint(p0[0]);
            af[1] = __float_as_uint(p0[8]);
            af[2] = __float_as_uint(p1[0]);
            af[3] = __float_as_uint(p1[8]);
        }
#pragma unroll
        for (int nt = 0; nt < 4; nt++) {
            const float* p = sW + (wn + nt * 8 + qr) * 132 + k + qc;
            bf[nt][0] = __float_as_uint(p[0]);
            bf[nt][1] = __float_as_uint(p[4]);
        }
#pragma unroll
        for (int nt = 0; nt < 4; nt++)
            mma8(acc[nt], af, bf[nt]);
    }

    int rj = wm + qr;
    float inv0 = sinv[rj],     mb0 = -inv0 * smm[rj];
    float inv1 = sinv[rj + 8], mb1 = -inv1 * smm[rj + 8];
#pragma unroll
    for (int nt = 0; nt < 4; nt++) {
        int e = wn + nt * 8 + qc * 2;
        float S0 = sS[e], S1 = sS[e + 1];
        float C0 = sC[e], C1 = sC[e + 1];
        size_t ro0 = (size_t)(i * 768 + j0 + rj) * 128 + e0 + e;
        size_t ro1 = ro0 + 8 * 128;
        float2 gt0 = *(const float2*)&g_G[ro0];
        float2 gt1 = *(const float2*)&g_G[ro1];
        *(float2*)&out[ro0] = make_float2(gt0.x * (inv0 * acc[nt][0] + mb0 * S0 + C0),
                                          gt0.y * (inv0 * acc[nt][1] + mb0 * S1 + C1));
        *(float2*)&out[ro1] = make_float2(gt1.x * (inv1 * acc[nt][2] + mb1 * S0 + C0),
                                          gt1.y * (inv1 * acc[nt][3] + mb1 * S1 + C1));
    }
}

// ---------------- launch ---------------------------------------------------------
extern "C" void kernel_launch(void* const* d_in, const int* in_sizes, int n_in,
                              void* d_out, int out_size) {
    const float* x    = (const float*)d_in[0];
    const float* mask = (const float*)d_in[1];
    const float* niw  = (const float*)d_in[2];
    const float* nib  = (const float*)d_in[3];
    const float* giw  = (const float*)d_in[4];
    const float* piw  = (const float*)d_in[5];
    const float* now  = (const float*)d_in[6];
    const float* nob  = (const float*)d_in[7];
    const float* gow  = (const float*)d_in[8];
    const float* pwo  = (const float*)d_in[9];
    float* out = (float*)d_out;

    size_t sm_proj  = (size_t)(6 * PCH + 384) * 4;     // 112128 B
    size_t sm_bgemm = (size_t)(3 * STG_F) * 4;         // 110592 B
    size_t sm_final = 18432 * 4;                       // 73728 B
    cudaFuncSetAttribute(proj_kernel,  cudaFuncAttributeMaxDynamicSharedMemorySize, (int)sm_proj);
    cudaFuncSetAttribute(bgemm_kernel, cudaFuncAttributeMaxDynamicSharedMemorySize, (int)sm_bgemm);
    cudaFuncSetAttribute(final_kernel, cudaFuncAttributeMaxDynamicSharedMemorySize, (int)sm_final);

    prep_w_kernel<<<64, 256>>>(giw, piw, gow, pwo, now, nob);
    proj_kernel<<<4608, 256, sm_proj>>>(x, mask, niw, nib);
    bgemm_kernel<<<dim3(6, 6, 128), 128, sm_bgemm>>>();
    final_kernel<<<dim3(2, 12, 768), 256, sm_final>>>(out);
}

// round 9
// speedup vs baseline: 1.3189x; 1.0547x over previous
#include <cuda_runtime.h>
#include <cstdint>

#define NN (768*768)
#define ST 36            // smem row stride (floats) for 32-wide K chunks
#define PCH 4608         // floats per 128x36 chunk buffer

// ---------------- scratch -----------------------------------------------------
__device__ float g_A [(size_t)128 * NN];   // a transposed: [d][i*768+k]
__device__ float g_B [(size_t)128 * NN];   // b transposed: [d][j*768+k]
__device__ float g_T [(size_t)128 * NN];   // t transposed: [d][i*768+j]
__device__ float g_G [(size_t)NN * 128];   // sigmoid(xn @ g_out_w), [r][e]
__device__ float g_Wc[640 * 128];          // rows 0..511: interleaved (g,p); 512..639: g_out_w
__device__ float g_Pw[128 * 128];          // W' = now_w[d]*p_out_w[e,d], tf32
__device__ float g_S [128];                // S[e] = sum_d now_w[d]*p_out_w[e,d]
__device__ float g_C [128];                // C[e] = sum_d now_b[d]*p_out_w[e,d]

// ---------------- helpers ------------------------------------------------------
__device__ __forceinline__ float tf32r(float x) {
    unsigned u;
    asm("cvt.rna.tf32.f32 %0, %1;" : "=r"(u) : "f"(x));
    return __uint_as_float(u);
}

__device__ __forceinline__ void mma8(float c[4], const unsigned a[4], const unsigned b[2]) {
    asm volatile(
        "mma.sync.aligned.m16n8k8.row.col.f32.tf32.tf32.f32 "
        "{%0,%1,%2,%3},{%4,%5,%6,%7},{%8,%9},{%0,%1,%2,%3};"
        : "+f"(c[0]), "+f"(c[1]), "+f"(c[2]), "+f"(c[3])
        : "r"(a[0]), "r"(a[1]), "r"(a[2]), "r"(a[3]), "r"(b[0]), "r"(b[1]));
}

__device__ __forceinline__ void cpa(void* s, const void* g) {
    unsigned sa = (unsigned)__cvta_generic_to_shared(s);
    asm volatile("cp.async.cg.shared.global [%0], [%1], 16;" :: "r"(sa), "l"(g));
}
__device__ __forceinline__ void cp_commit() { asm volatile("cp.async.commit_group;"); }
template<int Nw> __device__ __forceinline__ void cp_wait() {
    asm volatile("cp.async.wait_group %0;" :: "n"(Nw));
}

// 64x64 warp tile, one K-chunk of 32 (bgemm).
__device__ __forceinline__ void gemm64(const float* sA, const float* sB,
                                       float acc[4][8][4],
                                       int wm, int wn, int qr, int qc) {
#pragma unroll
    for (int k = 0; k < 32; k += 8) {
        unsigned af[4][4], bf[8][2];
#pragma unroll
        for (int mt = 0; mt < 4; mt++) {
            const float* p = sA + (wm + mt * 16 + qr) * ST + k + qc;
            af[mt][0] = __float_as_uint(p[0]);
            af[mt][1] = __float_as_uint(p[8 * ST]);
            af[mt][2] = __float_as_uint(p[4]);
            af[mt][3] = __float_as_uint(p[8 * ST + 4]);
        }
#pragma unroll
        for (int nt = 0; nt < 8; nt++) {
            const float* p = sB + (wn + nt * 8 + qr) * ST + k + qc;
            bf[nt][0] = __float_as_uint(p[0]);
            bf[nt][1] = __float_as_uint(p[4]);
        }
#pragma unroll
        for (int mt = 0; mt < 4; mt++)
#pragma unroll
            for (int nt = 0; nt < 8; nt++)
                mma8(acc[mt][nt], af[mt], bf[nt]);
    }
}

// 64x32 warp tile, one K-chunk of 32 (proj).
__device__ __forceinline__ void gemm_c32(const float* sA, const float* sB,
                                         float acc[4][4][4],
                                         int wm, int wn, int qr, int qc) {
#pragma unroll
    for (int k = 0; k < 32; k += 8) {
        unsigned af[4][4], bf[4][2];
#pragma unroll
        for (int mt = 0; mt < 4; mt++) {
            const float* p = sA + (wm + mt * 16 + qr) * ST + k + qc;
            af[mt][0] = __float_as_uint(p[0]);
            af[mt][1] = __float_as_uint(p[8 * ST]);
            af[mt][2] = __float_as_uint(p[4]);
            af[mt][3] = __float_as_uint(p[8 * ST + 4]);
        }
#pragma unroll
        for (int nt = 0; nt < 4; nt++) {
            const float* p = sB + (wn + nt * 8 + qr) * ST + k + qc;
            bf[nt][0] = __float_as_uint(p[0]);
            bf[nt][1] = __float_as_uint(p[4]);
        }
#pragma unroll
        for (int mt = 0; mt < 4; mt++)
#pragma unroll
            for (int nt = 0; nt < 4; nt++)
                mma8(acc[mt][nt], af[mt], bf[nt]);
    }
}

// ---------------- kernel 0: weight prep ----------------------------------------
__global__ void prep_w_kernel(const float* __restrict__ gin, const float* __restrict__ pin,
                              const float* __restrict__ gout, const float* __restrict__ pout,
                              const float* __restrict__ now, const float* __restrict__ nob) {
    int stride = gridDim.x * blockDim.x;
    int tid = threadIdx.x;
    for (int idx = blockIdx.x * blockDim.x + tid; idx < 256 * 128; idx += stride) {
        int e = idx >> 7, d = idx & 127;
        g_Wc[(2 * e) * 128 + d]     = tf32r(gin[idx]);
        g_Wc[(2 * e + 1) * 128 + d] = tf32r(pin[idx]);
    }
    for (int idx = blockIdx.x * blockDim.x + tid; idx < 128 * 128; idx += stride) {
        g_Wc[512 * 128 + idx] = tf32r(gout[idx]);
        g_Pw[idx]             = tf32r(pout[idx] * now[idx & 127]);   // W'
    }
    if (blockIdx.x == 0) {
        int e = tid >> 1, hh = tid & 1;
        float s = 0.0f, c = 0.0f;
        for (int d = hh * 64; d < hh * 64 + 64; d++) {
            float p = pout[e * 128 + d];
            s += now[d] * p;
            c += nob[d] * p;
        }
        s += __shfl_xor_sync(0xffffffffu, s, 1);
        c += __shfl_xor_sync(0xffffffffu, c, 1);
        if (hh == 0) { g_S[e] = s; g_C[e] = c; }
    }
}

// ---------------- kernel 1: fused LN(x) + all projections + gate + mask ----------
// 256 thr, 2 CTAs/SM. One block: LN once on a 128-row x tile (resident in smem),
// then 5 sequential 128x128 W-tiles. Epilogue stores DIRECTLY from accumulators
// (32B-coalesced scatter) so the W double-buffer prefetches tile w+1 during tile w.
__global__ void __launch_bounds__(256, 2) proj_kernel(const float* __restrict__ x,
                                                      const float* __restrict__ mask,
                                                      const float* __restrict__ niw,
                                                      const float* __restrict__ nib) {
    extern __shared__ float sm[];
    float* WB  = sm + 4 * PCH;         // 2 x PCH W double-buffer
    float* msk = sm + 6 * PCH;         // 128
    float* wv  = msk + 128;            // 128
    float* bv  = wv + 128;             // 128
    int rt = blockIdx.x;
    int i = rt / 6, k0 = (rt % 6) * 128;
    int tid = threadIdx.x;

    if (tid < 128) {
        msk[tid] = mask[i * 768 + k0 + tid];
        wv[tid]  = niw[tid];
        bv[tid]  = nib[tid];
    }

    const float* Xb = x + (size_t)(i * 768 + k0) * 128;

    auto ldW = [&](int buf, int w, int chunk) {
#pragma unroll
        for (int t = 0; t < 4; t++) {
            int idx = t * 256 + tid;
            int r = idx >> 3, cc = (idx & 7) * 4;
            cpa(WB + buf * PCH + r * ST + cc,
                g_Wc + (size_t)w * 16384 + (size_t)r * 128 + chunk * 32 + cc);
        }
    };

    // A: all 4 chunks, one group
#pragma unroll
    for (int c = 0; c < 4; c++)
#pragma unroll
        for (int t = 0; t < 4; t++) {
            int idx = t * 256 + tid;
            int r = idx >> 3, cc = (idx & 7) * 4;
            cpa(sm + c * PCH + r * ST + cc, Xb + (size_t)r * 128 + c * 32 + cc);
        }
    cp_commit();
    ldW(0, 0, 0); cp_commit();
    ldW(1, 0, 1); cp_commit();

    cp_wait<2>();        // A complete
    __syncthreads();

    // In-smem LayerNorm: 4 threads per row, k = 4*kk + h (conflict-free).
    {
        int h = tid & 3, q = tid >> 2;
#pragma unroll
        for (int pass = 0; pass < 2; pass++) {
            int r = pass * 64 + q;
            float s = 0.0f, s2 = 0.0f;
#pragma unroll
            for (int kk = 0; kk < 32; kk++) {
                int kg = 4 * kk + h;
                float v = sm[(kg >> 5) * PCH + r * ST + (kg & 31)];
                s += v; s2 += v * v;
            }
            s  += __shfl_xor_sync(0xffffffffu, s,  1);
            s2 += __shfl_xor_sync(0xffffffffu, s2, 1);
            s  += __shfl_xor_sync(0xffffffffu, s,  2);
            s2 += __shfl_xor_sync(0xffffffffu, s2, 2);
            float m   = s * (1.0f / 128.0f);
            float var = s2 * (1.0f / 128.0f) - m * m;
            float inv = rsqrtf(var + 1e-5f);
#pragma unroll
            for (int kk = 0; kk < 32; kk++) {
                int kg = 4 * kk + h;
                float* p = sm + (kg >> 5) * PCH + r * ST + (kg & 31);
                *p = tf32r((*p - m) * inv * wv[kg] + bv[kg]);
            }
        }
    }

    int warp = tid >> 5, lane = tid & 31;
    int wm = (warp >> 2) * 64, wn = (warp & 3) * 32;
    int qr = lane >> 2, qc = lane & 3;

#pragma unroll 1
    for (int w = 0; w < 5; w++) {
        float acc[4][4][4] = {};
#pragma unroll 1
        for (int c = 0; c < 4; c++) {
            cp_wait<1>();
            __syncthreads();            // publishes LN writes on first iter
            gemm_c32(sm + c * PCH, WB + (c & 1) * PCH, acc, wm, wn, qr, qc);
            __syncthreads();            // buffer reads done before refill
            if (c < 2)       ldW(c & 1, w, c + 2);          // this tile chunks 2,3
            else if (w < 4)  ldW(c & 1, w + 1, c - 2);      // next tile chunks 0,1
            cp_commit();
        }

        // epilogue: direct from accumulators, no syncs (loads for w+1 in flight)
        if (w == 4) {
#pragma unroll
            for (int mt = 0; mt < 4; mt++)
#pragma unroll
                for (int nt = 0; nt < 4; nt++) {
                    int rm0 = wm + mt * 16 + qr, rm1 = rm0 + 8;
                    int cn = wn + nt * 8 + qc * 2;
                    size_t r0 = (size_t)(i * 768 + k0 + rm0) * 128 + cn;
                    size_t r1 = (size_t)(i * 768 + k0 + rm1) * 128 + cn;
                    *(float2*)&g_G[r0] = make_float2(1.0f / (1.0f + __expf(-acc[mt][nt][0])),
                                                     1.0f / (1.0f + __expf(-acc[mt][nt][1])));
                    *(float2*)&g_G[r1] = make_float2(1.0f / (1.0f + __expf(-acc[mt][nt][2])),
                                                     1.0f / (1.0f + __expf(-acc[mt][nt][3])));
                }
        } else {
            bool isA = (w < 2);
#pragma unroll
            for (int mt = 0; mt < 4; mt++)
#pragma unroll
                for (int nt = 0; nt < 4; nt++) {
                    int rm0 = wm + mt * 16 + qr, rm1 = rm0 + 8;
                    int chl = (wn >> 1) + nt * 4 + qc;
                    float v0 = acc[mt][nt][1] * (1.0f / (1.0f + __expf(-acc[mt][nt][0])));
                    float v1 = acc[mt][nt][3] * (1.0f / (1.0f + __expf(-acc[mt][nt][2])));
                    if (isA) { v0 *= msk[rm0]; v1 *= msk[rm1]; }
                    int ch = w * 64 + chl;
                    float* dst = (ch < 128) ? (g_A + (size_t)ch * NN)
                                            : (g_B + (size_t)(ch - 128) * NN);
                    dst[i * 768 + k0 + rm0] = tf32r(v0);
                    dst[i * 768 + k0 + rm1] = tf32r(v1);
                }
        }
    }
}

// ---------------- kernel 2: batched einsum  t_d = A_d @ B_d^T --------------------
#define STG_F 9216
__global__ void __launch_bounds__(128, 2) bgemm_kernel() {
    extern __shared__ float sm[];
    int jt = blockIdx.x, it = blockIdx.y, d = blockIdx.z;
    int tid = threadIdx.x;
    const float* Ab = g_A + (size_t)d * NN + (size_t)(it * 128) * 768;
    const float* Bb = g_B + (size_t)d * NN + (size_t)(jt * 128) * 768;

    auto ld = [&](int s, int kc) {
        float* S = sm + s * STG_F;
#pragma unroll
        for (int t = 0; t < 16; t++) {
            int idx = t * 128 + tid;
            int r = idx >> 3, c = (idx & 7) * 4;
            const float* g = (r < 128) ? Ab + (size_t)r * 768 + kc + c
                                       : Bb + (size_t)(r - 128) * 768 + kc + c;
            cpa(&S[r * ST + c], g);
        }
    };

    int wid = tid >> 5, lane = tid & 31;
    int wm = (wid >> 1) * 64, wn = (wid & 1) * 64;
    int qr = lane >> 2, qc = lane & 3;
    float acc[4][8][4] = {};

    ld(0, 0);  cp_commit();
    ld(1, 32); cp_commit();
#pragma unroll 1
    for (int c = 0; c < 24; c++) {
        cp_wait<1>();
        __syncthreads();
        float* S = sm + (c % 3) * STG_F;
        gemm64(S, S + 128 * ST, acc, wm, wn, qr, qc);
        int kn = (c + 2) * 32;
        if (kn < 768) ld((c + 2) % 3, kn);
        cp_commit();
    }

    float* outp = g_T + (size_t)d * NN;
#pragma unroll
    for (int mt = 0; mt < 4; mt++)
#pragma unroll
        for (int nt = 0; nt < 8; nt++) {
            int rm0 = it * 128 + wm + mt * 16 + qr;
            int cn  = jt * 128 + wn + nt * 8 + qc * 2;
            *(float2*)&outp[(size_t)rm0 * 768 + cn]       = make_float2(acc[mt][nt][0], acc[mt][nt][1]);
            *(float2*)&outp[(size_t)(rm0 + 8) * 768 + cn] = make_float2(acc[mt][nt][2], acc[mt][nt][3]);
        }
}

// ---------------- kernel 3: LN(t) folded into GEMM + gate ------------------------
// out[j][e] = gate * ( inv_j * (t @ W'^T)[j][e]  - inv_j*m_j*S[e] + C[e] )
// t fed to HMMA as raw fp32 (HW tf32-truncation). 64j x 64e, 3 CTAs/SM.
__global__ void __launch_bounds__(256, 3) final_kernel(float* __restrict__ out) {
    extern __shared__ float sm[];
    float* sT   = sm;               // 128 d x 72 (64 j used)
    float* sW   = sm + 9216;        // 64 e x 132
    float* sS   = sm + 17664;       // 64
    float* sC   = sm + 17728;       // 64
    float* smm  = sm + 17792;       // 64
    float* sinv = sm + 17856;       // 64
    float* sred = sm + 17920;       // 512
    int h  = blockIdx.x;            // e-half
    int jt = blockIdx.y;
    int i  = blockIdx.z;
    int j0 = jt * 64, e0 = h * 64;
    int tid = threadIdx.x;

    const float* Tg = g_T + (size_t)i * 768 + j0;
#pragma unroll
    for (int t = 0; t < 8; t++) {
        int idx = t * 256 + tid;
        int dd = idx >> 4, c4 = (idx & 15) * 4;
        cpa(&sT[dd * 72 + c4], &Tg[(size_t)dd * NN + c4]);
    }
#pragma unroll
    for (int t = 0; t < 8; t++) {
        int idx = t * 256 + tid;
        int r = idx >> 5, c4 = (idx & 31) * 4;
        cpa(&sW[r * 132 + c4], &g_Pw[(size_t)(e0 + r) * 128 + c4]);
    }
    if (tid < 64) { sS[tid] = g_S[e0 + tid]; sC[tid] = g_C[e0 + tid]; }
    cp_commit();
    cp_wait<0>();
    __syncthreads();

    // stats pass (read-only; t fed raw to HMMA)
    {
        int h2 = tid >> 6, j = tid & 63;
        float s = 0.0f, s2 = 0.0f;
#pragma unroll 8
        for (int kk = 0; kk < 32; kk++) {
            int dd = h2 * 32 + kk;
            float v = sT[dd * 72 + j];
            s += v; s2 += v * v;
        }
        sred[h2 * 64 + j] = s;
        sred[256 + h2 * 64 + j] = s2;
    }
    __syncthreads();
    if (tid < 64) {
        float s  = sred[tid] + sred[64 + tid] + sred[128 + tid] + sred[192 + tid];
        float s2 = sred[256 + tid] + sred[320 + tid] + sred[384 + tid] + sred[448 + tid];
        float m   = s * (1.0f / 128.0f);
        float var = s2 * (1.0f / 128.0f) - m * m;
        smm[tid]  = m;
        sinv[tid] = rsqrtf(var + 1e-5f);
    }
    __syncthreads();

    int warp = tid >> 5, lane = tid & 31;
    int wm = (warp >> 1) * 16, wn = (warp & 1) * 32;
    int qr = lane >> 2, qc = lane & 3;
    float acc[4][4] = {};

#pragma unroll
    for (int k = 0; k < 128; k += 8) {
        unsigned af[4], bf[4][2];
        {
            int r = wm + qr;
            const float* p0 = sT + (k + qc) * 72 + r;
            const float* p1 = sT + (k + qc + 4) * 72 + r;
            af[0] = __float_as_uint(p0[0]);
            af[1] = __float_as_uint(p0[8]);
            af[2] = __float_as_uint(p1[0]);
            af[3] = __float_as_uint(p1[8]);
        }
#pragma unroll
        for (int nt = 0; nt < 4; nt++) {
            const float* p = sW + (wn + nt * 8 + qr) * 132 + k + qc;
            bf[nt][0] = __float_as_uint(p[0]);
            bf[nt][1] = __float_as_uint(p[4]);
        }
#pragma unroll
        for (int nt = 0; nt < 4; nt++)
            mma8(acc[nt], af, bf[nt]);
    }

    int rj = wm + qr;
    float inv0 = sinv[rj],     mb0 = -inv0 * smm[rj];
    float inv1 = sinv[rj + 8], mb1 = -inv1 * smm[rj + 8];
#pragma unroll
    for (int nt = 0; nt < 4; nt++) {
        int e = wn + nt * 8 + qc * 2;
        float S0 = sS[e], S1 = sS[e + 1];
        float C0 = sC[e], C1 = sC[e + 1];
        size_t ro0 = (size_t)(i * 768 + j0 + rj) * 128 + e0 + e;
        size_t ro1 = ro0 + 8 * 128;
        float2 gt0 = *(const float2*)&g_G[ro0];
        float2 gt1 = *(const float2*)&g_G[ro1];
        *(float2*)&out[ro0] = make_float2(gt0.x * (inv0 * acc[nt][0] + mb0 * S0 + C0),
                                          gt0.y * (inv0 * acc[nt][1] + mb0 * S1 + C1));
        *(float2*)&out[ro1] = make_float2(gt1.x * (inv1 * acc[nt][2] + mb1 * S0 + C0),
                                          gt1.y * (inv1 * acc[nt][3] + mb1 * S1 + C1));
    }
}

// ---------------- launch ---------------------------------------------------------
extern "C" void kernel_launch(void* const* d_in, const int* in_sizes, int n_in,
                              void* d_out, int out_size) {
    const float* x    = (const float*)d_in[0];
    const float* mask = (const float*)d_in[1];
    const float* niw  = (const float*)d_in[2];
    const float* nib  = (const float*)d_in[3];
    const float* giw  = (const float*)d_in[4];
    const float* piw  = (const float*)d_in[5];
    const float* now  = (const float*)d_in[6];
    const float* nob  = (const float*)d_in[7];
    const float* gow  = (const float*)d_in[8];
    const float* pwo  = (const float*)d_in[9];
    float* out = (float*)d_out;

    size_t sm_proj  = (size_t)(6 * PCH + 384) * 4;     // 112128 B
    size_t sm_bgemm = (size_t)(3 * STG_F) * 4;         // 110592 B
    size_t sm_final = 18432 * 4;                       // 73728 B
    cudaFuncSetAttribute(proj_kernel,  cudaFuncAttributeMaxDynamicSharedMemorySize, (int)sm_proj);
    cudaFuncSetAttribute(bgemm_kernel, cudaFuncAttributeMaxDynamicSharedMemorySize, (int)sm_bgemm);
    cudaFuncSetAttribute(final_kernel, cudaFuncAttributeMaxDynamicSharedMemorySize, (int)sm_final);

    prep_w_kernel<<<64, 256>>>(giw, piw, gow, pwo, now, nob);
    proj_kernel<<<4608, 256, sm_proj>>>(x, mask, niw, nib);
    bgemm_kernel<<<dim3(6, 6, 128), 128, sm_bgemm>>>();
    final_kernel<<<dim3(2, 12, 768), 256, sm_final>>>(out);
}

// round 10
// speedup vs baseline: 1.3703x; 1.0390x over previous
#include <cuda_runtime.h>
#include <cstdint>

#define NN (768*768)
#define ST 36            // smem row stride (floats) for 32-wide K chunks
#define PCH 4608         // floats per 128x36 chunk buffer

// ---------------- scratch -----------------------------------------------------
__device__ float g_A [(size_t)128 * NN];   // a transposed: [d][i*768+k]
__device__ float g_B [(size_t)128 * NN];   // b transposed: [d][j*768+k]
__device__ float g_T [(size_t)128 * NN];   // t transposed: [d][i*768+j]
__device__ float g_G [(size_t)NN * 128];   // sigmoid(xn @ g_out_w), [r][e]
__device__ float g_Wc[640 * 128];          // rows 0..511: interleaved (g,p); 512..639: g_out_w
__device__ float g_Pw[128 * 128];          // W' = now_w[d]*p_out_w[e,d], tf32
__device__ float g_S [128];                // S[e] = sum_d now_w[d]*p_out_w[e,d]
__device__ float g_C [128];                // C[e] = sum_d now_b[d]*p_out_w[e,d]

// ---------------- helpers ------------------------------------------------------
__device__ __forceinline__ float tf32r(float x) {
    unsigned u;
    asm("cvt.rna.tf32.f32 %0, %1;" : "=r"(u) : "f"(x));
    return __uint_as_float(u);
}

__device__ __forceinline__ void mma8(float c[4], const unsigned a[4], const unsigned b[2]) {
    asm volatile(
        "mma.sync.aligned.m16n8k8.row.col.f32.tf32.tf32.f32 "
        "{%0,%1,%2,%3},{%4,%5,%6,%7},{%8,%9},{%0,%1,%2,%3};"
        : "+f"(c[0]), "+f"(c[1]), "+f"(c[2]), "+f"(c[3])
        : "r"(a[0]), "r"(a[1]), "r"(a[2]), "r"(a[3]), "r"(b[0]), "r"(b[1]));
}

__device__ __forceinline__ void ldsm4(unsigned r[4], uint32_t a) {
    asm volatile("ldmatrix.sync.aligned.m8n8.x4.shared.b16 {%0,%1,%2,%3}, [%4];"
        : "=r"(r[0]), "=r"(r[1]), "=r"(r[2]), "=r"(r[3]) : "r"(a));
}

__device__ __forceinline__ void cpa(void* s, const void* g) {
    unsigned sa = (unsigned)__cvta_generic_to_shared(s);
    asm volatile("cp.async.cg.shared.global [%0], [%1], 16;" :: "r"(sa), "l"(g));
}
__device__ __forceinline__ void cp_commit() { asm volatile("cp.async.commit_group;"); }
template<int Nw> __device__ __forceinline__ void cp_wait() {
    asm volatile("cp.async.wait_group %0;" :: "n"(Nw));
}

// 64x64 warp tile, one K-chunk of 32 (bgemm). Fragments via ldmatrix.
// A tiles: lanes 0-7 rows r..r+7 col k | 8-15 rows r+8.. col k | 16-23 r.. col k+4 | 24-31 r+8 col k+4
// B x4: lanes g=lane>>3 provide col k+g*4, rows wn+nt*8+(lane&7): regs = b0(k),b1(k),b0(k+8),b1(k+8)
__device__ __forceinline__ void gemm64(const float* sA, const float* sB,
                                       float acc[4][8][4],
                                       int wm, int wn, int lane) {
    uint32_t ab = (uint32_t)__cvta_generic_to_shared(sA);
    uint32_t bb = (uint32_t)__cvta_generic_to_shared(sB);
    int lr = lane & 7, grp = lane >> 3;
    uint32_t aoff = ab + (uint32_t)(((wm + lr + (grp & 1) * 8) * ST + (grp >> 1) * 4) * 4);
    uint32_t boff = bb + (uint32_t)(((wn + lr) * ST + grp * 4) * 4);
#pragma unroll
    for (int kp = 0; kp < 2; kp++) {           // k pairs {0,8}, {16,24}
        unsigned bf[8][4];
#pragma unroll
        for (int nt = 0; nt < 8; nt++)
            ldsm4(bf[nt], boff + (uint32_t)(nt * 8 * ST * 4 + kp * 64));
#pragma unroll
        for (int ks = 0; ks < 2; ks++) {
            unsigned af[4][4];
#pragma unroll
            for (int mt = 0; mt < 4; mt++)
                ldsm4(af[mt], aoff + (uint32_t)(mt * 16 * ST * 4 + (kp * 16 + ks * 8) * 4));
#pragma unroll
            for (int mt = 0; mt < 4; mt++)
#pragma unroll
                for (int nt = 0; nt < 8; nt++)
                    mma8(acc[mt][nt], af[mt], &bf[nt][ks * 2]);
        }
    }
}

// 64x32 warp tile, one K-chunk of 32 (proj). Same ldmatrix scheme, 4 nt.
__device__ __forceinline__ void gemm_c32(const float* sA, const float* sB,
                                         float acc[4][4][4],
                                         int wm, int wn, int lane) {
    uint32_t ab = (uint32_t)__cvta_generic_to_shared(sA);
    uint32_t bb = (uint32_t)__cvta_generic_to_shared(sB);
    int lr = lane & 7, grp = lane >> 3;
    uint32_t aoff = ab + (uint32_t)(((wm + lr + (grp & 1) * 8) * ST + (grp >> 1) * 4) * 4);
    uint32_t boff = bb + (uint32_t)(((wn + lr) * ST + grp * 4) * 4);
#pragma unroll
    for (int kp = 0; kp < 2; kp++) {
        unsigned bf[4][4];
#pragma unroll
        for (int nt = 0; nt < 4; nt++)
            ldsm4(bf[nt], boff + (uint32_t)(nt * 8 * ST * 4 + kp * 64));
#pragma unroll
        for (int ks = 0; ks < 2; ks++) {
            unsigned af[4][4];
#pragma unroll
            for (int mt = 0; mt < 4; mt++)
                ldsm4(af[mt], aoff + (uint32_t)(mt * 16 * ST * 4 + (kp * 16 + ks * 8) * 4));
#pragma unroll
            for (int mt = 0; mt < 4; mt++)
#pragma unroll
                for (int nt = 0; nt < 4; nt++)
                    mma8(acc[mt][nt], af[mt], &bf[nt][ks * 2]);
        }
    }
}

// ---------------- kernel 0: weight prep ----------------------------------------
__global__ void prep_w_kernel(const float* __restrict__ gin, const float* __restrict__ pin,
                              const float* __restrict__ gout, const float* __restrict__ pout,
                              const float* __restrict__ now, const float* __restrict__ nob) {
    int stride = gridDim.x * blockDim.x;
    int tid = threadIdx.x;
    for (int idx = blockIdx.x * blockDim.x + tid; idx < 256 * 128; idx += stride) {
        int e = idx >> 7, d = idx & 127;
        g_Wc[(2 * e) * 128 + d]     = tf32r(gin[idx]);
        g_Wc[(2 * e + 1) * 128 + d] = tf32r(pin[idx]);
    }
    for (int idx = blockIdx.x * blockDim.x + tid; idx < 128 * 128; idx += stride) {
        g_Wc[512 * 128 + idx] = tf32r(gout[idx]);
        g_Pw[idx]             = tf32r(pout[idx] * now[idx & 127]);   // W'
    }
    if (blockIdx.x == 0) {
        int e = tid >> 1, hh = tid & 1;
        float s = 0.0f, c = 0.0f;
        for (int d = hh * 64; d < hh * 64 + 64; d++) {
            float p = pout[e * 128 + d];
            s += now[d] * p;
            c += nob[d] * p;
        }
        s += __shfl_xor_sync(0xffffffffu, s, 1);
        c += __shfl_xor_sync(0xffffffffu, c, 1);
        if (hh == 0) { g_S[e] = s; g_C[e] = c; }
    }
}

// ---------------- kernel 1: fused LN(x) + all projections + gate + mask ----------
__global__ void __launch_bounds__(256, 2) proj_kernel(const float* __restrict__ x,
                                                      const float* __restrict__ mask,
                                                      const float* __restrict__ niw,
                                                      const float* __restrict__ nib) {
    extern __shared__ float sm[];
    float* WB  = sm + 4 * PCH;         // 2 x PCH W double-buffer
    float* msk = sm + 6 * PCH;         // 128
    float* wv  = msk + 128;            // 128
    float* bv  = wv + 128;             // 128
    int rt = blockIdx.x;
    int i = rt / 6, k0 = (rt % 6) * 128;
    int tid = threadIdx.x;

    if (tid < 128) {
        msk[tid] = mask[i * 768 + k0 + tid];
        wv[tid]  = niw[tid];
        bv[tid]  = nib[tid];
    }

    const float* Xb = x + (size_t)(i * 768 + k0) * 128;

    auto ldW = [&](int buf, int w, int chunk) {
#pragma unroll
        for (int t = 0; t < 4; t++) {
            int idx = t * 256 + tid;
            int r = idx >> 3, cc = (idx & 7) * 4;
            cpa(WB + buf * PCH + r * ST + cc,
                g_Wc + (size_t)w * 16384 + (size_t)r * 128 + chunk * 32 + cc);
        }
    };

    // A: all 4 chunks, one group
#pragma unroll
    for (int c = 0; c < 4; c++)
#pragma unroll
        for (int t = 0; t < 4; t++) {
            int idx = t * 256 + tid;
            int r = idx >> 3, cc = (idx & 7) * 4;
            cpa(sm + c * PCH + r * ST + cc, Xb + (size_t)r * 128 + c * 32 + cc);
        }
    cp_commit();
    ldW(0, 0, 0); cp_commit();
    ldW(1, 0, 1); cp_commit();

    cp_wait<2>();        // A complete
    __syncthreads();

    // In-smem LayerNorm: 4 threads per row, k = 4*kk + h (conflict-free).
    {
        int h = tid & 3, q = tid >> 2;
#pragma unroll
        for (int pass = 0; pass < 2; pass++) {
            int r = pass * 64 + q;
            float s = 0.0f, s2 = 0.0f;
#pragma unroll
            for (int kk = 0; kk < 32; kk++) {
                int kg = 4 * kk + h;
                float v = sm[(kg >> 5) * PCH + r * ST + (kg & 31)];
                s += v; s2 += v * v;
            }
            s  += __shfl_xor_sync(0xffffffffu, s,  1);
            s2 += __shfl_xor_sync(0xffffffffu, s2, 1);
            s  += __shfl_xor_sync(0xffffffffu, s,  2);
            s2 += __shfl_xor_sync(0xffffffffu, s2, 2);
            float m   = s * (1.0f / 128.0f);
            float var = s2 * (1.0f / 128.0f) - m * m;
            float inv = rsqrtf(var + 1e-5f);
#pragma unroll
            for (int kk = 0; kk < 32; kk++) {
                int kg = 4 * kk + h;
                float* p = sm + (kg >> 5) * PCH + r * ST + (kg & 31);
                *p = tf32r((*p - m) * inv * wv[kg] + bv[kg]);
            }
        }
    }

    int warp = tid >> 5, lane = tid & 31;
    int wm = (warp >> 2) * 64, wn = (warp & 3) * 32;
    int qr = lane >> 2, qc = lane & 3;

#pragma unroll 1
    for (int w = 0; w < 5; w++) {
        float acc[4][4][4] = {};
#pragma unroll 1
        for (int c = 0; c < 4; c++) {
            cp_wait<1>();
            __syncthreads();            // publishes LN writes on first iter
            gemm_c32(sm + c * PCH, WB + (c & 1) * PCH, acc, wm, wn, lane);
            __syncthreads();            // buffer reads done before refill
            if (c < 2)       ldW(c & 1, w, c + 2);          // this tile chunks 2,3
            else if (w < 4)  ldW(c & 1, w + 1, c - 2);      // next tile chunks 0,1
            cp_commit();
        }

        // epilogue: direct from accumulators, no syncs (loads for w+1 in flight)
        if (w == 4) {
#pragma unroll
            for (int mt = 0; mt < 4; mt++)
#pragma unroll
                for (int nt = 0; nt < 4; nt++) {
                    int rm0 = wm + mt * 16 + qr, rm1 = rm0 + 8;
                    int cn = wn + nt * 8 + qc * 2;
                    size_t r0 = (size_t)(i * 768 + k0 + rm0) * 128 + cn;
                    size_t r1 = (size_t)(i * 768 + k0 + rm1) * 128 + cn;
                    *(float2*)&g_G[r0] = make_float2(1.0f / (1.0f + __expf(-acc[mt][nt][0])),
                                                     1.0f / (1.0f + __expf(-acc[mt][nt][1])));
                    *(float2*)&g_G[r1] = make_float2(1.0f / (1.0f + __expf(-acc[mt][nt][2])),
                                                     1.0f / (1.0f + __expf(-acc[mt][nt][3])));
                }
        } else {
            bool isA = (w < 2);
#pragma unroll
            for (int mt = 0; mt < 4; mt++)
#pragma unroll
                for (int nt = 0; nt < 4; nt++) {
                    int rm0 = wm + mt * 16 + qr, rm1 = rm0 + 8;
                    int chl = (wn >> 1) + nt * 4 + qc;
                    float v0 = acc[mt][nt][1] * (1.0f / (1.0f + __expf(-acc[mt][nt][0])));
                    float v1 = acc[mt][nt][3] * (1.0f / (1.0f + __expf(-acc[mt][nt][2])));
                    if (isA) { v0 *= msk[rm0]; v1 *= msk[rm1]; }
                    int ch = w * 64 + chl;
                    float* dst = (ch < 128) ? (g_A + (size_t)ch * NN)
                                            : (g_B + (size_t)(ch - 128) * NN);
                    dst[i * 768 + k0 + rm0] = tf32r(v0);
                    dst[i * 768 + k0 + rm1] = tf32r(v1);
                }
        }
    }
}

// ---------------- kernel 2: batched einsum  t_d = A_d @ B_d^T --------------------
#define STG_F 9216
__global__ void __launch_bounds__(128, 2) bgemm_kernel() {
    extern __shared__ float sm[];
    int jt = blockIdx.x, it = blockIdx.y, d = blockIdx.z;
    int tid = threadIdx.x;
    const float* Ab = g_A + (size_t)d * NN + (size_t)(it * 128) * 768;
    const float* Bb = g_B + (size_t)d * NN + (size_t)(jt * 128) * 768;

    auto ld = [&](int s, int kc) {
        float* S = sm + s * STG_F;
#pragma unroll
        for (int t = 0; t < 16; t++) {
            int idx = t * 128 + tid;
            int r = idx >> 3, c = (idx & 7) * 4;
            const float* g = (r < 128) ? Ab + (size_t)r * 768 + kc + c
                                       : Bb + (size_t)(r - 128) * 768 + kc + c;
            cpa(&S[r * ST + c], g);
        }
    };

    int wid = tid >> 5, lane = tid & 31;
    int wm = (wid >> 1) * 64, wn = (wid & 1) * 64;
    int qr = lane >> 2, qc = lane & 3;
    float acc[4][8][4] = {};

    ld(0, 0);  cp_commit();
    ld(1, 32); cp_commit();
#pragma unroll 1
    for (int c = 0; c < 24; c++) {
        cp_wait<1>();
        __syncthreads();
        int kn = (c + 2) * 32;
        if (kn < 768) ld((c + 2) % 3, kn);    // issue loads BEFORE compute
        cp_commit();
        float* S = sm + (c % 3) * STG_F;
        gemm64(S, S + 128 * ST, acc, wm, wn, lane);
    }

    float* outp = g_T + (size_t)d * NN;
#pragma unroll
    for (int mt = 0; mt < 4; mt++)
#pragma unroll
        for (int nt = 0; nt < 8; nt++) {
            int rm0 = it * 128 + wm + mt * 16 + qr;
            int cn  = jt * 128 + wn + nt * 8 + qc * 2;
            *(float2*)&outp[(size_t)rm0 * 768 + cn]       = make_float2(acc[mt][nt][0], acc[mt][nt][1]);
            *(float2*)&outp[(size_t)(rm0 + 8) * 768 + cn] = make_float2(acc[mt][nt][2], acc[mt][nt][3]);
        }
}

// ---------------- kernel 3: LN(t) folded into GEMM + gate ------------------------
__global__ void __launch_bounds__(256, 3) final_kernel(float* __restrict__ out) {
    extern __shared__ float sm[];
    float* sT   = sm;               // 128 d x 72 (64 j used)
    float* sW   = sm + 9216;        // 64 e x 132
    float* sS   = sm + 17664;       // 64
    float* sC   = sm + 17728;       // 64
    float* smm  = sm + 17792;       // 64
    float* sinv = sm + 17856;       // 64
    float* sred = sm + 17920;       // 512
    int h  = blockIdx.x;            // e-half
    int jt = blockIdx.y;
    int i  = blockIdx.z;
    int j0 = jt * 64, e0 = h * 64;
    int tid = threadIdx.x;

    const float* Tg = g_T + (size_t)i * 768 + j0;
#pragma unroll
    for (int t = 0; t < 8; t++) {
        int idx = t * 256 + tid;
        int dd = idx >> 4, c4 = (idx & 15) * 4;
        cpa(&sT[dd * 72 + c4], &Tg[(size_t)dd * NN + c4]);
    }
#pragma unroll
    for (int t = 0; t < 8; t++) {
        int idx = t * 256 + tid;
        int r = idx >> 5, c4 = (idx & 31) * 4;
        cpa(&sW[r * 132 + c4], &g_Pw[(size_t)(e0 + r) * 128 + c4]);
    }
    if (tid < 64) { sS[tid] = g_S[e0 + tid]; sC[tid] = g_C[e0 + tid]; }
    cp_commit();
    cp_wait<0>();
    __syncthreads();

    // stats pass (read-only; t fed raw to HMMA)
    {
        int h2 = tid >> 6, j = tid & 63;
        float s = 0.0f, s2 = 0.0f;
#pragma unroll 8
        for (int kk = 0; kk < 32; kk++) {
            int dd = h2 * 32 + kk;
            float v = sT[dd * 72 + j];
            s += v; s2 += v * v;
        }
        sred[h2 * 64 + j] = s;
        sred[256 + h2 * 64 + j] = s2;
    }
    __syncthreads();
    if (tid < 64) {
        float s  = sred[tid] + sred[64 + tid] + sred[128 + tid] + sred[192 + tid];
        float s2 = sred[256 + tid] + sred[320 + tid] + sred[384 + tid] + sred[448 + tid];
        float m   = s * (1.0f / 128.0f);
        float var = s2 * (1.0f / 128.0f) - m * m;
        smm[tid]  = m;
        sinv[tid] = rsqrtf(var + 1e-5f);
    }
    __syncthreads();

    int warp = tid >> 5, lane = tid & 31;
    int wm = (warp >> 1) * 16, wn = (warp & 1) * 32;
    int qr = lane >> 2, qc = lane & 3;
    float acc[4][4] = {};

#pragma unroll
    for (int k = 0; k < 128; k += 8) {
        unsigned af[4], bf[4][2];
        {
            int r = wm + qr;
            const float* p0 = sT + (k + qc) * 72 + r;
            const float* p1 = sT + (k + qc + 4) * 72 + r;
            af[0] = __float_as_uint(p0[0]);
            af[1] = __float_as_uint(p0[8]);
            af[2] = __float_as_uint(p1[0]);
            af[3] = __float_as_uint(p1[8]);
        }
#pragma unroll
        for (int nt = 0; nt < 4; nt++) {
            const float* p = sW + (wn + nt * 8 + qr) * 132 + k + qc;
            bf[nt][0] = __float_as_uint(p[0]);
            bf[nt][1] = __float_as_uint(p[4]);
        }
#pragma unroll
        for (int nt = 0; nt < 4; nt++)
            mma8(acc[nt], af, bf[nt]);
    }

    int rj = wm + qr;
    float inv0 = sinv[rj],     mb0 = -inv0 * smm[rj];
    float inv1 = sinv[rj + 8], mb1 = -inv1 * smm[rj + 8];
#pragma unroll
    for (int nt = 0; nt < 4; nt++) {
        int e = wn + nt * 8 + qc * 2;
        float S0 = sS[e], S1 = sS[e + 1];
        float C0 = sC[e], C1 = sC[e + 1];
        size_t ro0 = (size_t)(i * 768 + j0 + rj) * 128 + e0 + e;
        size_t ro1 = ro0 + 8 * 128;
        float2 gt0 = *(const float2*)&g_G[ro0];
        float2 gt1 = *(const float2*)&g_G[ro1];
        *(float2*)&out[ro0] = make_float2(gt0.x * (inv0 * acc[nt][0] + mb0 * S0 + C0),
                                          gt0.y * (inv0 * acc[nt][1] + mb0 * S1 + C1));
        *(float2*)&out[ro1] = make_float2(gt1.x * (inv1 * acc[nt][2] + mb1 * S0 + C0),
                                          gt1.y * (inv1 * acc[nt][3] + mb1 * S1 + C1));
    }
}

// ---------------- launch ---------------------------------------------------------
extern "C" void kernel_launch(void* const* d_in, const int* in_sizes, int n_in,
                              void* d_out, int out_size) {
    const float* x    = (const float*)d_in[0];
    const float* mask = (const float*)d_in[1];
    const float* niw  = (const float*)d_in[2];
    const float* nib  = (const float*)d_in[3];
    const float* giw  = (const float*)d_in[4];
    const float* piw  = (const float*)d_in[5];
    const float* now  = (const float*)d_in[6];
    const float* nob  = (const float*)d_in[7];
    const float* gow  = (const float*)d_in[8];
    const float* pwo  = (const float*)d_in[9];
    float* out = (float*)d_out;

    size_t sm_proj  = (size_t)(6 * PCH + 384) * 4;     // 112128 B
    size_t sm_bgemm = (size_t)(3 * STG_F) * 4;         // 110592 B
    size_t sm_final = 18432 * 4;                       // 73728 B
    cudaFuncSetAttribute(proj_kernel,  cudaFuncAttributeMaxDynamicSharedMemorySize, (int)sm_proj);
    cudaFuncSetAttribute(bgemm_kernel, cudaFuncAttributeMaxDynamicSharedMemorySize, (int)sm_bgemm);
    cudaFuncSetAttribute(final_kernel, cudaFuncAttributeMaxDynamicSharedMemorySize, (int)sm_final);

    prep_w_kernel<<<64, 256>>>(giw, piw, gow, pwo, now, nob);
    proj_kernel<<<4608, 256, sm_proj>>>(x, mask, niw, nib);
    bgemm_kernel<<<dim3(6, 6, 128), 128, sm_bgemm>>>();
    final_kernel<<<dim3(2, 12, 768), 256, sm_final>>>(out);
}

// round 12
// speedup vs baseline: 1.3833x; 1.0095x over previous
#include <cuda_runtime.h>
#include <cstdint>

#define NN (768*768)
#define ST 36            // smem row stride (floats) for 32-wide K chunks
#define PCH 4608         // floats per 128x36 chunk buffer

// ---------------- scratch -----------------------------------------------------
__device__ float g_A [(size_t)128 * NN];   // a transposed: [d][i*768+k]
__device__ float g_B [(size_t)128 * NN];   // b transposed: [d][j*768+k]
__device__ float g_T [(size_t)128 * NN];   // t transposed: [d][i*768+j]
__device__ float g_G [(size_t)NN * 128];   // sigmoid(xn @ g_out_w), [r][e]
__device__ float g_Wc[640 * 128];          // rows 0..511: interleaved (g,p); 512..639: g_out_w
__device__ float g_Pw[128 * 128];          // W' = now_w[d]*p_out_w[e,d], tf32
__device__ float g_S [128];                // S[e] = sum_d now_w[d]*p_out_w[e,d]
__device__ float g_C [128];                // C[e] = sum_d now_b[d]*p_out_w[e,d]

// ---------------- helpers ------------------------------------------------------
__device__ __forceinline__ float tf32r(float x) {
    unsigned u;
    asm("cvt.rna.tf32.f32 %0, %1;" : "=r"(u) : "f"(x));
    return __uint_as_float(u);
}

__device__ __forceinline__ void mma8(float c[4], const unsigned a[4], const unsigned b[2]) {
    asm volatile(
        "mma.sync.aligned.m16n8k8.row.col.f32.tf32.tf32.f32 "
        "{%0,%1,%2,%3},{%4,%5,%6,%7},{%8,%9},{%0,%1,%2,%3};"
        : "+f"(c[0]), "+f"(c[1]), "+f"(c[2]), "+f"(c[3])
        : "r"(a[0]), "r"(a[1]), "r"(a[2]), "r"(a[3]), "r"(b[0]), "r"(b[1]));
}

__device__ __forceinline__ void ldsm4(unsigned r[4], uint32_t a) {
    asm volatile("ldmatrix.sync.aligned.m8n8.x4.shared.b16 {%0,%1,%2,%3}, [%4];"
        : "=r"(r[0]), "=r"(r[1]), "=r"(r[2]), "=r"(r[3]) : "r"(a));
}

__device__ __forceinline__ void cpa(void* s, const void* g) {
    unsigned sa = (unsigned)__cvta_generic_to_shared(s);
    asm volatile("cp.async.cg.shared.global [%0], [%1], 16;" :: "r"(sa), "l"(g));
}
__device__ __forceinline__ void cp_commit() { asm volatile("cp.async.commit_group;"); }
template<int Nw> __device__ __forceinline__ void cp_wait() {
    asm volatile("cp.async.wait_group %0;" :: "n"(Nw));
}

// 64x64 warp tile, one K-chunk of 32 (bgemm). Fragments via ldmatrix.
__device__ __forceinline__ void gemm64(const float* sA, const float* sB,
                                       float acc[4][8][4],
                                       int wm, int wn, int lane) {
    uint32_t ab = (uint32_t)__cvta_generic_to_shared(sA);
    uint32_t bb = (uint32_t)__cvta_generic_to_shared(sB);
    int lr = lane & 7, grp = lane >> 3;
    uint32_t aoff = ab + (uint32_t)(((wm + lr + (grp & 1) * 8) * ST + (grp >> 1) * 4) * 4);
    uint32_t boff = bb + (uint32_t)(((wn + lr) * ST + grp * 4) * 4);
#pragma unroll
    for (int kp = 0; kp < 2; kp++) {           // k pairs {0,8}, {16,24}
        unsigned bf[8][4];
#pragma unroll
        for (int nt = 0; nt < 8; nt++)
            ldsm4(bf[nt], boff + (uint32_t)(nt * 8 * ST * 4 + kp * 64));
#pragma unroll
        for (int ks = 0; ks < 2; ks++) {
            unsigned af[4][4];
#pragma unroll
            for (int mt = 0; mt < 4; mt++)
                ldsm4(af[mt], aoff + (uint32_t)(mt * 16 * ST * 4 + (kp * 16 + ks * 8) * 4));
#pragma unroll
            for (int mt = 0; mt < 4; mt++)
#pragma unroll
                for (int nt = 0; nt < 8; nt++)
                    mma8(acc[mt][nt], af[mt], &bf[nt][ks * 2]);
        }
    }
}

// 64x32 warp tile, one K-chunk of 32 (proj). Same ldmatrix scheme, 4 nt.
__device__ __forceinline__ void gemm_c32(const float* sA, const float* sB,
                                         float acc[4][4][4],
                                         int wm, int wn, int lane) {
    uint32_t ab = (uint32_t)__cvta_generic_to_shared(sA);
    uint32_t bb = (uint32_t)__cvta_generic_to_shared(sB);
    int lr = lane & 7, grp = lane >> 3;
    uint32_t aoff = ab + (uint32_t)(((wm + lr + (grp & 1) * 8) * ST + (grp >> 1) * 4) * 4);
    uint32_t boff = bb + (uint32_t)(((wn + lr) * ST + grp * 4) * 4);
#pragma unroll
    for (int kp = 0; kp < 2; kp++) {
        unsigned bf[4][4];
#pragma unroll
        for (int nt = 0; nt < 4; nt++)
            ldsm4(bf[nt], boff + (uint32_t)(nt * 8 * ST * 4 + kp * 64));
#pragma unroll
        for (int ks = 0; ks < 2; ks++) {
            unsigned af[4][4];
#pragma unroll
            for (int mt = 0; mt < 4; mt++)
                ldsm4(af[mt], aoff + (uint32_t)(mt * 16 * ST * 4 + (kp * 16 + ks * 8) * 4));
#pragma unroll
            for (int mt = 0; mt < 4; mt++)
#pragma unroll
                for (int nt = 0; nt < 4; nt++)
                    mma8(acc[mt][nt], af[mt], &bf[nt][ks * 2]);
        }
    }
}

// ---------------- kernel 0: weight prep ----------------------------------------
__global__ void prep_w_kernel(const float* __restrict__ gin, const float* __restrict__ pin,
                              const float* __restrict__ gout, const float* __restrict__ pout,
                              const float* __restrict__ now, const float* __restrict__ nob) {
    int stride = gridDim.x * blockDim.x;
    int tid = threadIdx.x;
    for (int idx = blockIdx.x * blockDim.x + tid; idx < 256 * 128; idx += stride) {
        int e = idx >> 7, d = idx & 127;
        g_Wc[(2 * e) * 128 + d]     = tf32r(gin[idx]);
        g_Wc[(2 * e + 1) * 128 + d] = tf32r(pin[idx]);
    }
    for (int idx = blockIdx.x * blockDim.x + tid; idx < 128 * 128; idx += stride) {
        g_Wc[512 * 128 + idx] = tf32r(gout[idx]);
        g_Pw[idx]             = tf32r(pout[idx] * now[idx & 127]);   // W'
    }
    if (blockIdx.x == 0) {
        int e = tid >> 1, hh = tid & 1;
        float s = 0.0f, c = 0.0f;
        for (int d = hh * 64; d < hh * 64 + 64; d++) {
            float p = pout[e * 128 + d];
            s += now[d] * p;
            c += nob[d] * p;
        }
        s += __shfl_xor_sync(0xffffffffu, s, 1);
        c += __shfl_xor_sync(0xffffffffu, c, 1);
        if (hh == 0) { g_S[e] = s; g_C[e] = c; }
    }
}

// ---------------- kernel 1: fused LN(x) + all projections + gate + mask ----------
__global__ void __launch_bounds__(256, 2) proj_kernel(const float* __restrict__ x,
                                                      const float* __restrict__ mask,
                                                      const float* __restrict__ niw,
                                                      const float* __restrict__ nib) {
    extern __shared__ float sm[];
    float* WB  = sm + 4 * PCH;         // 2 x PCH W double-buffer
    float* msk = sm + 6 * PCH;         // 128
    float* wv  = msk + 128;            // 128
    float* bv  = wv + 128;             // 128
    int rt = blockIdx.x;
    int i = rt / 6, k0 = (rt % 6) * 128;
    int tid = threadIdx.x;

    if (tid < 128) {
        msk[tid] = mask[i * 768 + k0 + tid];
        wv[tid]  = niw[tid];
        bv[tid]  = nib[tid];
    }

    const float* Xb = x + (size_t)(i * 768 + k0) * 128;

    auto ldW = [&](int buf, int w, int chunk) {
#pragma unroll
        for (int t = 0; t < 4; t++) {
            int idx = t * 256 + tid;
            int r = idx >> 3, cc = (idx & 7) * 4;
            cpa(WB + buf * PCH + r * ST + cc,
                g_Wc + (size_t)w * 16384 + (size_t)r * 128 + chunk * 32 + cc);
        }
    };

    // A: all 4 chunks, one group
#pragma unroll
    for (int c = 0; c < 4; c++)
#pragma unroll
        for (int t = 0; t < 4; t++) {
            int idx = t * 256 + tid;
            int r = idx >> 3, cc = (idx & 7) * 4;
            cpa(sm + c * PCH + r * ST + cc, Xb + (size_t)r * 128 + c * 32 + cc);
        }
    cp_commit();
    ldW(0, 0, 0); cp_commit();
    ldW(1, 0, 1); cp_commit();

    cp_wait<2>();        // A complete
    __syncthreads();

    // In-smem LayerNorm: 4 threads per row, k = 4*kk + h (conflict-free).
    {
        int h = tid & 3, q = tid >> 2;
#pragma unroll
        for (int pass = 0; pass < 2; pass++) {
            int r = pass * 64 + q;
            float s = 0.0f, s2 = 0.0f;
#pragma unroll
            for (int kk = 0; kk < 32; kk++) {
                int kg = 4 * kk + h;
                float v = sm[(kg >> 5) * PCH + r * ST + (kg & 31)];
                s += v; s2 += v * v;
            }
            s  += __shfl_xor_sync(0xffffffffu, s,  1);
            s2 += __shfl_xor_sync(0xffffffffu, s2, 1);
            s  += __shfl_xor_sync(0xffffffffu, s,  2);
            s2 += __shfl_xor_sync(0xffffffffu, s2, 2);
            float m   = s * (1.0f / 128.0f);
            float var = s2 * (1.0f / 128.0f) - m * m;
            float inv = rsqrtf(var + 1e-5f);
#pragma unroll
            for (int kk = 0; kk < 32; kk++) {
                int kg = 4 * kk + h;
                float* p = sm + (kg >> 5) * PCH + r * ST + (kg & 31);
                *p = tf32r((*p - m) * inv * wv[kg] + bv[kg]);
            }
        }
    }

    int warp = tid >> 5, lane = tid & 31;
    int wm = (warp >> 2) * 64, wn = (warp & 3) * 32;
    int qr = lane >> 2, qc = lane & 3;

#pragma unroll 1
    for (int w = 0; w < 5; w++) {
        float acc[4][4][4] = {};
#pragma unroll 1
        for (int c = 0; c < 4; c++) {
            cp_wait<1>();
            __syncthreads();            // publishes LN writes on first iter
            gemm_c32(sm + c * PCH, WB + (c & 1) * PCH, acc, wm, wn, lane);
            __syncthreads();            // buffer reads done before refill
            if (c < 2)       ldW(c & 1, w, c + 2);          // this tile chunks 2,3
            else if (w < 4)  ldW(c & 1, w + 1, c - 2);      // next tile chunks 0,1
            cp_commit();
        }

        // epilogue: direct from accumulators, no syncs (loads for w+1 in flight)
        if (w == 4) {
#pragma unroll
            for (int mt = 0; mt < 4; mt++)
#pragma unroll
                for (int nt = 0; nt < 4; nt++) {
                    int rm0 = wm + mt * 16 + qr, rm1 = rm0 + 8;
                    int cn = wn + nt * 8 + qc * 2;
                    size_t r0 = (size_t)(i * 768 + k0 + rm0) * 128 + cn;
                    size_t r1 = (size_t)(i * 768 + k0 + rm1) * 128 + cn;
                    *(float2*)&g_G[r0] = make_float2(1.0f / (1.0f + __expf(-acc[mt][nt][0])),
                                                     1.0f / (1.0f + __expf(-acc[mt][nt][1])));
                    *(float2*)&g_G[r1] = make_float2(1.0f / (1.0f + __expf(-acc[mt][nt][2])),
                                                     1.0f / (1.0f + __expf(-acc[mt][nt][3])));
                }
        } else {
            bool isA = (w < 2);
#pragma unroll
            for (int mt = 0; mt < 4; mt++)
#pragma unroll
                for (int nt = 0; nt < 4; nt++) {
                    int rm0 = wm + mt * 16 + qr, rm1 = rm0 + 8;
                    int chl = (wn >> 1) + nt * 4 + qc;
                    float v0 = acc[mt][nt][1] * (1.0f / (1.0f + __expf(-acc[mt][nt][0])));
                    float v1 = acc[mt][nt][3] * (1.0f / (1.0f + __expf(-acc[mt][nt][2])));
                    if (isA) { v0 *= msk[rm0]; v1 *= msk[rm1]; }
                    int ch = w * 64 + chl;
                    float* dst = (ch < 128) ? (g_A + (size_t)ch * NN)
                                            : (g_B + (size_t)(ch - 128) * NN);
                    dst[i * 768 + k0 + rm0] = tf32r(v0);
                    dst[i * 768 + k0 + rm1] = tf32r(v1);
                }
        }
    }
}

// ---------------- kernel 2: batched einsum  t_d = A_d @ B_d^T --------------------
#define STG_F 9216
__global__ void __launch_bounds__(128, 2) bgemm_kernel() {
    extern __shared__ float sm[];
    int jt = blockIdx.x, it = blockIdx.y, d = blockIdx.z;
    int tid = threadIdx.x;
    const float* Ab = g_A + (size_t)d * NN + (size_t)(it * 128) * 768;
    const float* Bb = g_B + (size_t)d * NN + (size_t)(jt * 128) * 768;

    auto ld = [&](int s, int kc) {
        float* S = sm + s * STG_F;
#pragma unroll
        for (int t = 0; t < 16; t++) {
            int idx = t * 128 + tid;
            int r = idx >> 3, c = (idx & 7) * 4;
            const float* g = (r < 128) ? Ab + (size_t)r * 768 + kc + c
                                       : Bb + (size_t)(r - 128) * 768 + kc + c;
            cpa(&S[r * ST + c], g);
        }
    };

    int wid = tid >> 5, lane = tid & 31;
    int wm = (wid >> 1) * 64, wn = (wid & 1) * 64;
    int qr = lane >> 2, qc = lane & 3;
    float acc[4][8][4] = {};

    ld(0, 0);  cp_commit();
    ld(1, 32); cp_commit();
#pragma unroll 1
    for (int c = 0; c < 24; c++) {
        cp_wait<1>();
        __syncthreads();
        int kn = (c + 2) * 32;
        if (kn < 768) ld((c + 2) % 3, kn);    // issue loads BEFORE compute
        cp_commit();
        float* S = sm + (c % 3) * STG_F;
        gemm64(S, S + 128 * ST, acc, wm, wn, lane);
    }

    float* outp = g_T + (size_t)d * NN;
#pragma unroll
    for (int mt = 0; mt < 4; mt++)
#pragma unroll
        for (int nt = 0; nt < 8; nt++) {
            int rm0 = it * 128 + wm + mt * 16 + qr;
            int cn  = jt * 128 + wn + nt * 8 + qc * 2;
            *(float2*)&outp[(size_t)rm0 * 768 + cn]       = make_float2(acc[mt][nt][0], acc[mt][nt][1]);
            *(float2*)&outp[(size_t)(rm0 + 8) * 768 + cn] = make_float2(acc[mt][nt][2], acc[mt][nt][3]);
        }
}

// ---------------- kernel 3: LN(t) folded into GEMM + gate ------------------------
// Merged e-halves: one block = 64 j x 128 e. t tile loaded ONCE, stats ONCE.
// Warps 4(m) x 2(n): each 16 j x 64 e. W fragments via ldmatrix. K loop kp<8.
__global__ void __launch_bounds__(256, 2) final_kernel(float* __restrict__ out) {
    extern __shared__ float sm[];
    float* sT   = sm;               // 128 d x 72 (64 j used)
    float* sW   = sm + 9216;        // 128 e x 132
    float* sS   = sm + 26112;       // 128
    float* sC   = sm + 26240;       // 128
    float* smm  = sm + 26368;       // 64
    float* sinv = sm + 26432;       // 64
    float* sred = sm + 26496;       // 512
    int jt = blockIdx.x;
    int i  = blockIdx.y;
    int j0 = jt * 64;
    int tid = threadIdx.x;

    const float* Tg = g_T + (size_t)i * 768 + j0;
#pragma unroll
    for (int t = 0; t < 8; t++) {
        int idx = t * 256 + tid;
        int dd = idx >> 4, c4 = (idx & 15) * 4;
        cpa(&sT[dd * 72 + c4], &Tg[(size_t)dd * NN + c4]);
    }
#pragma unroll
    for (int t = 0; t < 16; t++) {
        int idx = t * 256 + tid;
        int r = idx >> 5, c4 = (idx & 31) * 4;
        cpa(&sW[r * 132 + c4], &g_Pw[(size_t)r * 128 + c4]);
    }
    if (tid < 128) { sS[tid] = g_S[tid]; sC[tid] = g_C[tid]; }
    cp_commit();
    cp_wait<0>();
    __syncthreads();

    // stats pass (read-only; t fed raw to HMMA)
    {
        int h2 = tid >> 6, j = tid & 63;
        float s = 0.0f, s2 = 0.0f;
#pragma unroll 8
        for (int kk = 0; kk < 32; kk++) {
            int dd = h2 * 32 + kk;
            float v = sT[dd * 72 + j];
            s += v; s2 += v * v;
        }
        sred[h2 * 64 + j] = s;
        sred[256 + h2 * 64 + j] = s2;
    }
    __syncthreads();
    if (tid < 64) {
        float s  = sred[tid] + sred[64 + tid] + sred[128 + tid] + sred[192 + tid];
        float s2 = sred[256 + tid] + sred[320 + tid] + sred[384 + tid] + sred[448 + tid];
        float m   = s * (1.0f / 128.0f);
        float var = s2 * (1.0f / 128.0f) - m * m;
        smm[tid]  = m;
        sinv[tid] = rsqrtf(var + 1e-5f);
    }
    __syncthreads();

    int warp = tid >> 5, lane = tid & 31;
    int wm = (warp & 3) * 16, wn = (warp >> 2) * 64;
    int qr = lane >> 2, qc = lane & 3;
    int lr = lane & 7, grp = lane >> 3;
    float acc[8][4] = {};

    uint32_t bb = (uint32_t)__cvta_generic_to_shared(sW);
    uint32_t boff = bb + (uint32_t)(((wn + lr) * 132 + grp * 4) * 4);

#pragma unroll
    for (int kp = 0; kp < 8; kp++) {          // each kp covers k = kp*16 .. kp*16+15
        unsigned bf[8][4];
#pragma unroll
        for (int nt = 0; nt < 8; nt++)
            ldsm4(bf[nt], boff + (uint32_t)(nt * 8 * 132 * 4 + kp * 64));
#pragma unroll
        for (int ks = 0; ks < 2; ks++) {
            int k = kp * 16 + ks * 8;
            unsigned af[4];
            {
                int r = wm + qr;
                const float* p0 = sT + (k + qc) * 72 + r;
                const float* p1 = sT + (k + qc + 4) * 72 + r;
                af[0] = __float_as_uint(p0[0]);
                af[1] = __float_as_uint(p0[8]);
                af[2] = __float_as_uint(p1[0]);
                af[3] = __float_as_uint(p1[8]);
            }
#pragma unroll
            for (int nt = 0; nt < 8; nt++)
                mma8(acc[nt], af, &bf[nt][ks * 2]);
        }
    }

    int rj = wm + qr;
    float inv0 = sinv[rj],     mb0 = -inv0 * smm[rj];
    float inv1 = sinv[rj + 8], mb1 = -inv1 * smm[rj + 8];
#pragma unroll
    for (int nt = 0; nt < 8; nt++) {
        int e = wn + nt * 8 + qc * 2;
        float S0 = sS[e], S1 = sS[e + 1];
        float C0 = sC[e], C1 = sC[e + 1];
        size_t ro0 = (size_t)(i * 768 + j0 + rj) * 128 + e;
        size_t ro1 = ro0 + 8 * 128;
        float2 gt0 = *(const float2*)&g_G[ro0];
        float2 gt1 = *(const float2*)&g_G[ro1];
        *(float2*)&out[ro0] = make_float2(gt0.x * (inv0 * acc[nt][0] + mb0 * S0 + C0),
                                          gt0.y * (inv0 * acc[nt][1] + mb0 * S1 + C1));
        *(float2*)&out[ro1] = make_float2(gt1.x * (inv1 * acc[nt][2] + mb1 * S0 + C0),
                                          gt1.y * (inv1 * acc[nt][3] + mb1 * S1 + C1));
    }
}

// ---------------- launch ---------------------------------------------------------
extern "C" void kernel_launch(void* const* d_in, const int* in_sizes, int n_in,
                              void* d_out, int out_size) {
    const float* x    = (const float*)d_in[0];
    const float* mask = (const float*)d_in[1];
    const float* niw  = (const float*)d_in[2];
    const float* nib  = (const float*)d_in[3];
    const float* giw  = (const float*)d_in[4];
    const float* piw  = (const float*)d_in[5];
    const float* now  = (const float*)d_in[6];
    const float* nob  = (const float*)d_in[7];
    const float* gow  = (const float*)d_in[8];
    const float* pwo  = (const float*)d_in[9];
    float* out = (float*)d_out;

    size_t sm_proj  = (size_t)(6 * PCH + 384) * 4;     // 112128 B
    size_t sm_bgemm = (size_t)(3 * STG_F) * 4;         // 110592 B
    size_t sm_final = 27008 * 4;                       // 108032 B
    cudaFuncSetAttribute(proj_kernel,  cudaFuncAttributeMaxDynamicSharedMemorySize, (int)sm_proj);
    cudaFuncSetAttribute(bgemm_kernel, cudaFuncAttributeMaxDynamicSharedMemorySize, (int)sm_bgemm);
    cudaFuncSetAttribute(final_kernel, cudaFuncAttributeMaxDynamicSharedMemorySize, (int)sm_final);

    prep_w_kernel<<<64, 256>>>(giw, piw, gow, pwo, now, nob);
    proj_kernel<<<4608, 256, sm_proj>>>(x, mask, niw, nib);
    bgemm_kernel<<<dim3(6, 6, 128), 128, sm_bgemm>>>();
    final_kernel<<<dim3(12, 768), 256, sm_final>>>(out);
}

// round 13
// speedup vs baseline: 1.4329x; 1.0358x over previous
#include <cuda_runtime.h>
#include <cstdint>

#define NN (768*768)
#define ST 36            // smem row stride (floats) for 32-wide K chunks
#define PCH 4608         // floats per 128x36 chunk buffer

// ---------------- scratch -----------------------------------------------------
__device__ float g_A [(size_t)128 * NN];   // a transposed: [d][i*768+k]
__device__ float g_B [(size_t)128 * NN];   // b transposed: [d][j*768+k]
__device__ float g_T [(size_t)128 * NN];   // t transposed: [d][i*768+j]
__device__ float g_G [(size_t)NN * 128];   // sigmoid(xn @ g_out_w), [r][e]
__device__ float g_Wc[640 * 128];          // rows 0..511: interleaved (g,p); 512..639: g_out_w
__device__ float g_Pw[128 * 128];          // W' = now_w[d]*p_out_w[e,d], tf32
__device__ float g_S [128];                // S[e] = sum_d now_w[d]*p_out_w[e,d]
__device__ float g_C [128];                // C[e] = sum_d now_b[d]*p_out_w[e,d]

// ---------------- helpers ------------------------------------------------------
__device__ __forceinline__ float tf32r(float x) {
    unsigned u;
    asm("cvt.rna.tf32.f32 %0, %1;" : "=r"(u) : "f"(x));
    return __uint_as_float(u);
}

__device__ __forceinline__ void mma8(float c[4], const unsigned a[4], const unsigned b[2]) {
    asm volatile(
        "mma.sync.aligned.m16n8k8.row.col.f32.tf32.tf32.f32 "
        "{%0,%1,%2,%3},{%4,%5,%6,%7},{%8,%9},{%0,%1,%2,%3};"
        : "+f"(c[0]), "+f"(c[1]), "+f"(c[2]), "+f"(c[3])
        : "r"(a[0]), "r"(a[1]), "r"(a[2]), "r"(a[3]), "r"(b[0]), "r"(b[1]));
}

__device__ __forceinline__ void ldsm4(unsigned r[4], uint32_t a) {
    asm volatile("ldmatrix.sync.aligned.m8n8.x4.shared.b16 {%0,%1,%2,%3}, [%4];"
        : "=r"(r[0]), "=r"(r[1]), "=r"(r[2]), "=r"(r[3]) : "r"(a));
}

__device__ __forceinline__ void cpa(void* s, const void* g) {
    unsigned sa = (unsigned)__cvta_generic_to_shared(s);
    asm volatile("cp.async.cg.shared.global [%0], [%1], 16;" :: "r"(sa), "l"(g));
}
__device__ __forceinline__ void cp_commit() { asm volatile("cp.async.commit_group;"); }
template<int Nw> __device__ __forceinline__ void cp_wait() {
    asm volatile("cp.async.wait_group %0;" :: "n"(Nw));
}
__device__ __forceinline__ void pair_bar(int id) {
    asm volatile("bar.sync %0, 64;" :: "r"(id) : "memory");
}

// 64x64 warp tile, one K-chunk of 32 (bgemm). Fragments via ldmatrix.
__device__ __forceinline__ void gemm64(const float* sA, const float* sB,
                                       float acc[4][8][4],
                                       int wm, int wn, int lane) {
    uint32_t ab = (uint32_t)__cvta_generic_to_shared(sA);
    uint32_t bb = (uint32_t)__cvta_generic_to_shared(sB);
    int lr = lane & 7, grp = lane >> 3;
    uint32_t aoff = ab + (uint32_t)(((wm + lr + (grp & 1) * 8) * ST + (grp >> 1) * 4) * 4);
    uint32_t boff = bb + (uint32_t)(((wn + lr) * ST + grp * 4) * 4);
#pragma unroll
    for (int kp = 0; kp < 2; kp++) {           // k pairs {0,8}, {16,24}
        unsigned bf[8][4];
#pragma unroll
        for (int nt = 0; nt < 8; nt++)
            ldsm4(bf[nt], boff + (uint32_t)(nt * 8 * ST * 4 + kp * 64));
#pragma unroll
        for (int ks = 0; ks < 2; ks++) {
            unsigned af[4][4];
#pragma unroll
            for (int mt = 0; mt < 4; mt++)
                ldsm4(af[mt], aoff + (uint32_t)(mt * 16 * ST * 4 + (kp * 16 + ks * 8) * 4));
#pragma unroll
            for (int mt = 0; mt < 4; mt++)
#pragma unroll
                for (int nt = 0; nt < 8; nt++)
                    mma8(acc[mt][nt], af[mt], &bf[nt][ks * 2]);
        }
    }
}

// 64x32 warp tile, one K-chunk of 32 (proj). Same ldmatrix scheme, 4 nt.
__device__ __forceinline__ void gemm_c32(const float* sA, const float* sB,
                                         float acc[4][4][4],
                                         int wm, int wn, int lane) {
    uint32_t ab = (uint32_t)__cvta_generic_to_shared(sA);
    uint32_t bb = (uint32_t)__cvta_generic_to_shared(sB);
    int lr = lane & 7, grp = lane >> 3;
    uint32_t aoff = ab + (uint32_t)(((wm + lr + (grp & 1) * 8) * ST + (grp >> 1) * 4) * 4);
    uint32_t boff = bb + (uint32_t)(((wn + lr) * ST + grp * 4) * 4);
#pragma unroll
    for (int kp = 0; kp < 2; kp++) {
        unsigned bf[4][4];
#pragma unroll
        for (int nt = 0; nt < 4; nt++)
            ldsm4(bf[nt], boff + (uint32_t)(nt * 8 * ST * 4 + kp * 64));
#pragma unroll
        for (int ks = 0; ks < 2; ks++) {
            unsigned af[4][4];
#pragma unroll
            for (int mt = 0; mt < 4; mt++)
                ldsm4(af[mt], aoff + (uint32_t)(mt * 16 * ST * 4 + (kp * 16 + ks * 8) * 4));
#pragma unroll
            for (int mt = 0; mt < 4; mt++)
#pragma unroll
                for (int nt = 0; nt < 4; nt++)
                    mma8(acc[mt][nt], af[mt], &bf[nt][ks * 2]);
        }
    }
}

// ---------------- kernel 0: weight prep ----------------------------------------
__global__ void prep_w_kernel(const float* __restrict__ gin, const float* __restrict__ pin,
                              const float* __restrict__ gout, const float* __restrict__ pout,
                              const float* __restrict__ now, const float* __restrict__ nob) {
    int stride = gridDim.x * blockDim.x;
    int tid = threadIdx.x;
    for (int idx = blockIdx.x * blockDim.x + tid; idx < 256 * 128; idx += stride) {
        int e = idx >> 7, d = idx & 127;
        g_Wc[(2 * e) * 128 + d]     = tf32r(gin[idx]);
        g_Wc[(2 * e + 1) * 128 + d] = tf32r(pin[idx]);
    }
    for (int idx = blockIdx.x * blockDim.x + tid; idx < 128 * 128; idx += stride) {
        g_Wc[512 * 128 + idx] = tf32r(gout[idx]);
        g_Pw[idx]             = tf32r(pout[idx] * now[idx & 127]);   // W'
    }
    if (blockIdx.x == 0) {
        int e = tid >> 1, hh = tid & 1;
        float s = 0.0f, c = 0.0f;
        for (int d = hh * 64; d < hh * 64 + 64; d++) {
            float p = pout[e * 128 + d];
            s += now[d] * p;
            c += nob[d] * p;
        }
        s += __shfl_xor_sync(0xffffffffu, s, 1);
        c += __shfl_xor_sync(0xffffffffu, c, 1);
        if (hh == 0) { g_S[e] = s; g_C[e] = c; }
    }
}

// ---------------- kernel 1: fused LN(x) + all projections + gate + mask ----------
// Pair-local W refill: W rows wn..wn+31 are read ONLY by warps {w, w+4}; that pair
// refills its own rows -> per-chunk sync is a 2-warp named barrier, not CTA-wide.
__global__ void __launch_bounds__(256, 2) proj_kernel(const float* __restrict__ x,
                                                      const float* __restrict__ mask,
                                                      const float* __restrict__ niw,
                                                      const float* __restrict__ nib) {
    extern __shared__ float sm[];
    float* WB  = sm + 4 * PCH;         // 2 x PCH W double-buffer
    float* msk = sm + 6 * PCH;         // 128
    float* wv  = msk + 128;            // 128
    float* bv  = wv + 128;             // 128
    int rt = blockIdx.x;
    int i = rt / 6, k0 = (rt % 6) * 128;
    int tid = threadIdx.x;

    if (tid < 128) {
        msk[tid] = mask[i * 768 + k0 + tid];
        wv[tid]  = niw[tid];
        bv[tid]  = nib[tid];
    }

    const float* Xb = x + (size_t)(i * 768 + k0) * 128;

    int warp = tid >> 5, lane = tid & 31;
    int pid  = warp & 3;                       // pair id (warps pid and pid+4)
    int barid = 1 + pid;
    int tau  = ((warp >> 2) << 5) + lane;      // 0..63 within pair

    // pair-partitioned W chunk load: rows [32*pid, 32*pid+32)
    auto ldW_pair = [&](int buf, int w, int ch) {
#pragma unroll
        for (int t = 0; t < 4; t++) {
            int f4 = t * 64 + tau;             // 0..255
            int r  = (pid << 5) + (f4 >> 3);
            int c4 = (f4 & 7) * 4;
            cpa(WB + buf * PCH + r * ST + c4,
                g_Wc + (size_t)w * 16384 + (size_t)r * 128 + ch * 32 + c4);
        }
    };

    // A: all 4 chunks, one group
#pragma unroll
    for (int c = 0; c < 4; c++)
#pragma unroll
        for (int t = 0; t < 4; t++) {
            int idx = t * 256 + tid;
            int r = idx >> 3, cc = (idx & 7) * 4;
            cpa(sm + c * PCH + r * ST + cc, Xb + (size_t)r * 128 + c * 32 + cc);
        }
    cp_commit();
    ldW_pair(0, 0, 0); cp_commit();
    ldW_pair(1, 0, 1); cp_commit();

    cp_wait<2>();        // A complete
    __syncthreads();

    // In-smem LayerNorm: 4 threads per row, k = 4*kk + h (conflict-free).
    {
        int h = tid & 3, q = tid >> 2;
#pragma unroll
        for (int pass = 0; pass < 2; pass++) {
            int r = pass * 64 + q;
            float s = 0.0f, s2 = 0.0f;
#pragma unroll
            for (int kk = 0; kk < 32; kk++) {
                int kg = 4 * kk + h;
                float v = sm[(kg >> 5) * PCH + r * ST + (kg & 31)];
                s += v; s2 += v * v;
            }
            s  += __shfl_xor_sync(0xffffffffu, s,  1);
            s2 += __shfl_xor_sync(0xffffffffu, s2, 1);
            s  += __shfl_xor_sync(0xffffffffu, s,  2);
            s2 += __shfl_xor_sync(0xffffffffu, s2, 2);
            float m   = s * (1.0f / 128.0f);
            float var = s2 * (1.0f / 128.0f) - m * m;
            float inv = rsqrtf(var + 1e-5f);
#pragma unroll
            for (int kk = 0; kk < 32; kk++) {
                int kg = 4 * kk + h;
                float* p = sm + (kg >> 5) * PCH + r * ST + (kg & 31);
                *p = tf32r((*p - m) * inv * wv[kg] + bv[kg]);
            }
        }
    }
    __syncthreads();     // publish LN writes; A is read-only hereafter

    int wm = (warp >> 2) * 64, wn = (warp & 3) * 32;
    int qr = lane >> 2, qc = lane & 3;

#pragma unroll 1
    for (int w = 0; w < 5; w++) {
        float acc[4][4][4] = {};
#pragma unroll 1
        for (int c = 0; c < 4; c++) {
            cp_wait<1>();
            pair_bar(barid);            // pair's loads for this buffer visible
            gemm_c32(sm + c * PCH, WB + (c & 1) * PCH, acc, wm, wn, lane);
            pair_bar(barid);            // pair done reading before refill
            if (c < 2)       ldW_pair(c & 1, w, c + 2);     // this tile chunks 2,3
            else if (w < 4)  ldW_pair(c & 1, w + 1, c - 2); // next tile chunks 0,1
            cp_commit();
        }

        // epilogue: direct from accumulators (loads for w+1 in flight)
        if (w == 4) {
#pragma unroll
            for (int mt = 0; mt < 4; mt++)
#pragma unroll
                for (int nt = 0; nt < 4; nt++) {
                    int rm0 = wm + mt * 16 + qr, rm1 = rm0 + 8;
                    int cn = wn + nt * 8 + qc * 2;
                    size_t r0 = (size_t)(i * 768 + k0 + rm0) * 128 + cn;
                    size_t r1 = (size_t)(i * 768 + k0 + rm1) * 128 + cn;
                    *(float2*)&g_G[r0] = make_float2(1.0f / (1.0f + __expf(-acc[mt][nt][0])),
                                                     1.0f / (1.0f + __expf(-acc[mt][nt][1])));
                    *(float2*)&g_G[r1] = make_float2(1.0f / (1.0f + __expf(-acc[mt][nt][2])),
                                                     1.0f / (1.0f + __expf(-acc[mt][nt][3])));
                }
        } else {
            bool isA = (w < 2);
#pragma unroll
            for (int mt = 0; mt < 4; mt++)
#pragma unroll
                for (int nt = 0; nt < 4; nt++) {
                    int rm0 = wm + mt * 16 + qr, rm1 = rm0 + 8;
                    int chl = (wn >> 1) + nt * 4 + qc;
                    float v0 = acc[mt][nt][1] * (1.0f / (1.0f + __expf(-acc[mt][nt][0])));
                    float v1 = acc[mt][nt][3] * (1.0f / (1.0f + __expf(-acc[mt][nt][2])));
                    if (isA) { v0 *= msk[rm0]; v1 *= msk[rm1]; }
                    int ch = w * 64 + chl;
                    float* dst = (ch < 128) ? (g_A + (size_t)ch * NN)
                                            : (g_B + (size_t)(ch - 128) * NN);
                    dst[i * 768 + k0 + rm0] = tf32r(v0);
                    dst[i * 768 + k0 + rm1] = tf32r(v1);
                }
        }
    }
}

// ---------------- kernel 2: batched einsum  t_d = A_d @ B_d^T --------------------
#define STG_F 9216
__global__ void __launch_bounds__(128, 2) bgemm_kernel() {
    extern __shared__ float sm[];
    int jt = blockIdx.x, it = blockIdx.y, d = blockIdx.z;
    int tid = threadIdx.x;
    const float* Ab = g_A + (size_t)d * NN + (size_t)(it * 128) * 768;
    const float* Bb = g_B + (size_t)d * NN + (size_t)(jt * 128) * 768;

    auto ld = [&](int s, int kc) {
        float* S = sm + s * STG_F;
#pragma unroll
        for (int t = 0; t < 16; t++) {
            int idx = t * 128 + tid;
            int r = idx >> 3, c = (idx & 7) * 4;
            const float* g = (r < 128) ? Ab + (size_t)r * 768 + kc + c
                                       : Bb + (size_t)(r - 128) * 768 + kc + c;
            cpa(&S[r * ST + c], g);
        }
    };

    int wid = tid >> 5, lane = tid & 31;
    int wm = (wid >> 1) * 64, wn = (wid & 1) * 64;
    int qr = lane >> 2, qc = lane & 3;
    float acc[4][8][4] = {};

    ld(0, 0);  cp_commit();
    ld(1, 32); cp_commit();
#pragma unroll 1
    for (int c = 0; c < 24; c++) {
        cp_wait<1>();
        __syncthreads();
        int kn = (c + 2) * 32;
        if (kn < 768) ld((c + 2) % 3, kn);    // issue loads BEFORE compute
        cp_commit();
        float* S = sm + (c % 3) * STG_F;
        gemm64(S, S + 128 * ST, acc, wm, wn, lane);
    }

    float* outp = g_T + (size_t)d * NN;
#pragma unroll
    for (int mt = 0; mt < 4; mt++)
#pragma unroll
        for (int nt = 0; nt < 8; nt++) {
            int rm0 = it * 128 + wm + mt * 16 + qr;
            int cn  = jt * 128 + wn + nt * 8 + qc * 2;
            *(float2*)&outp[(size_t)rm0 * 768 + cn]       = make_float2(acc[mt][nt][0], acc[mt][nt][1]);
            *(float2*)&outp[(size_t)(rm0 + 8) * 768 + cn] = make_float2(acc[mt][nt][2], acc[mt][nt][3]);
        }
}

// ---------------- kernel 3: LN(t) folded into GEMM + gate ------------------------
// One block = 128-wide j tile processed as two 64-j subtiles; W loaded ONCE.
// Second subtile's t load overlaps first subtile's epilogue stores.
__global__ void __launch_bounds__(256, 2) final_kernel(float* __restrict__ out) {
    extern __shared__ float sm[];
    float* sT   = sm;               // 128 d x 72 (64 j used)
    float* sW   = sm + 9216;        // 128 e x 132
    float* sS   = sm + 26112;       // 128
    float* sC   = sm + 26240;       // 128
    float* smm  = sm + 26368;       // 64
    float* sinv = sm + 26432;       // 64
    float* sred = sm + 26496;       // 512
    int jt = blockIdx.x;            // 0..5 (128-wide)
    int i  = blockIdx.y;
    int tid = threadIdx.x;

    const float* Tg = g_T + (size_t)i * 768 + jt * 128;

    // W + S/C once; t subtile 0
#pragma unroll
    for (int t = 0; t < 16; t++) {
        int idx = t * 256 + tid;
        int r = idx >> 5, c4 = (idx & 31) * 4;
        cpa(&sW[r * 132 + c4], &g_Pw[(size_t)r * 128 + c4]);
    }
    if (tid < 128) { sS[tid] = g_S[tid]; sC[tid] = g_C[tid]; }
#pragma unroll
    for (int t = 0; t < 8; t++) {
        int idx = t * 256 + tid;
        int dd = idx >> 4, c4 = (idx & 15) * 4;
        cpa(&sT[dd * 72 + c4], &Tg[(size_t)dd * NN + c4]);
    }
    cp_commit();

    int warp = tid >> 5, lane = tid & 31;
    int wm = (warp & 3) * 16, wn = (warp >> 2) * 64;
    int qr = lane >> 2, qc = lane & 3;
    int lr = lane & 7, grp = lane >> 3;
    uint32_t bb = (uint32_t)__cvta_generic_to_shared(sW);
    uint32_t boff = bb + (uint32_t)(((wn + lr) * 132 + grp * 4) * 4);

#pragma unroll 1
    for (int sub = 0; sub < 2; sub++) {
        int j0 = jt * 128 + sub * 64;
        cp_wait<0>();
        __syncthreads();

        // stats pass (read-only; t fed raw to HMMA)
        {
            int h2 = tid >> 6, j = tid & 63;
            float s = 0.0f, s2 = 0.0f;
#pragma unroll 8
            for (int kk = 0; kk < 32; kk++) {
                int dd = h2 * 32 + kk;
                float v = sT[dd * 72 + j];
                s += v; s2 += v * v;
            }
            sred[h2 * 64 + j] = s;
            sred[256 + h2 * 64 + j] = s2;
        }
        __syncthreads();
        if (tid < 64) {
            float s  = sred[tid] + sred[64 + tid] + sred[128 + tid] + sred[192 + tid];
            float s2 = sred[256 + tid] + sred[320 + tid] + sred[384 + tid] + sred[448 + tid];
            float m   = s * (1.0f / 128.0f);
            float var = s2 * (1.0f / 128.0f) - m * m;
            smm[tid]  = m;
            sinv[tid] = rsqrtf(var + 1e-5f);
        }
        __syncthreads();

        float acc[8][4] = {};
#pragma unroll
        for (int kp = 0; kp < 8; kp++) {      // each kp covers k = kp*16 .. +15
            unsigned bf[8][4];
#pragma unroll
            for (int nt = 0; nt < 8; nt++)
                ldsm4(bf[nt], boff + (uint32_t)(nt * 8 * 132 * 4 + kp * 64));
#pragma unroll
            for (int ks = 0; ks < 2; ks++) {
                int k = kp * 16 + ks * 8;
                unsigned af[4];
                {
                    int r = wm + qr;
                    const float* p0 = sT + (k + qc) * 72 + r;
                    const float* p1 = sT + (k + qc + 4) * 72 + r;
                    af[0] = __float_as_uint(p0[0]);
                    af[1] = __float_as_uint(p0[8]);
                    af[2] = __float_as_uint(p1[0]);
                    af[3] = __float_as_uint(p1[8]);
                }
#pragma unroll
                for (int nt = 0; nt < 8; nt++)
                    mma8(acc[nt], af, &bf[nt][ks * 2]);
            }
        }

        __syncthreads();                     // all sT reads done
        if (sub == 0) {                      // prefetch subtile 1 during epilogue
            const float* Tg1 = Tg + 64;
#pragma unroll
            for (int t = 0; t < 8; t++) {
                int idx = t * 256 + tid;
                int dd = idx >> 4, c4 = (idx & 15) * 4;
                cpa(&sT[dd * 72 + c4], &Tg1[(size_t)dd * NN + c4]);
            }
            cp_commit();
        }

        int rj = wm + qr;
        float inv0 = sinv[rj],     mb0 = -inv0 * smm[rj];
        float inv1 = sinv[rj + 8], mb1 = -inv1 * smm[rj + 8];
#pragma unroll
        for (int nt = 0; nt < 8; nt++) {
            int e = wn + nt * 8 + qc * 2;
            float S0 = sS[e], S1 = sS[e + 1];
            float C0 = sC[e], C1 = sC[e + 1];
            size_t ro0 = (size_t)(i * 768 + j0 + rj) * 128 + e;
            size_t ro1 = ro0 + 8 * 128;
            float2 gt0 = *(const float2*)&g_G[ro0];
            float2 gt1 = *(const float2*)&g_G[ro1];
            *(float2*)&out[ro0] = make_float2(gt0.x * (inv0 * acc[nt][0] + mb0 * S0 + C0),
                                              gt0.y * (inv0 * acc[nt][1] + mb0 * S1 + C1));
            *(float2*)&out[ro1] = make_float2(gt1.x * (inv1 * acc[nt][2] + mb1 * S0 + C0),
                                              gt1.y * (inv1 * acc[nt][3] + mb1 * S1 + C1));
        }
    }
}

// ---------------- launch ---------------------------------------------------------
extern "C" void kernel_launch(void* const* d_in, const int* in_sizes, int n_in,
                              void* d_out, int out_size) {
    const float* x    = (const float*)d_in[0];
    const float* mask = (const float*)d_in[1];
    const float* niw  = (const float*)d_in[2];
    const float* nib  = (const float*)d_in[3];
    const float* giw  = (const float*)d_in[4];
    const float* piw  = (const float*)d_in[5];
    const float* now  = (const float*)d_in[6];
    const float* nob  = (const float*)d_in[7];
    const float* gow  = (const float*)d_in[8];
    const float* pwo  = (const float*)d_in[9];
    float* out = (float*)d_out;

    size_t sm_proj  = (size_t)(6 * PCH + 384) * 4;     // 112128 B
    size_t sm_bgemm = (size_t)(3 * STG_F) * 4;         // 110592 B
    size_t sm_final = 27008 * 4;                       // 108032 B
    cudaFuncSetAttribute(proj_kernel,  cudaFuncAttributeMaxDynamicSharedMemorySize, (int)sm_proj);
    cudaFuncSetAttribute(bgemm_kernel, cudaFuncAttributeMaxDynamicSharedMemorySize, (int)sm_bgemm);
    cudaFuncSetAttribute(final_kernel, cudaFuncAttributeMaxDynamicSharedMemorySize, (int)sm_final);

    prep_w_kernel<<<64, 256>>>(giw, piw, gow, pwo, now, nob);
    proj_kernel<<<4608, 256, sm_proj>>>(x, mask, niw, nib);
    bgemm_kernel<<<dim3(6, 6, 128), 128, sm_bgemm>>>();
    final_kernel<<<dim3(6, 768), 256, sm_final>>>(out);
}

// round 14
// speedup vs baseline: 1.4506x; 1.0123x over previous
#include <cuda_runtime.h>
#include <cstdint>

#define NN (768*768)
#define ST 36            // smem row stride (floats) for 32-wide K chunks
#define PCH 4608         // floats per 128x36 chunk buffer

// ---------------- scratch -----------------------------------------------------
__device__ float g_A [(size_t)128 * NN];   // a transposed: [d][i*768+k]
__device__ float g_B [(size_t)128 * NN];   // b transposed: [d][j*768+k]
__device__ float g_T [(size_t)128 * NN];   // t transposed: [d][i*768+j]
__device__ float g_G [(size_t)NN * 128];   // sigmoid(xn @ g_out_w), [r][e]
__device__ float g_Wc[640 * 128];          // rows 0..511: interleaved (g,p); 512..639: g_out_w
__device__ float g_Pw[128 * 128];          // W' = now_w[d]*p_out_w[e,d], tf32
__device__ float g_S [128];                // S[e] = sum_d now_w[d]*p_out_w[e,d]
__device__ float g_C [128];                // C[e] = sum_d now_b[d]*p_out_w[e,d]

// ---------------- helpers ------------------------------------------------------
__device__ __forceinline__ float tf32r(float x) {
    unsigned u;
    asm("cvt.rna.tf32.f32 %0, %1;" : "=r"(u) : "f"(x));
    return __uint_as_float(u);
}

__device__ __forceinline__ void mma8(float c[4], const unsigned a[4], const unsigned b[2]) {
    asm volatile(
        "mma.sync.aligned.m16n8k8.row.col.f32.tf32.tf32.f32 "
        "{%0,%1,%2,%3},{%4,%5,%6,%7},{%8,%9},{%0,%1,%2,%3};"
        : "+f"(c[0]), "+f"(c[1]), "+f"(c[2]), "+f"(c[3])
        : "r"(a[0]), "r"(a[1]), "r"(a[2]), "r"(a[3]), "r"(b[0]), "r"(b[1]));
}

__device__ __forceinline__ void ldsm4(unsigned r[4], uint32_t a) {
    asm volatile("ldmatrix.sync.aligned.m8n8.x4.shared.b16 {%0,%1,%2,%3}, [%4];"
        : "=r"(r[0]), "=r"(r[1]), "=r"(r[2]), "=r"(r[3]) : "r"(a));
}

__device__ __forceinline__ void cpa(void* s, const void* g) {
    unsigned sa = (unsigned)__cvta_generic_to_shared(s);
    asm volatile("cp.async.cg.shared.global [%0], [%1], 16;" :: "r"(sa), "l"(g));
}
__device__ __forceinline__ void cp_commit() { asm volatile("cp.async.commit_group;"); }
template<int Nw> __device__ __forceinline__ void cp_wait() {
    asm volatile("cp.async.wait_group %0;" :: "n"(Nw));
}
__device__ __forceinline__ void pair_bar(int id) {
    asm volatile("bar.sync %0, 64;" :: "r"(id) : "memory");
}

// 64x64 warp tile, one K-chunk of 32 (bgemm). Fragments via ldmatrix.
__device__ __forceinline__ void gemm64(const float* sA, const float* sB,
                                       float acc[4][8][4],
                                       int wm, int wn, int lane) {
    uint32_t ab = (uint32_t)__cvta_generic_to_shared(sA);
    uint32_t bb = (uint32_t)__cvta_generic_to_shared(sB);
    int lr = lane & 7, grp = lane >> 3;
    uint32_t aoff = ab + (uint32_t)(((wm + lr + (grp & 1) * 8) * ST + (grp >> 1) * 4) * 4);
    uint32_t boff = bb + (uint32_t)(((wn + lr) * ST + grp * 4) * 4);
#pragma unroll
    for (int kp = 0; kp < 2; kp++) {           // k pairs {0,8}, {16,24}
        unsigned bf[8][4];
#pragma unroll
        for (int nt = 0; nt < 8; nt++)
            ldsm4(bf[nt], boff + (uint32_t)(nt * 8 * ST * 4 + kp * 64));
#pragma unroll
        for (int ks = 0; ks < 2; ks++) {
            unsigned af[4][4];
#pragma unroll
            for (int mt = 0; mt < 4; mt++)
                ldsm4(af[mt], aoff + (uint32_t)(mt * 16 * ST * 4 + (kp * 16 + ks * 8) * 4));
#pragma unroll
            for (int mt = 0; mt < 4; mt++)
#pragma unroll
                for (int nt = 0; nt < 8; nt++)
                    mma8(acc[mt][nt], af[mt], &bf[nt][ks * 2]);
        }
    }
}

// 64x32 warp tile, one K-chunk of 32 (proj). Same ldmatrix scheme, 4 nt.
__device__ __forceinline__ void gemm_c32(const float* sA, const float* sB,
                                         float acc[4][4][4],
                                         int wm, int wn, int lane) {
    uint32_t ab = (uint32_t)__cvta_generic_to_shared(sA);
    uint32_t bb = (uint32_t)__cvta_generic_to_shared(sB);
    int lr = lane & 7, grp = lane >> 3;
    uint32_t aoff = ab + (uint32_t)(((wm + lr + (grp & 1) * 8) * ST + (grp >> 1) * 4) * 4);
    uint32_t boff = bb + (uint32_t)(((wn + lr) * ST + grp * 4) * 4);
#pragma unroll
    for (int kp = 0; kp < 2; kp++) {
        unsigned bf[4][4];
#pragma unroll
        for (int nt = 0; nt < 4; nt++)
            ldsm4(bf[nt], boff + (uint32_t)(nt * 8 * ST * 4 + kp * 64));
#pragma unroll
        for (int ks = 0; ks < 2; ks++) {
            unsigned af[4][4];
#pragma unroll
            for (int mt = 0; mt < 4; mt++)
                ldsm4(af[mt], aoff + (uint32_t)(mt * 16 * ST * 4 + (kp * 16 + ks * 8) * 4));
#pragma unroll
            for (int mt = 0; mt < 4; mt++)
#pragma unroll
                for (int nt = 0; nt < 4; nt++)
                    mma8(acc[mt][nt], af[mt], &bf[nt][ks * 2]);
        }
    }
}

// ---------------- kernel 0: weight prep ----------------------------------------
__global__ void prep_w_kernel(const float* __restrict__ gin, const float* __restrict__ pin,
                              const float* __restrict__ gout, const float* __restrict__ pout,
                              const float* __restrict__ now, const float* __restrict__ nob) {
    int stride = gridDim.x * blockDim.x;
    int tid = threadIdx.x;
    for (int idx = blockIdx.x * blockDim.x + tid; idx < 256 * 128; idx += stride) {
        int e = idx >> 7, d = idx & 127;
        g_Wc[(2 * e) * 128 + d]     = tf32r(gin[idx]);
        g_Wc[(2 * e + 1) * 128 + d] = tf32r(pin[idx]);
    }
    for (int idx = blockIdx.x * blockDim.x + tid; idx < 128 * 128; idx += stride) {
        g_Wc[512 * 128 + idx] = tf32r(gout[idx]);
        g_Pw[idx]             = tf32r(pout[idx] * now[idx & 127]);   // W'
    }
    if (blockIdx.x == 0) {
        int e = tid >> 1, hh = tid & 1;
        float s = 0.0f, c = 0.0f;
        for (int d = hh * 64; d < hh * 64 + 64; d++) {
            float p = pout[e * 128 + d];
            s += now[d] * p;
            c += nob[d] * p;
        }
        s += __shfl_xor_sync(0xffffffffu, s, 1);
        c += __shfl_xor_sync(0xffffffffu, c, 1);
        if (hh == 0) { g_S[e] = s; g_C[e] = c; }
    }
}

// ---------------- kernel 1: fused LN(x) + all projections + gate + mask ----------
// Pair-local W refill: W rows wn..wn+31 are read ONLY by warps {w, w+4}; that pair
// refills its own rows -> per-chunk sync is a 2-warp named barrier, not CTA-wide.
__global__ void __launch_bounds__(256, 2) proj_kernel(const float* __restrict__ x,
                                                      const float* __restrict__ mask,
                                                      const float* __restrict__ niw,
                                                      const float* __restrict__ nib) {
    extern __shared__ float sm[];
    float* WB  = sm + 4 * PCH;         // 2 x PCH W double-buffer
    float* msk = sm + 6 * PCH;         // 128
    float* wv  = msk + 128;            // 128
    float* bv  = wv + 128;             // 128
    int rt = blockIdx.x;
    int i = rt / 6, k0 = (rt % 6) * 128;
    int tid = threadIdx.x;

    if (tid < 128) {
        msk[tid] = mask[i * 768 + k0 + tid];
        wv[tid]  = niw[tid];
        bv[tid]  = nib[tid];
    }

    const float* Xb = x + (size_t)(i * 768 + k0) * 128;

    int warp = tid >> 5, lane = tid & 31;
    int pid  = warp & 3;                       // pair id (warps pid and pid+4)
    int barid = 1 + pid;
    int tau  = ((warp >> 2) << 5) + lane;      // 0..63 within pair

    // pair-partitioned W chunk load: rows [32*pid, 32*pid+32)
    auto ldW_pair = [&](int buf, int w, int ch) {
#pragma unroll
        for (int t = 0; t < 4; t++) {
            int f4 = t * 64 + tau;             // 0..255
            int r  = (pid << 5) + (f4 >> 3);
            int c4 = (f4 & 7) * 4;
            cpa(WB + buf * PCH + r * ST + c4,
                g_Wc + (size_t)w * 16384 + (size_t)r * 128 + ch * 32 + c4);
        }
    };

    // A: all 4 chunks, one group
#pragma unroll
    for (int c = 0; c < 4; c++)
#pragma unroll
        for (int t = 0; t < 4; t++) {
            int idx = t * 256 + tid;
            int r = idx >> 3, cc = (idx & 7) * 4;
            cpa(sm + c * PCH + r * ST + cc, Xb + (size_t)r * 128 + c * 32 + cc);
        }
    cp_commit();
    ldW_pair(0, 0, 0); cp_commit();
    ldW_pair(1, 0, 1); cp_commit();

    cp_wait<2>();        // A complete
    __syncthreads();

    // In-smem LayerNorm: 4 threads per row, k = 4*kk + h (conflict-free).
    {
        int h = tid & 3, q = tid >> 2;
#pragma unroll
        for (int pass = 0; pass < 2; pass++) {
            int r = pass * 64 + q;
            float s = 0.0f, s2 = 0.0f;
#pragma unroll
            for (int kk = 0; kk < 32; kk++) {
                int kg = 4 * kk + h;
                float v = sm[(kg >> 5) * PCH + r * ST + (kg & 31)];
                s += v; s2 += v * v;
            }
            s  += __shfl_xor_sync(0xffffffffu, s,  1);
            s2 += __shfl_xor_sync(0xffffffffu, s2, 1);
            s  += __shfl_xor_sync(0xffffffffu, s,  2);
            s2 += __shfl_xor_sync(0xffffffffu, s2, 2);
            float m   = s * (1.0f / 128.0f);
            float var = s2 * (1.0f / 128.0f) - m * m;
            float inv = rsqrtf(var + 1e-5f);
#pragma unroll
            for (int kk = 0; kk < 32; kk++) {
                int kg = 4 * kk + h;
                float* p = sm + (kg >> 5) * PCH + r * ST + (kg & 31);
                *p = tf32r((*p - m) * inv * wv[kg] + bv[kg]);
            }
        }
    }
    __syncthreads();     // publish LN writes; A is read-only hereafter

    int wm = (warp >> 2) * 64, wn = (warp & 3) * 32;
    int qr = lane >> 2, qc = lane & 3;

#pragma unroll 1
    for (int w = 0; w < 5; w++) {
        float acc[4][4][4] = {};
#pragma unroll 1
        for (int c = 0; c < 4; c++) {
            cp_wait<1>();
            pair_bar(barid);            // pair's loads for this buffer visible
            gemm_c32(sm + c * PCH, WB + (c & 1) * PCH, acc, wm, wn, lane);
            pair_bar(barid);            // pair done reading before refill
            if (c < 2)       ldW_pair(c & 1, w, c + 2);     // this tile chunks 2,3
            else if (w < 4)  ldW_pair(c & 1, w + 1, c - 2); // next tile chunks 0,1
            cp_commit();
        }

        // epilogue: direct from accumulators (loads for w+1 in flight)
        if (w == 4) {
#pragma unroll
            for (int mt = 0; mt < 4; mt++)
#pragma unroll
                for (int nt = 0; nt < 4; nt++) {
                    int rm0 = wm + mt * 16 + qr, rm1 = rm0 + 8;
                    int cn = wn + nt * 8 + qc * 2;
                    size_t r0 = (size_t)(i * 768 + k0 + rm0) * 128 + cn;
                    size_t r1 = (size_t)(i * 768 + k0 + rm1) * 128 + cn;
                    *(float2*)&g_G[r0] = make_float2(1.0f / (1.0f + __expf(-acc[mt][nt][0])),
                                                     1.0f / (1.0f + __expf(-acc[mt][nt][1])));
                    *(float2*)&g_G[r1] = make_float2(1.0f / (1.0f + __expf(-acc[mt][nt][2])),
                                                     1.0f / (1.0f + __expf(-acc[mt][nt][3])));
                }
        } else {
            bool isA = (w < 2);
#pragma unroll
            for (int mt = 0; mt < 4; mt++)
#pragma unroll
                for (int nt = 0; nt < 4; nt++) {
                    int rm0 = wm + mt * 16 + qr, rm1 = rm0 + 8;
                    int chl = (wn >> 1) + nt * 4 + qc;
                    float v0 = acc[mt][nt][1] * (1.0f / (1.0f + __expf(-acc[mt][nt][0])));
                    float v1 = acc[mt][nt][3] * (1.0f / (1.0f + __expf(-acc[mt][nt][2])));
                    if (isA) { v0 *= msk[rm0]; v1 *= msk[rm1]; }
                    int ch = w * 64 + chl;
                    float* dst = (ch < 128) ? (g_A + (size_t)ch * NN)
                                            : (g_B + (size_t)(ch - 128) * NN);
                    dst[i * 768 + k0 + rm0] = tf32r(v0);
                    dst[i * 768 + k0 + rm1] = tf32r(v1);
                }
        }
    }
}

// ---------------- kernel 2: batched einsum  t_d = A_d @ B_d^T --------------------
#define STG_F 9216
__global__ void __launch_bounds__(128, 2) bgemm_kernel() {
    extern __shared__ float sm[];
    int jt = blockIdx.x, it = blockIdx.y, d = blockIdx.z;
    int tid = threadIdx.x;
    const float* Ab = g_A + (size_t)d * NN + (size_t)(it * 128) * 768;
    const float* Bb = g_B + (size_t)d * NN + (size_t)(jt * 128) * 768;

    auto ld = [&](int s, int kc) {
        float* S = sm + s * STG_F;
#pragma unroll
        for (int t = 0; t < 16; t++) {
            int idx = t * 128 + tid;
            int r = idx >> 3, c = (idx & 7) * 4;
            const float* g = (r < 128) ? Ab + (size_t)r * 768 + kc + c
                                       : Bb + (size_t)(r - 128) * 768 + kc + c;
            cpa(&S[r * ST + c], g);
        }
    };

    int wid = tid >> 5, lane = tid & 31;
    int wm = (wid >> 1) * 64, wn = (wid & 1) * 64;
    int qr = lane >> 2, qc = lane & 3;
    float acc[4][8][4] = {};

    ld(0, 0);  cp_commit();
    ld(1, 32); cp_commit();
#pragma unroll 1
    for (int c = 0; c < 24; c++) {
        cp_wait<1>();
        __syncthreads();
        int kn = (c + 2) * 32;
        if (kn < 768) ld((c + 2) % 3, kn);    // issue loads BEFORE compute
        cp_commit();
        float* S = sm + (c % 3) * STG_F;
        gemm64(S, S + 128 * ST, acc, wm, wn, lane);
    }

    float* outp = g_T + (size_t)d * NN;
#pragma unroll
    for (int mt = 0; mt < 4; mt++)
#pragma unroll
        for (int nt = 0; nt < 8; nt++) {
            int rm0 = it * 128 + wm + mt * 16 + qr;
            int cn  = jt * 128 + wn + nt * 8 + qc * 2;
            *(float2*)&outp[(size_t)rm0 * 768 + cn]       = make_float2(acc[mt][nt][0], acc[mt][nt][1]);
            *(float2*)&outp[(size_t)(rm0 + 8) * 768 + cn] = make_float2(acc[mt][nt][2], acc[mt][nt][3]);
        }
}

// ---------------- kernel 3: LN(t) folded into GEMM + gate ------------------------
// R12 shape: one block = 64 j x 128 e, grid (12, 768). t loaded once, stats once,
// W fragments via ldmatrix, K loop kp<8.
__global__ void __launch_bounds__(256, 2) final_kernel(float* __restrict__ out) {
    extern __shared__ float sm[];
    float* sT   = sm;               // 128 d x 72 (64 j used)
    float* sW   = sm + 9216;        // 128 e x 132
    float* sS   = sm + 26112;       // 128
    float* sC   = sm + 26240;       // 128
    float* smm  = sm + 26368;       // 64
    float* sinv = sm + 26432;       // 64
    float* sred = sm + 26496;       // 512
    int jt = blockIdx.x;
    int i  = blockIdx.y;
    int j0 = jt * 64;
    int tid = threadIdx.x;

    const float* Tg = g_T + (size_t)i * 768 + j0;
#pragma unroll
    for (int t = 0; t < 8; t++) {
        int idx = t * 256 + tid;
        int dd = idx >> 4, c4 = (idx & 15) * 4;
        cpa(&sT[dd * 72 + c4], &Tg[(size_t)dd * NN + c4]);
    }
#pragma unroll
    for (int t = 0; t < 16; t++) {
        int idx = t * 256 + tid;
        int r = idx >> 5, c4 = (idx & 31) * 4;
        cpa(&sW[r * 132 + c4], &g_Pw[(size_t)r * 128 + c4]);
    }
    if (tid < 128) { sS[tid] = g_S[tid]; sC[tid] = g_C[tid]; }
    cp_commit();
    cp_wait<0>();
    __syncthreads();

    // stats pass (read-only; t fed raw to HMMA)
    {
        int h2 = tid >> 6, j = tid & 63;
        float s = 0.0f, s2 = 0.0f;
#pragma unroll 8
        for (int kk = 0; kk < 32; kk++) {
            int dd = h2 * 32 + kk;
            float v = sT[dd * 72 + j];
            s += v; s2 += v * v;
        }
        sred[h2 * 64 + j] = s;
        sred[256 + h2 * 64 + j] = s2;
    }
    __syncthreads();
    if (tid < 64) {
        float s  = sred[tid] + sred[64 + tid] + sred[128 + tid] + sred[192 + tid];
        float s2 = sred[256 + tid] + sred[320 + tid] + sred[384 + tid] + sred[448 + tid];
        float m   = s * (1.0f / 128.0f);
        float var = s2 * (1.0f / 128.0f) - m * m;
        smm[tid]  = m;
        sinv[tid] = rsqrtf(var + 1e-5f);
    }
    __syncthreads();

    int warp = tid >> 5, lane = tid & 31;
    int wm = (warp & 3) * 16, wn = (warp >> 2) * 64;
    int qr = lane >> 2, qc = lane & 3;
    int lr = lane & 7, grp = lane >> 3;
    float acc[8][4] = {};

    uint32_t bb = (uint32_t)__cvta_generic_to_shared(sW);
    uint32_t boff = bb + (uint32_t)(((wn + lr) * 132 + grp * 4) * 4);

#pragma unroll
    for (int kp = 0; kp < 8; kp++) {          // each kp covers k = kp*16 .. kp*16+15
        unsigned bf[8][4];
#pragma unroll
        for (int nt = 0; nt < 8; nt++)
            ldsm4(bf[nt], boff + (uint32_t)(nt * 8 * 132 * 4 + kp * 64));
#pragma unroll
        for (int ks = 0; ks < 2; ks++) {
            int k = kp * 16 + ks * 8;
            unsigned af[4];
            {
                int r = wm + qr;
                const float* p0 = sT + (k + qc) * 72 + r;
                const float* p1 = sT + (k + qc + 4) * 72 + r;
                af[0] = __float_as_uint(p0[0]);
                af[1] = __float_as_uint(p0[8]);
                af[2] = __float_as_uint(p1[0]);
                af[3] = __float_as_uint(p1[8]);
            }
#pragma unroll
            for (int nt = 0; nt < 8; nt++)
                mma8(acc[nt], af, &bf[nt][ks * 2]);
        }
    }

    int rj = wm + qr;
    float inv0 = sinv[rj],     mb0 = -inv0 * smm[rj];
    float inv1 = sinv[rj + 8], mb1 = -inv1 * smm[rj + 8];
#pragma unroll
    for (int nt = 0; nt < 8; nt++) {
        int e = wn + nt * 8 + qc * 2;
        float S0 = sS[e], S1 = sS[e + 1];
        float C0 = sC[e], C1 = sC[e + 1];
        size_t ro0 = (size_t)(i * 768 + j0 + rj) * 128 + e;
        size_t ro1 = ro0 + 8 * 128;
        float2 gt0 = *(const float2*)&g_G[ro0];
        float2 gt1 = *(const float2*)&g_G[ro1];
        *(float2*)&out[ro0] = make_float2(gt0.x * (inv0 * acc[nt][0] + mb0 * S0 + C0),
                                          gt0.y * (inv0 * acc[nt][1] + mb0 * S1 + C1));
        *(float2*)&out[ro1] = make_float2(gt1.x * (inv1 * acc[nt][2] + mb1 * S0 + C0),
                                          gt1.y * (inv1 * acc[nt][3] + mb1 * S1 + C1));
    }
}

// ---------------- launch ---------------------------------------------------------
extern "C" void kernel_launch(void* const* d_in, const int* in_sizes, int n_in,
                              void* d_out, int out_size) {
    const float* x    = (const float*)d_in[0];
    const float* mask = (const float*)d_in[1];
    const float* niw  = (const float*)d_in[2];
    const float* nib  = (const float*)d_in[3];
    const float* giw  = (const float*)d_in[4];
    const float* piw  = (const float*)d_in[5];
    const float* now  = (const float*)d_in[6];
    const float* nob  = (const float*)d_in[7];
    const float* gow  = (const float*)d_in[8];
    const float* pwo  = (const float*)d_in[9];
    float* out = (float*)d_out;

    size_t sm_proj  = (size_t)(6 * PCH + 384) * 4;     // 112128 B
    size_t sm_bgemm = (size_t)(3 * STG_F) * 4;         // 110592 B
    size_t sm_final = 27008 * 4;                       // 108032 B
    cudaFuncSetAttribute(proj_kernel,  cudaFuncAttributeMaxDynamicSharedMemorySize, (int)sm_proj);
    cudaFuncSetAttribute(bgemm_kernel, cudaFuncAttributeMaxDynamicSharedMemorySize, (int)sm_bgemm);
    cudaFuncSetAttribute(final_kernel, cudaFuncAttributeMaxDynamicSharedMemorySize, (int)sm_final);

    prep_w_kernel<<<64, 256>>>(giw, piw, gow, pwo, now, nob);
    proj_kernel<<<4608, 256, sm_proj>>>(x, mask, niw, nib);
    bgemm_kernel<<<dim3(6, 6, 128), 128, sm_bgemm>>>();
    final_kernel<<<dim3(12, 768), 256, sm_final>>>(out);
}

// round 15
// speedup vs baseline: 1.7668x; 1.2180x over previous
#include <cuda_runtime.h>
#include <cuda_fp16.h>
#include <cstdint>

#define NN (768*768)
#define ST 36            // smem row stride (fp32 words) for 32-wide K chunks (proj)
#define PCH 4608         // floats per 128x36 chunk buffer (proj)
#define STH 40           // smem row stride (halves) for bgemm fp16 chunks (80 B)
#define STG_H 10240      // halves per bgemm stage: 256 rows * 40

// ---------------- scratch -----------------------------------------------------
__device__ __half g_A [(size_t)128 * NN];  // a transposed: [d][i*768+k], fp16
__device__ __half g_B [(size_t)128 * NN];  // b transposed: [d][j*768+k], fp16
__device__ float  g_T [(size_t)128 * NN];  // t transposed: [d][i*768+j], fp32
__device__ __half g_G [(size_t)NN * 128];  // sigmoid(xn @ g_out_w), [r][e], fp16
__device__ float  g_Wc[640 * 128];         // rows 0..511: interleaved (g,p); 512..639: g_out_w
__device__ float  g_Pw[128 * 128];         // W' = now_w[d]*p_out_w[e,d], tf32
__device__ float  g_S [128];
__device__ float  g_C [128];

// ---------------- helpers ------------------------------------------------------
__device__ __forceinline__ float tf32r(float x) {
    unsigned u;
    asm("cvt.rna.tf32.f32 %0, %1;" : "=r"(u) : "f"(x));
    return __uint_as_float(u);
}

__device__ __forceinline__ void mma8(float c[4], const unsigned a[4], const unsigned b[2]) {
    asm volatile(
        "mma.sync.aligned.m16n8k8.row.col.f32.tf32.tf32.f32 "
        "{%0,%1,%2,%3},{%4,%5,%6,%7},{%8,%9},{%0,%1,%2,%3};"
        : "+f"(c[0]), "+f"(c[1]), "+f"(c[2]), "+f"(c[3])
        : "r"(a[0]), "r"(a[1]), "r"(a[2]), "r"(a[3]), "r"(b[0]), "r"(b[1]));
}

__device__ __forceinline__ void mma16h(float c[4], const unsigned a[4], const unsigned b[2]) {
    asm volatile(
        "mma.sync.aligned.m16n8k16.row.col.f32.f16.f16.f32 "
        "{%0,%1,%2,%3},{%4,%5,%6,%7},{%8,%9},{%0,%1,%2,%3};"
        : "+f"(c[0]), "+f"(c[1]), "+f"(c[2]), "+f"(c[3])
        : "r"(a[0]), "r"(a[1]), "r"(a[2]), "r"(a[3]), "r"(b[0]), "r"(b[1]));
}

__device__ __forceinline__ void ldsm4(unsigned r[4], uint32_t a) {
    asm volatile("ldmatrix.sync.aligned.m8n8.x4.shared.b16 {%0,%1,%2,%3}, [%4];"
        : "=r"(r[0]), "=r"(r[1]), "=r"(r[2]), "=r"(r[3]) : "r"(a));
}

__device__ __forceinline__ void cpa(void* s, const void* g) {
    unsigned sa = (unsigned)__cvta_generic_to_shared(s);
    asm volatile("cp.async.cg.shared.global [%0], [%1], 16;" :: "r"(sa), "l"(g));
}
__device__ __forceinline__ void cp_commit() { asm volatile("cp.async.commit_group;"); }
template<int Nw> __device__ __forceinline__ void cp_wait() {
    asm volatile("cp.async.wait_group %0;" :: "n"(Nw));
}
__device__ __forceinline__ void pair_bar(int id) {
    asm volatile("bar.sync %0, 64;" :: "r"(id) : "memory");
}

// fp16 64x64 warp tile, one K-chunk of 32 (bgemm). m16n8k16, fragments via ldmatrix.
__device__ __forceinline__ void gemm64h(const __half* sA, const __half* sB,
                                        float acc[4][8][4],
                                        int wm, int wn, int lane) {
    uint32_t ab = (uint32_t)__cvta_generic_to_shared(sA);
    uint32_t bb = (uint32_t)__cvta_generic_to_shared(sB);
    int lr = lane & 7, grp = lane >> 3;
    // A: m0 rows wm..+7 k0-7 | m1 rows +8 k0-7 | m2 rows wm.. k8-15 | m3 rows +8 k8-15
    uint32_t aoff = ab + (uint32_t)(((wm + lr + (grp & 1) * 8) * STH) * 2 + (grp >> 1) * 16);
    // B: m0 rows wn..+7 k0-7 | m1 same rows k8-15 | m2 rows +8 k0-7 | m3 rows +8 k8-15
    uint32_t boff = bb + (uint32_t)(((wn + lr + (grp >> 1) * 8) * STH) * 2 + (grp & 1) * 16);
#pragma unroll
    for (int ks = 0; ks < 2; ks++) {           // k steps of 16
        unsigned bf[4][4];                     // bf[np]: nt=2np regs 0,1 ; nt=2np+1 regs 2,3
#pragma unroll
        for (int np = 0; np < 4; np++)
            ldsm4(bf[np], boff + (uint32_t)(np * 16 * STH * 2 + ks * 32));
        unsigned af[4][4];
#pragma unroll
        for (int mt = 0; mt < 4; mt++)
            ldsm4(af[mt], aoff + (uint32_t)(mt * 16 * STH * 2 + ks * 32));
#pragma unroll
        for (int mt = 0; mt < 4; mt++)
#pragma unroll
            for (int nt = 0; nt < 8; nt++)
                mma16h(acc[mt][nt], af[mt], &bf[nt >> 1][(nt & 1) * 2]);
    }
}

// tf32 64x32 warp tile, one K-chunk of 32 (proj). ldmatrix scheme.
__device__ __forceinline__ void gemm_c32(const float* sA, const float* sB,
                                         float acc[4][4][4],
                                         int wm, int wn, int lane) {
    uint32_t ab = (uint32_t)__cvta_generic_to_shared(sA);
    uint32_t bb = (uint32_t)__cvta_generic_to_shared(sB);
    int lr = lane & 7, grp = lane >> 3;
    uint32_t aoff = ab + (uint32_t)(((wm + lr + (grp & 1) * 8) * ST + (grp >> 1) * 4) * 4);
    uint32_t boff = bb + (uint32_t)(((wn + lr) * ST + grp * 4) * 4);
#pragma unroll
    for (int kp = 0; kp < 2; kp++) {
        unsigned bf[4][4];
#pragma unroll
        for (int nt = 0; nt < 4; nt++)
            ldsm4(bf[nt], boff + (uint32_t)(nt * 8 * ST * 4 + kp * 64));
#pragma unroll
        for (int ks = 0; ks < 2; ks++) {
            unsigned af[4][4];
#pragma unroll
            for (int mt = 0; mt < 4; mt++)
                ldsm4(af[mt], aoff + (uint32_t)(mt * 16 * ST * 4 + (kp * 16 + ks * 8) * 4));
#pragma unroll
            for (int mt = 0; mt < 4; mt++)
#pragma unroll
                for (int nt = 0; nt < 4; nt++)
                    mma8(acc[mt][nt], af[mt], &bf[nt][ks * 2]);
        }
    }
}

// ---------------- kernel 0: weight prep ----------------------------------------
__global__ void prep_w_kernel(const float* __restrict__ gin, const float* __restrict__ pin,
                              const float* __restrict__ gout, const float* __restrict__ pout,
                              const float* __restrict__ now, const float* __restrict__ nob) {
    int stride = gridDim.x * blockDim.x;
    int tid = threadIdx.x;
    for (int idx = blockIdx.x * blockDim.x + tid; idx < 256 * 128; idx += stride) {
        int e = idx >> 7, d = idx & 127;
        g_Wc[(2 * e) * 128 + d]     = tf32r(gin[idx]);
        g_Wc[(2 * e + 1) * 128 + d] = tf32r(pin[idx]);
    }
    for (int idx = blockIdx.x * blockDim.x + tid; idx < 128 * 128; idx += stride) {
        g_Wc[512 * 128 + idx] = tf32r(gout[idx]);
        g_Pw[idx]             = tf32r(pout[idx] * now[idx & 127]);   // W'
    }
    if (blockIdx.x == 0) {
        int e = tid >> 1, hh = tid & 1;
        float s = 0.0f, c = 0.0f;
        for (int d = hh * 64; d < hh * 64 + 64; d++) {
            float p = pout[e * 128 + d];
            s += now[d] * p;
            c += nob[d] * p;
        }
        s += __shfl_xor_sync(0xffffffffu, s, 1);
        c += __shfl_xor_sync(0xffffffffu, c, 1);
        if (hh == 0) { g_S[e] = s; g_C[e] = c; }
    }
}

// ---------------- kernel 1: fused LN(x) + all projections + gate + mask ----------
__global__ void __launch_bounds__(256, 2) proj_kernel(const float* __restrict__ x,
                                                      const float* __restrict__ mask,
                                                      const float* __restrict__ niw,
                                                      const float* __restrict__ nib) {
    extern __shared__ float sm[];
    float* WB  = sm + 4 * PCH;
    float* msk = sm + 6 * PCH;
    float* wv  = msk + 128;
    float* bv  = wv + 128;
    int rt = blockIdx.x;
    int i = rt / 6, k0 = (rt % 6) * 128;
    int tid = threadIdx.x;

    if (tid < 128) {
        msk[tid] = mask[i * 768 + k0 + tid];
        wv[tid]  = niw[tid];
        bv[tid]  = nib[tid];
    }

    const float* Xb = x + (size_t)(i * 768 + k0) * 128;

    int warp = tid >> 5, lane = tid & 31;
    int pid  = warp & 3;
    int barid = 1 + pid;
    int tau  = ((warp >> 2) << 5) + lane;

    auto ldW_pair = [&](int buf, int w, int ch) {
#pragma unroll
        for (int t = 0; t < 4; t++) {
            int f4 = t * 64 + tau;
            int r  = (pid << 5) + (f4 >> 3);
            int c4 = (f4 & 7) * 4;
            cpa(WB + buf * PCH + r * ST + c4,
                g_Wc + (size_t)w * 16384 + (size_t)r * 128 + ch * 32 + c4);
        }
    };

#pragma unroll
    for (int c = 0; c < 4; c++)
#pragma unroll
        for (int t = 0; t < 4; t++) {
            int idx = t * 256 + tid;
            int r = idx >> 3, cc = (idx & 7) * 4;
            cpa(sm + c * PCH + r * ST + cc, Xb + (size_t)r * 128 + c * 32 + cc);
        }
    cp_commit();
    ldW_pair(0, 0, 0); cp_commit();
    ldW_pair(1, 0, 1); cp_commit();

    cp_wait<2>();
    __syncthreads();

    // In-smem LayerNorm
    {
        int h = tid & 3, q = tid >> 2;
#pragma unroll
        for (int pass = 0; pass < 2; pass++) {
            int r = pass * 64 + q;
            float s = 0.0f, s2 = 0.0f;
#pragma unroll
            for (int kk = 0; kk < 32; kk++) {
                int kg = 4 * kk + h;
                float v = sm[(kg >> 5) * PCH + r * ST + (kg & 31)];
                s += v; s2 += v * v;
            }
            s  += __shfl_xor_sync(0xffffffffu, s,  1);
            s2 += __shfl_xor_sync(0xffffffffu, s2, 1);
            s  += __shfl_xor_sync(0xffffffffu, s,  2);
            s2 += __shfl_xor_sync(0xffffffffu, s2, 2);
            float m   = s * (1.0f / 128.0f);
            float var = s2 * (1.0f / 128.0f) - m * m;
            float inv = rsqrtf(var + 1e-5f);
#pragma unroll
            for (int kk = 0; kk < 32; kk++) {
                int kg = 4 * kk + h;
                float* p = sm + (kg >> 5) * PCH + r * ST + (kg & 31);
                *p = tf32r((*p - m) * inv * wv[kg] + bv[kg]);
            }
        }
    }
    __syncthreads();

    int wm = (warp >> 2) * 64, wn = (warp & 3) * 32;
    int qr = lane >> 2, qc = lane & 3;

#pragma unroll 1
    for (int w = 0; w < 5; w++) {
        float acc[4][4][4] = {};
#pragma unroll 1
        for (int c = 0; c < 4; c++) {
            cp_wait<1>();
            pair_bar(barid);
            gemm_c32(sm + c * PCH, WB + (c & 1) * PCH, acc, wm, wn, lane);
            pair_bar(barid);
            if (c < 2)       ldW_pair(c & 1, w, c + 2);
            else if (w < 4)  ldW_pair(c & 1, w + 1, c - 2);
            cp_commit();
        }

        if (w == 4) {
#pragma unroll
            for (int mt = 0; mt < 4; mt++)
#pragma unroll
                for (int nt = 0; nt < 4; nt++) {
                    int rm0 = wm + mt * 16 + qr, rm1 = rm0 + 8;
                    int cn = wn + nt * 8 + qc * 2;
                    size_t r0 = (size_t)(i * 768 + k0 + rm0) * 128 + cn;
                    size_t r1 = (size_t)(i * 768 + k0 + rm1) * 128 + cn;
                    *(__half2*)&g_G[r0] = __floats2half2_rn(
                        1.0f / (1.0f + __expf(-acc[mt][nt][0])),
                        1.0f / (1.0f + __expf(-acc[mt][nt][1])));
                    *(__half2*)&g_G[r1] = __floats2half2_rn(
                        1.0f / (1.0f + __expf(-acc[mt][nt][2])),
                        1.0f / (1.0f + __expf(-acc[mt][nt][3])));
                }
        } else {
            bool isA = (w < 2);
#pragma unroll
            for (int mt = 0; mt < 4; mt++)
#pragma unroll
                for (int nt = 0; nt < 4; nt++) {
                    int rm0 = wm + mt * 16 + qr, rm1 = rm0 + 8;
                    int chl = (wn >> 1) + nt * 4 + qc;
                    float v0 = acc[mt][nt][1] * (1.0f / (1.0f + __expf(-acc[mt][nt][0])));
                    float v1 = acc[mt][nt][3] * (1.0f / (1.0f + __expf(-acc[mt][nt][2])));
                    if (isA) { v0 *= msk[rm0]; v1 *= msk[rm1]; }
                    int ch = w * 64 + chl;
                    __half* dst = (ch < 128) ? (g_A + (size_t)ch * NN)
                                             : (g_B + (size_t)(ch - 128) * NN);
                    dst[i * 768 + k0 + rm0] = __float2half_rn(v0);
                    dst[i * 768 + k0 + rm1] = __float2half_rn(v1);
                }
        }
    }
}

// ---------------- kernel 2: batched einsum  t_d = A_d @ B_d^T (fp16 HMMA) --------
__global__ void __launch_bounds__(128, 2) bgemm_kernel() {
    extern __shared__ __half smh[];
    int jt = blockIdx.x, it = blockIdx.y, d = blockIdx.z;
    int tid = threadIdx.x;
    const __half* Ab = g_A + (size_t)d * NN + (size_t)(it * 128) * 768;
    const __half* Bb = g_B + (size_t)d * NN + (size_t)(jt * 128) * 768;

    auto ld = [&](int s, int kc) {
        __half* S = smh + s * STG_H;
#pragma unroll
        for (int t = 0; t < 8; t++) {
            int idx = t * 128 + tid;
            int r = idx >> 2, c = (idx & 3) * 8;     // 16B = 8 halves
            const __half* g = (r < 128) ? Ab + (size_t)r * 768 + kc + c
                                        : Bb + (size_t)(r - 128) * 768 + kc + c;
            cpa(S + r * STH + c, g);
        }
    };

    int wid = tid >> 5, lane = tid & 31;
    int wm = (wid >> 1) * 64, wn = (wid & 1) * 64;
    int qr = lane >> 2, qc = lane & 3;
    float acc[4][8][4] = {};

    ld(0, 0);  cp_commit();
    ld(1, 32); cp_commit();
#pragma unroll 1
    for (int c = 0; c < 24; c++) {
        cp_wait<1>();
        __syncthreads();
        int kn = (c + 2) * 32;
        if (kn < 768) ld((c + 2) % 3, kn);
        cp_commit();
        __half* S = smh + (c % 3) * STG_H;
        gemm64h(S, S + 128 * STH, acc, wm, wn, lane);
    }

    float* outp = g_T + (size_t)d * NN;
#pragma unroll
    for (int mt = 0; mt < 4; mt++)
#pragma unroll
        for (int nt = 0; nt < 8; nt++) {
            int rm0 = it * 128 + wm + mt * 16 + qr;
            int cn  = jt * 128 + wn + nt * 8 + qc * 2;
            *(float2*)&outp[(size_t)rm0 * 768 + cn]       = make_float2(acc[mt][nt][0], acc[mt][nt][1]);
            *(float2*)&outp[(size_t)(rm0 + 8) * 768 + cn] = make_float2(acc[mt][nt][2], acc[mt][nt][3]);
        }
}

// ---------------- kernel 3: LN(t) folded into GEMM + gate ------------------------
__global__ void __launch_bounds__(256, 2) final_kernel(float* __restrict__ out) {
    extern __shared__ float sm[];
    float* sT   = sm;               // 128 d x 72 (64 j used)
    float* sW   = sm + 9216;        // 128 e x 132
    float* sS   = sm + 26112;       // 128
    float* sC   = sm + 26240;       // 128
    float* smm  = sm + 26368;       // 64
    float* sinv = sm + 26432;       // 64
    float* sred = sm + 26496;       // 512
    int jt = blockIdx.x;
    int i  = blockIdx.y;
    int j0 = jt * 64;
    int tid = threadIdx.x;

    const float* Tg = g_T + (size_t)i * 768 + j0;
#pragma unroll
    for (int t = 0; t < 8; t++) {
        int idx = t * 256 + tid;
        int dd = idx >> 4, c4 = (idx & 15) * 4;
        cpa(&sT[dd * 72 + c4], &Tg[(size_t)dd * NN + c4]);
    }
#pragma unroll
    for (int t = 0; t < 16; t++) {
        int idx = t * 256 + tid;
        int r = idx >> 5, c4 = (idx & 31) * 4;
        cpa(&sW[r * 132 + c4], &g_Pw[(size_t)r * 128 + c4]);
    }
    if (tid < 128) { sS[tid] = g_S[tid]; sC[tid] = g_C[tid]; }
    cp_commit();
    cp_wait<0>();
    __syncthreads();

    // stats pass (read-only; t fed raw to HMMA)
    {
        int h2 = tid >> 6, j = tid & 63;
        float s = 0.0f, s2 = 0.0f;
#pragma unroll 8
        for (int kk = 0; kk < 32; kk++) {
            int dd = h2 * 32 + kk;
            float v = sT[dd * 72 + j];
            s += v; s2 += v * v;
        }
        sred[h2 * 64 + j] = s;
        sred[256 + h2 * 64 + j] = s2;
    }
    __syncthreads();
    if (tid < 64) {
        float s  = sred[tid] + sred[64 + tid] + sred[128 + tid] + sred[192 + tid];
        float s2 = sred[256 + tid] + sred[320 + tid] + sred[384 + tid] + sred[448 + tid];
        float m   = s * (1.0f / 128.0f);
        float var = s2 * (1.0f / 128.0f) - m * m;
        smm[tid]  = m;
        sinv[tid] = rsqrtf(var + 1e-5f);
    }
    __syncthreads();

    int warp = tid >> 5, lane = tid & 31;
    int wm = (warp & 3) * 16, wn = (warp >> 2) * 64;
    int qr = lane >> 2, qc = lane & 3;
    int lr = lane & 7, grp = lane >> 3;
    float acc[8][4] = {};

    uint32_t bb = (uint32_t)__cvta_generic_to_shared(sW);
    uint32_t boff = bb + (uint32_t)(((wn + lr) * 132 + grp * 4) * 4);

#pragma unroll
    for (int kp = 0; kp < 8; kp++) {
        unsigned bf[8][4];
#pragma unroll
        for (int nt = 0; nt < 8; nt++)
            ldsm4(bf[nt], boff + (uint32_t)(nt * 8 * 132 * 4 + kp * 64));
#pragma unroll
        for (int ks = 0; ks < 2; ks++) {
            int k = kp * 16 + ks * 8;
            unsigned af[4];
            {
                int r = wm + qr;
                const float* p0 = sT + (k + qc) * 72 + r;
                const float* p1 = sT + (k + qc + 4) * 72 + r;
                af[0] = __float_as_uint(p0[0]);
                af[1] = __float_as_uint(p0[8]);
                af[2] = __float_as_uint(p1[0]);
                af[3] = __float_as_uint(p1[8]);
            }
#pragma unroll
            for (int nt = 0; nt < 8; nt++)
                mma8(acc[nt], af, &bf[nt][ks * 2]);
        }
    }

    int rj = wm + qr;
    float inv0 = sinv[rj],     mb0 = -inv0 * smm[rj];
    float inv1 = sinv[rj + 8], mb1 = -inv1 * smm[rj + 8];
#pragma unroll
    for (int nt = 0; nt < 8; nt++) {
        int e = wn + nt * 8 + qc * 2;
        float S0 = sS[e], S1 = sS[e + 1];
        float C0 = sC[e], C1 = sC[e + 1];
        size_t ro0 = (size_t)(i * 768 + j0 + rj) * 128 + e;
        size_t ro1 = ro0 + 8 * 128;
        float2 gt0 = __half22float2(*(const __half2*)&g_G[ro0]);
        float2 gt1 = __half22float2(*(const __half2*)&g_G[ro1]);
        *(float2*)&out[ro0] = make_float2(gt0.x * (inv0 * acc[nt][0] + mb0 * S0 + C0),
                                          gt0.y * (inv0 * acc[nt][1] + mb0 * S1 + C1));
        *(float2*)&out[ro1] = make_float2(gt1.x * (inv1 * acc[nt][2] + mb1 * S0 + C0),
                                          gt1.y * (inv1 * acc[nt][3] + mb1 * S1 + C1));
    }
}

// ---------------- launch ---------------------------------------------------------
extern "C" void kernel_launch(void* const* d_in, const int* in_sizes, int n_in,
                              void* d_out, int out_size) {
    const float* x    = (const float*)d_in[0];
    const float* mask = (const float*)d_in[1];
    const float* niw  = (const float*)d_in[2];
    const float* nib  = (const float*)d_in[3];
    const float* giw  = (const float*)d_in[4];
    const float* piw  = (const float*)d_in[5];
    const float* now  = (const float*)d_in[6];
    const float* nob  = (const float*)d_in[7];
    const float* gow  = (const float*)d_in[8];
    const float* pwo  = (const float*)d_in[9];
    float* out = (float*)d_out;

    size_t sm_proj  = (size_t)(6 * PCH + 384) * 4;     // 112128 B
    size_t sm_bgemm = (size_t)(3 * STG_H) * 2;         // 61440 B
    size_t sm_final = 27008 * 4;                       // 108032 B
    cudaFuncSetAttribute(proj_kernel,  cudaFuncAttributeMaxDynamicSharedMemorySize, (int)sm_proj);
    cudaFuncSetAttribute(bgemm_kernel, cudaFuncAttributeMaxDynamicSharedMemorySize, (int)sm_bgemm);
    cudaFuncSetAttribute(final_kernel, cudaFuncAttributeMaxDynamicSharedMemorySize, (int)sm_final);

    prep_w_kernel<<<64, 256>>>(giw, piw, gow, pwo, now, nob);
    proj_kernel<<<4608, 256, sm_proj>>>(x, mask, niw, nib);
    bgemm_kernel<<<dim3(6, 6, 128), 128, sm_bgemm>>>();
    final_kernel<<<dim3(12, 768), 256, sm_final>>>(out);
}

// round 16
// speedup vs baseline: 2.0514x; 1.1610x over previous
#include <cuda_runtime.h>
#include <cuda_fp16.h>
#include <cstdint>

#define NN (768*768)
#define STH 40           // bgemm smem row stride (halves) = 80 B
#define STG_H 10240      // halves per bgemm stage: 256 rows * 40
#define STHA 136         // proj A smem row stride (halves) = 272 B
#define WBH 5120         // halves per proj W chunk buffer: 128 rows * 40

// ---------------- scratch -----------------------------------------------------
__device__ __half g_A [(size_t)128 * NN];  // a transposed: [d][i*768+k], fp16
__device__ __half g_B [(size_t)128 * NN];  // b transposed: [d][j*768+k], fp16
__device__ float  g_T [(size_t)128 * NN];  // t transposed: [d][i*768+j], fp32
__device__ __half g_G [(size_t)NN * 128];  // sigmoid(xn @ g_out_w), [r][e], fp16
__device__ __half g_Wc[640 * 128];         // fp16: rows 0..511 interleaved (g,p); 512..639 g_out_w
__device__ float  g_Pw[128 * 128];         // W' = now_w[d]*p_out_w[e,d], tf32
__device__ float  g_S [128];
__device__ float  g_C [128];

// ---------------- helpers ------------------------------------------------------
__device__ __forceinline__ float tf32r(float x) {
    unsigned u;
    asm("cvt.rna.tf32.f32 %0, %1;" : "=r"(u) : "f"(x));
    return __uint_as_float(u);
}

__device__ __forceinline__ void mma8(float c[4], const unsigned a[4], const unsigned b[2]) {
    asm volatile(
        "mma.sync.aligned.m16n8k8.row.col.f32.tf32.tf32.f32 "
        "{%0,%1,%2,%3},{%4,%5,%6,%7},{%8,%9},{%0,%1,%2,%3};"
        : "+f"(c[0]), "+f"(c[1]), "+f"(c[2]), "+f"(c[3])
        : "r"(a[0]), "r"(a[1]), "r"(a[2]), "r"(a[3]), "r"(b[0]), "r"(b[1]));
}

__device__ __forceinline__ void mma16h(float c[4], const unsigned a[4], const unsigned b[2]) {
    asm volatile(
        "mma.sync.aligned.m16n8k16.row.col.f32.f16.f16.f32 "
        "{%0,%1,%2,%3},{%4,%5,%6,%7},{%8,%9},{%0,%1,%2,%3};"
        : "+f"(c[0]), "+f"(c[1]), "+f"(c[2]), "+f"(c[3])
        : "r"(a[0]), "r"(a[1]), "r"(a[2]), "r"(a[3]), "r"(b[0]), "r"(b[1]));
}

__device__ __forceinline__ void ldsm4(unsigned r[4], uint32_t a) {
    asm volatile("ldmatrix.sync.aligned.m8n8.x4.shared.b16 {%0,%1,%2,%3}, [%4];"
        : "=r"(r[0]), "=r"(r[1]), "=r"(r[2]), "=r"(r[3]) : "r"(a));
}

__device__ __forceinline__ void cpa(void* s, const void* g) {
    unsigned sa = (unsigned)__cvta_generic_to_shared(s);
    asm volatile("cp.async.cg.shared.global [%0], [%1], 16;" :: "r"(sa), "l"(g));
}
__device__ __forceinline__ void cp_commit() { asm volatile("cp.async.commit_group;"); }
template<int Nw> __device__ __forceinline__ void cp_wait() {
    asm volatile("cp.async.wait_group %0;" :: "n"(Nw));
}
__device__ __forceinline__ void pair_bar(int id) {
    asm volatile("bar.sync %0, 64;" :: "r"(id) : "memory");
}

// fp16 64x64 warp tile, one K-chunk of 32 (bgemm). m16n8k16, fragments via ldmatrix.
__device__ __forceinline__ void gemm64h(const __half* sA, const __half* sB,
                                        float acc[4][8][4],
                                        int wm, int wn, int lane) {
    uint32_t ab = (uint32_t)__cvta_generic_to_shared(sA);
    uint32_t bb = (uint32_t)__cvta_generic_to_shared(sB);
    int lr = lane & 7, grp = lane >> 3;
    uint32_t aoff = ab + (uint32_t)(((wm + lr + (grp & 1) * 8) * STH) * 2 + (grp >> 1) * 16);
    uint32_t boff = bb + (uint32_t)(((wn + lr + (grp >> 1) * 8) * STH) * 2 + (grp & 1) * 16);
#pragma unroll
    for (int ks = 0; ks < 2; ks++) {
        unsigned bf[4][4];
#pragma unroll
        for (int np = 0; np < 4; np++)
            ldsm4(bf[np], boff + (uint32_t)(np * 16 * STH * 2 + ks * 32));
        unsigned af[4][4];
#pragma unroll
        for (int mt = 0; mt < 4; mt++)
            ldsm4(af[mt], aoff + (uint32_t)(mt * 16 * STH * 2 + ks * 32));
#pragma unroll
        for (int mt = 0; mt < 4; mt++)
#pragma unroll
            for (int nt = 0; nt < 8; nt++)
                mma16h(acc[mt][nt], af[mt], &bf[nt >> 1][(nt & 1) * 2]);
    }
}

// fp16 64x32 warp tile, one K-chunk of 32 (proj). A stride STHA, B stride STH.
__device__ __forceinline__ void gemm_c32h(const __half* sA, const __half* sB,
                                          float acc[4][4][4],
                                          int wm, int wn, int lane, int kbase) {
    uint32_t ab = (uint32_t)__cvta_generic_to_shared(sA);
    uint32_t bb = (uint32_t)__cvta_generic_to_shared(sB);
    int lr = lane & 7, grp = lane >> 3;
    uint32_t aoff = ab + (uint32_t)((wm + lr + (grp & 1) * 8) * STHA * 2 + (grp >> 1) * 16 + kbase * 2);
    uint32_t boff = bb + (uint32_t)((wn + lr + (grp >> 1) * 8) * STH * 2 + (grp & 1) * 16);
#pragma unroll
    for (int ks = 0; ks < 2; ks++) {
        unsigned bf[2][4];
#pragma unroll
        for (int np = 0; np < 2; np++)
            ldsm4(bf[np], boff + (uint32_t)(np * 16 * STH * 2 + ks * 32));
        unsigned af[4][4];
#pragma unroll
        for (int mt = 0; mt < 4; mt++)
            ldsm4(af[mt], aoff + (uint32_t)(mt * 16 * STHA * 2 + ks * 32));
#pragma unroll
        for (int mt = 0; mt < 4; mt++)
#pragma unroll
            for (int nt = 0; nt < 4; nt++)
                mma16h(acc[mt][nt], af[mt], &bf[nt >> 1][(nt & 1) * 2]);
    }
}

// ---------------- kernel 0: weight prep ----------------------------------------
__global__ void prep_w_kernel(const float* __restrict__ gin, const float* __restrict__ pin,
                              const float* __restrict__ gout, const float* __restrict__ pout,
                              const float* __restrict__ now, const float* __restrict__ nob) {
    int stride = gridDim.x * blockDim.x;
    int tid = threadIdx.x;
    for (int idx = blockIdx.x * blockDim.x + tid; idx < 256 * 128; idx += stride) {
        int e = idx >> 7, d = idx & 127;
        g_Wc[(2 * e) * 128 + d]     = __float2half_rn(gin[idx]);
        g_Wc[(2 * e + 1) * 128 + d] = __float2half_rn(pin[idx]);
    }
    for (int idx = blockIdx.x * blockDim.x + tid; idx < 128 * 128; idx += stride) {
        g_Wc[512 * 128 + idx] = __float2half_rn(gout[idx]);
        g_Pw[idx]             = tf32r(pout[idx] * now[idx & 127]);   // W'
    }
    if (blockIdx.x == 0) {
        int e = tid >> 1, hh = tid & 1;
        float s = 0.0f, c = 0.0f;
        for (int d = hh * 64; d < hh * 64 + 64; d++) {
            float p = pout[e * 128 + d];
            s += now[d] * p;
            c += nob[d] * p;
        }
        s += __shfl_xor_sync(0xffffffffu, s, 1);
        c += __shfl_xor_sync(0xffffffffu, c, 1);
        if (hh == 0) { g_S[e] = s; g_C[e] = c; }
    }
}

// ---------------- kernel 1: fused LN(x) + all projections + gate + mask ----------
// fp16 path: x loaded straight to registers, LN'd, written fp16 to smem A once.
// W streamed fp16 2-buffer with pair-local refill + pair barriers.
__global__ void __launch_bounds__(256, 2) proj_kernel(const float* __restrict__ x,
                                                      const float* __restrict__ mask,
                                                      const float* __restrict__ niw,
                                                      const float* __restrict__ nib) {
    extern __shared__ __half smh[];
    __half* sAh = smh;                       // [128][STHA] = 17408 halves
    __half* WBh = smh + 17408;               // 2 x WBH halves
    float*  fr  = (float*)(smh + 17408 + 2 * WBH);   // byte 55296
    float* msk = fr;                         // 128
    float* wv  = fr + 128;                   // 128
    float* bv  = fr + 256;                   // 128
    int rt = blockIdx.x;
    int i = rt / 6, k0 = (rt % 6) * 128;
    int tid = threadIdx.x;

    if (tid < 128) {
        msk[tid] = mask[i * 768 + k0 + tid];
        wv[tid]  = niw[tid];
        bv[tid]  = nib[tid];
    }

    const float* Xb = x + (size_t)(i * 768 + k0) * 128;

    int warp = tid >> 5, lane = tid & 31;
    int pid  = warp & 3;                     // pair id (warps pid, pid+4)
    int barid = 1 + pid;
    int tau  = ((warp >> 2) << 5) + lane;    // 0..63 within pair

    // pair-partitioned fp16 W chunk load: rows [32*pid, +32), 32 halves wide
    auto ldW_pair = [&](int buf, int w, int ch) {
#pragma unroll
        for (int t = 0; t < 2; t++) {
            int u = t * 64 + tau;            // 0..127 sixteen-byte units
            int r = (pid << 5) + (u >> 2);
            int c8 = (u & 3) * 8;            // half offset
            cpa(WBh + buf * WBH + r * STH + c8,
                g_Wc + (size_t)w * 16384 + (size_t)r * 128 + ch * 32 + c8);
        }
    };

    ldW_pair(0, 0, 0); cp_commit();
    ldW_pair(1, 0, 1); cp_commit();
    __syncthreads();                         // wv/bv/msk visible

    // LN: 4 threads per row, values in registers, fp16 A written once.
    {
        int h = tid & 3, q = tid >> 2;
#pragma unroll 1
        for (int p = 0; p < 2; p++) {
            int r = p * 64 + q;
            const float4* Xr = (const float4*)(Xb + (size_t)r * 128);
            float4 v[8];
#pragma unroll
            for (int t = 0; t < 8; t++) v[t] = Xr[h + 4 * t];
            float s = 0.0f, s2 = 0.0f;
#pragma unroll
            for (int t = 0; t < 8; t++) {
                s  += v[t].x + v[t].y + v[t].z + v[t].w;
                s2 += v[t].x * v[t].x + v[t].y * v[t].y + v[t].z * v[t].z + v[t].w * v[t].w;
            }
            s  += __shfl_xor_sync(0xffffffffu, s,  1);
            s2 += __shfl_xor_sync(0xffffffffu, s2, 1);
            s  += __shfl_xor_sync(0xffffffffu, s,  2);
            s2 += __shfl_xor_sync(0xffffffffu, s2, 2);
            float m   = s * (1.0f / 128.0f);
            float var = s2 * (1.0f / 128.0f) - m * m;
            float inv = rsqrtf(var + 1e-5f);
#pragma unroll
            for (int t = 0; t < 8; t++) {
                int c = (h + 4 * t) * 4;
                __half2 lo = __floats2half2_rn((v[t].x - m) * inv * wv[c]     + bv[c],
                                               (v[t].y - m) * inv * wv[c + 1] + bv[c + 1]);
                __half2 hi = __floats2half2_rn((v[t].z - m) * inv * wv[c + 2] + bv[c + 2],
                                               (v[t].w - m) * inv * wv[c + 3] + bv[c + 3]);
                *(__half2*)(sAh + r * STHA + c)     = lo;
                *(__half2*)(sAh + r * STHA + c + 2) = hi;
            }
        }
    }
    __syncthreads();                         // publish fp16 A

    int wm = (warp >> 2) * 64, wn = (warp & 3) * 32;
    int qr = lane >> 2, qc = lane & 3;

#pragma unroll 1
    for (int w = 0; w < 5; w++) {
        float acc[4][4][4] = {};
#pragma unroll 1
        for (int c = 0; c < 4; c++) {
            cp_wait<1>();
            pair_bar(barid);                 // pair's loads for this buffer visible
            gemm_c32h(sAh, WBh + (c & 1) * WBH, acc, wm, wn, lane, c * 32);
            pair_bar(barid);                 // pair done reading before refill
            if (c < 2)       ldW_pair(c & 1, w, c + 2);
            else if (w < 4)  ldW_pair(c & 1, w + 1, c - 2);
            cp_commit();
        }

        if (w == 4) {
#pragma unroll
            for (int mt = 0; mt < 4; mt++)
#pragma unroll
                for (int nt = 0; nt < 4; nt++) {
                    int rm0 = wm + mt * 16 + qr, rm1 = rm0 + 8;
                    int cn = wn + nt * 8 + qc * 2;
                    size_t r0 = (size_t)(i * 768 + k0 + rm0) * 128 + cn;
                    size_t r1 = (size_t)(i * 768 + k0 + rm1) * 128 + cn;
                    *(__half2*)&g_G[r0] = __floats2half2_rn(
                        1.0f / (1.0f + __expf(-acc[mt][nt][0])),
                        1.0f / (1.0f + __expf(-acc[mt][nt][1])));
                    *(__half2*)&g_G[r1] = __floats2half2_rn(
                        1.0f / (1.0f + __expf(-acc[mt][nt][2])),
                        1.0f / (1.0f + __expf(-acc[mt][nt][3])));
                }
        } else {
            bool isA = (w < 2);
#pragma unroll
            for (int mt = 0; mt < 4; mt++)
#pragma unroll
                for (int nt = 0; nt < 4; nt++) {
                    int rm0 = wm + mt * 16 + qr, rm1 = rm0 + 8;
                    int chl = (wn >> 1) + nt * 4 + qc;
                    float v0 = acc[mt][nt][1] * (1.0f / (1.0f + __expf(-acc[mt][nt][0])));
                    float v1 = acc[mt][nt][3] * (1.0f / (1.0f + __expf(-acc[mt][nt][2])));
                    if (isA) { v0 *= msk[rm0]; v1 *= msk[rm1]; }
                    int ch = w * 64 + chl;
                    __half* dst = (ch < 128) ? (g_A + (size_t)ch * NN)
                                             : (g_B + (size_t)(ch - 128) * NN);
                    dst[i * 768 + k0 + rm0] = __float2half_rn(v0);
                    dst[i * 768 + k0 + rm1] = __float2half_rn(v1);
                }
        }
    }
}

// ---------------- kernel 2: batched einsum  t_d = A_d @ B_d^T (fp16 HMMA) --------
__global__ void __launch_bounds__(128, 2) bgemm_kernel() {
    extern __shared__ __half smh[];
    int jt = blockIdx.x, it = blockIdx.y, d = blockIdx.z;
    int tid = threadIdx.x;
    const __half* Ab = g_A + (size_t)d * NN + (size_t)(it * 128) * 768;
    const __half* Bb = g_B + (size_t)d * NN + (size_t)(jt * 128) * 768;

    auto ld = [&](int s, int kc) {
        __half* S = smh + s * STG_H;
#pragma unroll
        for (int t = 0; t < 8; t++) {
            int idx = t * 128 + tid;
            int r = idx >> 2, c = (idx & 3) * 8;
            const __half* g = (r < 128) ? Ab + (size_t)r * 768 + kc + c
                                        : Bb + (size_t)(r - 128) * 768 + kc + c;
            cpa(S + r * STH + c, g);
        }
    };

    int wid = tid >> 5, lane = tid & 31;
    int wm = (wid >> 1) * 64, wn = (wid & 1) * 64;
    int qr = lane >> 2, qc = lane & 3;
    float acc[4][8][4] = {};

    ld(0, 0);  cp_commit();
    ld(1, 32); cp_commit();
#pragma unroll 1
    for (int c = 0; c < 24; c++) {
        cp_wait<1>();
        __syncthreads();
        int kn = (c + 2) * 32;
        if (kn < 768) ld((c + 2) % 3, kn);
        cp_commit();
        __half* S = smh + (c % 3) * STG_H;
        gemm64h(S, S + 128 * STH, acc, wm, wn, lane);
    }

    float* outp = g_T + (size_t)d * NN;
#pragma unroll
    for (int mt = 0; mt < 4; mt++)
#pragma unroll
        for (int nt = 0; nt < 8; nt++) {
            int rm0 = it * 128 + wm + mt * 16 + qr;
            int cn  = jt * 128 + wn + nt * 8 + qc * 2;
            *(float2*)&outp[(size_t)rm0 * 768 + cn]       = make_float2(acc[mt][nt][0], acc[mt][nt][1]);
            *(float2*)&outp[(size_t)(rm0 + 8) * 768 + cn] = make_float2(acc[mt][nt][2], acc[mt][nt][3]);
        }
}

// ---------------- kernel 3: LN(t) folded into GEMM + gate ------------------------
__global__ void __launch_bounds__(256, 2) final_kernel(float* __restrict__ out) {
    extern __shared__ float sm[];
    float* sT   = sm;               // 128 d x 72 (64 j used)
    float* sW   = sm + 9216;        // 128 e x 132
    float* sS   = sm + 26112;       // 128
    float* sC   = sm + 26240;       // 128
    float* smm  = sm + 26368;       // 64
    float* sinv = sm + 26432;       // 64
    float* sred = sm + 26496;       // 512
    int jt = blockIdx.x;
    int i  = blockIdx.y;
    int j0 = jt * 64;
    int tid = threadIdx.x;

    const float* Tg = g_T + (size_t)i * 768 + j0;
#pragma unroll
    for (int t = 0; t < 8; t++) {
        int idx = t * 256 + tid;
        int dd = idx >> 4, c4 = (idx & 15) * 4;
        cpa(&sT[dd * 72 + c4], &Tg[(size_t)dd * NN + c4]);
    }
#pragma unroll
    for (int t = 0; t < 16; t++) {
        int idx = t * 256 + tid;
        int r = idx >> 5, c4 = (idx & 31) * 4;
        cpa(&sW[r * 132 + c4], &g_Pw[(size_t)r * 128 + c4]);
    }
    if (tid < 128) { sS[tid] = g_S[tid]; sC[tid] = g_C[tid]; }
    cp_commit();
    cp_wait<0>();
    __syncthreads();

    {
        int h2 = tid >> 6, j = tid & 63;
        float s = 0.0f, s2 = 0.0f;
#pragma unroll 8
        for (int kk = 0; kk < 32; kk++) {
            int dd = h2 * 32 + kk;
            float v = sT[dd * 72 + j];
            s += v; s2 += v * v;
        }
        sred[h2 * 64 + j] = s;
        sred[256 + h2 * 64 + j] = s2;
    }
    __syncthreads();
    if (tid < 64) {
        float s  = sred[tid] + sred[64 + tid] + sred[128 + tid] + sred[192 + tid];
        float s2 = sred[256 + tid] + sred[320 + tid] + sred[384 + tid] + sred[448 + tid];
        float m   = s * (1.0f / 128.0f);
        float var = s2 * (1.0f / 128.0f) - m * m;
        smm[tid]  = m;
        sinv[tid] = rsqrtf(var + 1e-5f);
    }
    __syncthreads();

    int warp = tid >> 5, lane = tid & 31;
    int wm = (warp & 3) * 16, wn = (warp >> 2) * 64;
    int qr = lane >> 2, qc = lane & 3;
    int lr = lane & 7, grp = lane >> 3;
    float acc[8][4] = {};

    uint32_t bb = (uint32_t)__cvta_generic_to_shared(sW);
    uint32_t boff = bb + (uint32_t)(((wn + lr) * 132 + grp * 4) * 4);

#pragma unroll
    for (int kp = 0; kp < 8; kp++) {
        unsigned bf[8][4];
#pragma unroll
        for (int nt = 0; nt < 8; nt++)
            ldsm4(bf[nt], boff + (uint32_t)(nt * 8 * 132 * 4 + kp * 64));
#pragma unroll
        for (int ks = 0; ks < 2; ks++) {
            int k = kp * 16 + ks * 8;
            unsigned af[4];
            {
                int r = wm + qr;
                const float* p0 = sT + (k + qc) * 72 + r;
                const float* p1 = sT + (k + qc + 4) * 72 + r;
                af[0] = __float_as_uint(p0[0]);
                af[1] = __float_as_uint(p0[8]);
                af[2] = __float_as_uint(p1[0]);
                af[3] = __float_as_uint(p1[8]);
            }
#pragma unroll
            for (int nt = 0; nt < 8; nt++)
                mma8(acc[nt], af, &bf[nt][ks * 2]);
        }
    }

    int rj = wm + qr;
    float inv0 = sinv[rj],     mb0 = -inv0 * smm[rj];
    float inv1 = sinv[rj + 8], mb1 = -inv1 * smm[rj + 8];
#pragma unroll
    for (int nt = 0; nt < 8; nt++) {
        int e = wn + nt * 8 + qc * 2;
        float S0 = sS[e], S1 = sS[e + 1];
        float C0 = sC[e], C1 = sC[e + 1];
        size_t ro0 = (size_t)(i * 768 + j0 + rj) * 128 + e;
        size_t ro1 = ro0 + 8 * 128;
        float2 gt0 = __half22float2(*(const __half2*)&g_G[ro0]);
        float2 gt1 = __half22float2(*(const __half2*)&g_G[ro1]);
        *(float2*)&out[ro0] = make_float2(gt0.x * (inv0 * acc[nt][0] + mb0 * S0 + C0),
                                          gt0.y * (inv0 * acc[nt][1] + mb0 * S1 + C1));
        *(float2*)&out[ro1] = make_float2(gt1.x * (inv1 * acc[nt][2] + mb1 * S0 + C0),
                                          gt1.y * (inv1 * acc[nt][3] + mb1 * S1 + C1));
    }
}

// ---------------- launch ---------------------------------------------------------
extern "C" void kernel_launch(void* const* d_in, const int* in_sizes, int n_in,
                              void* d_out, int out_size) {
    const float* x    = (const float*)d_in[0];
    const float* mask = (const float*)d_in[1];
    const float* niw  = (const float*)d_in[2];
    const float* nib  = (const float*)d_in[3];
    const float* giw  = (const float*)d_in[4];
    const float* piw  = (const float*)d_in[5];
    const float* now  = (const float*)d_in[6];
    const float* nob  = (const float*)d_in[7];
    const float* gow  = (const float*)d_in[8];
    const float* pwo  = (const float*)d_in[9];
    float* out = (float*)d_out;

    size_t sm_proj  = (size_t)(17408 + 2 * WBH) * 2 + 384 * 4;   // 56832 B
    size_t sm_bgemm = (size_t)(3 * STG_H) * 2;                   // 61440 B
    size_t sm_final = 27008 * 4;                                 // 108032 B
    cudaFuncSetAttribute(proj_kernel,  cudaFuncAttributeMaxDynamicSharedMemorySize, (int)sm_proj);
    cudaFuncSetAttribute(bgemm_kernel, cudaFuncAttributeMaxDynamicSharedMemorySize, (int)sm_bgemm);
    cudaFuncSetAttribute(final_kernel, cudaFuncAttributeMaxDynamicSharedMemorySize, (int)sm_final);

    prep_w_kernel<<<64, 256>>>(giw, piw, gow, pwo, now, nob);
    proj_kernel<<<4608, 256, sm_proj>>>(x, mask, niw, nib);
    bgemm_kernel<<<dim3(6, 6, 128), 128, sm_bgemm>>>();
    final_kernel<<<dim3(12, 768), 256, sm_final>>>(out);
}

// round 17
// speedup vs baseline: 2.1903x; 1.0677x over previous
#include <cuda_runtime.h>
#include <cuda_fp16.h>
#include <cstdint>

#define NN (768*768)
#define STH 40           // bgemm smem row stride (halves) = 80 B
#define STG_H 10240      // halves per bgemm stage: 256 rows * 40
#define STHA 136         // proj A / final W smem row stride (halves) = 272 B
#define WBH 5120         // halves per proj W chunk buffer: 128 rows * 40

// ---------------- scratch -----------------------------------------------------
__device__ __half g_A [(size_t)128 * NN];  // a transposed: [d][i*768+k], fp16
__device__ __half g_B [(size_t)128 * NN];  // b transposed: [d][j*768+k], fp16
__device__ __half g_T [(size_t)128 * NN];  // t transposed: [d][i*768+j], fp16
__device__ __half g_G [(size_t)NN * 128];  // sigmoid(xn @ g_out_w), [r][e], fp16
__device__ __half g_Wc[640 * 128];         // fp16: rows 0..511 interleaved (g,p); 512..639 g_out_w
__device__ __half g_Pw[128 * 128];         // W' = now_w[d]*p_out_w[e,d], fp16
__device__ float  g_S [128];               // S[e] = sum_d half(now_w[d]*p_out_w[e,d])
__device__ float  g_C [128];               // C[e] = sum_d now_b[d]*p_out_w[e,d]

// ---------------- helpers ------------------------------------------------------
__device__ __forceinline__ void mma16h(float c[4], const unsigned a[4], const unsigned b[2]) {
    asm volatile(
        "mma.sync.aligned.m16n8k16.row.col.f32.f16.f16.f32 "
        "{%0,%1,%2,%3},{%4,%5,%6,%7},{%8,%9},{%0,%1,%2,%3};"
        : "+f"(c[0]), "+f"(c[1]), "+f"(c[2]), "+f"(c[3])
        : "r"(a[0]), "r"(a[1]), "r"(a[2]), "r"(a[3]), "r"(b[0]), "r"(b[1]));
}

__device__ __forceinline__ void ldsm4(unsigned r[4], uint32_t a) {
    asm volatile("ldmatrix.sync.aligned.m8n8.x4.shared.b16 {%0,%1,%2,%3}, [%4];"
        : "=r"(r[0]), "=r"(r[1]), "=r"(r[2]), "=r"(r[3]) : "r"(a));
}
__device__ __forceinline__ void ldsm4t(unsigned r[4], uint32_t a) {
    asm volatile("ldmatrix.sync.aligned.m8n8.x4.trans.shared.b16 {%0,%1,%2,%3}, [%4];"
        : "=r"(r[0]), "=r"(r[1]), "=r"(r[2]), "=r"(r[3]) : "r"(a));
}

__device__ __forceinline__ void cpa(void* s, const void* g) {
    unsigned sa = (unsigned)__cvta_generic_to_shared(s);
    asm volatile("cp.async.cg.shared.global [%0], [%1], 16;" :: "r"(sa), "l"(g));
}
__device__ __forceinline__ void cp_commit() { asm volatile("cp.async.commit_group;"); }
template<int Nw> __device__ __forceinline__ void cp_wait() {
    asm volatile("cp.async.wait_group %0;" :: "n"(Nw));
}
__device__ __forceinline__ void pair_bar(int id) {
    asm volatile("bar.sync %0, 64;" :: "r"(id) : "memory");
}

// fp16 64x64 warp tile, one K-chunk of 32 (bgemm). m16n8k16, fragments via ldmatrix.
__device__ __forceinline__ void gemm64h(const __half* sA, const __half* sB,
                                        float acc[4][8][4],
                                        int wm, int wn, int lane) {
    uint32_t ab = (uint32_t)__cvta_generic_to_shared(sA);
    uint32_t bb = (uint32_t)__cvta_generic_to_shared(sB);
    int lr = lane & 7, grp = lane >> 3;
    uint32_t aoff = ab + (uint32_t)(((wm + lr + (grp & 1) * 8) * STH) * 2 + (grp >> 1) * 16);
    uint32_t boff = bb + (uint32_t)(((wn + lr + (grp >> 1) * 8) * STH) * 2 + (grp & 1) * 16);
#pragma unroll
    for (int ks = 0; ks < 2; ks++) {
        unsigned bf[4][4];
#pragma unroll
        for (int np = 0; np < 4; np++)
            ldsm4(bf[np], boff + (uint32_t)(np * 16 * STH * 2 + ks * 32));
        unsigned af[4][4];
#pragma unroll
        for (int mt = 0; mt < 4; mt++)
            ldsm4(af[mt], aoff + (uint32_t)(mt * 16 * STH * 2 + ks * 32));
#pragma unroll
        for (int mt = 0; mt < 4; mt++)
#pragma unroll
            for (int nt = 0; nt < 8; nt++)
                mma16h(acc[mt][nt], af[mt], &bf[nt >> 1][(nt & 1) * 2]);
    }
}

// fp16 64x32 warp tile, one K-chunk of 32 (proj). A stride STHA, B stride STH.
__device__ __forceinline__ void gemm_c32h(const __half* sA, const __half* sB,
                                          float acc[4][4][4],
                                          int wm, int wn, int lane, int kbase) {
    uint32_t ab = (uint32_t)__cvta_generic_to_shared(sA);
    uint32_t bb = (uint32_t)__cvta_generic_to_shared(sB);
    int lr = lane & 7, grp = lane >> 3;
    uint32_t aoff = ab + (uint32_t)((wm + lr + (grp & 1) * 8) * STHA * 2 + (grp >> 1) * 16 + kbase * 2);
    uint32_t boff = bb + (uint32_t)((wn + lr + (grp >> 1) * 8) * STH * 2 + (grp & 1) * 16);
#pragma unroll
    for (int ks = 0; ks < 2; ks++) {
        unsigned bf[2][4];
#pragma unroll
        for (int np = 0; np < 2; np++)
            ldsm4(bf[np], boff + (uint32_t)(np * 16 * STH * 2 + ks * 32));
        unsigned af[4][4];
#pragma unroll
        for (int mt = 0; mt < 4; mt++)
            ldsm4(af[mt], aoff + (uint32_t)(mt * 16 * STHA * 2 + ks * 32));
#pragma unroll
        for (int mt = 0; mt < 4; mt++)
#pragma unroll
            for (int nt = 0; nt < 4; nt++)
                mma16h(acc[mt][nt], af[mt], &bf[nt >> 1][(nt & 1) * 2]);
    }
}

// ---------------- kernel 0: weight prep ----------------------------------------
__global__ void prep_w_kernel(const float* __restrict__ gin, const float* __restrict__ pin,
                              const float* __restrict__ gout, const float* __restrict__ pout,
                              const float* __restrict__ now, const float* __restrict__ nob) {
    int stride = gridDim.x * blockDim.x;
    int tid = threadIdx.x;
    for (int idx = blockIdx.x * blockDim.x + tid; idx < 256 * 128; idx += stride) {
        int e = idx >> 7, d = idx & 127;
        g_Wc[(2 * e) * 128 + d]     = __float2half_rn(gin[idx]);
        g_Wc[(2 * e + 1) * 128 + d] = __float2half_rn(pin[idx]);
    }
    for (int idx = blockIdx.x * blockDim.x + tid; idx < 128 * 128; idx += stride) {
        g_Wc[512 * 128 + idx] = __float2half_rn(gout[idx]);
        g_Pw[idx]             = __float2half_rn(pout[idx] * now[idx & 127]);   // W'
    }
    if (blockIdx.x == 0) {
        int e = tid >> 1, hh = tid & 1;
        float s = 0.0f, c = 0.0f;
        for (int d = hh * 64; d < hh * 64 + 64; d++) {
            float p = pout[e * 128 + d];
            s += __half2float(__float2half_rn(now[d] * p));   // match rounded W'
            c += nob[d] * p;
        }
        s += __shfl_xor_sync(0xffffffffu, s, 1);
        c += __shfl_xor_sync(0xffffffffu, c, 1);
        if (hh == 0) { g_S[e] = s; g_C[e] = c; }
    }
}

// ---------------- kernel 1: fused LN(x) + all projections + gate + mask ----------
__global__ void __launch_bounds__(256, 2) proj_kernel(const float* __restrict__ x,
                                                      const float* __restrict__ mask,
                                                      const float* __restrict__ niw,
                                                      const float* __restrict__ nib) {
    extern __shared__ __half smh[];
    __half* sAh = smh;                       // [128][STHA]
    __half* WBh = smh + 17408;               // 2 x WBH
    float*  fr  = (float*)(smh + 17408 + 2 * WBH);
    float* msk = fr;
    float* wv  = fr + 128;
    float* bv  = fr + 256;
    int rt = blockIdx.x;
    int i = rt / 6, k0 = (rt % 6) * 128;
    int tid = threadIdx.x;

    if (tid < 128) {
        msk[tid] = mask[i * 768 + k0 + tid];
        wv[tid]  = niw[tid];
        bv[tid]  = nib[tid];
    }

    const float* Xb = x + (size_t)(i * 768 + k0) * 128;

    int warp = tid >> 5, lane = tid & 31;
    int pid  = warp & 3;
    int barid = 1 + pid;
    int tau  = ((warp >> 2) << 5) + lane;

    auto ldW_pair = [&](int buf, int w, int ch) {
#pragma unroll
        for (int t = 0; t < 2; t++) {
            int u = t * 64 + tau;
            int r = (pid << 5) + (u >> 2);
            int c8 = (u & 3) * 8;
            cpa(WBh + buf * WBH + r * STH + c8,
                g_Wc + (size_t)w * 16384 + (size_t)r * 128 + ch * 32 + c8);
        }
    };

    ldW_pair(0, 0, 0); cp_commit();
    ldW_pair(1, 0, 1); cp_commit();
    __syncthreads();

    // LN: 4 threads per row, values in registers, fp16 A written once.
    {
        int h = tid & 3, q = tid >> 2;
#pragma unroll 1
        for (int p = 0; p < 2; p++) {
            int r = p * 64 + q;
            const float4* Xr = (const float4*)(Xb + (size_t)r * 128);
            float4 v[8];
#pragma unroll
            for (int t = 0; t < 8; t++) v[t] = Xr[h + 4 * t];
            float s = 0.0f, s2 = 0.0f;
#pragma unroll
            for (int t = 0; t < 8; t++) {
                s  += v[t].x + v[t].y + v[t].z + v[t].w;
                s2 += v[t].x * v[t].x + v[t].y * v[t].y + v[t].z * v[t].z + v[t].w * v[t].w;
            }
            s  += __shfl_xor_sync(0xffffffffu, s,  1);
            s2 += __shfl_xor_sync(0xffffffffu, s2, 1);
            s  += __shfl_xor_sync(0xffffffffu, s,  2);
            s2 += __shfl_xor_sync(0xffffffffu, s2, 2);
            float m   = s * (1.0f / 128.0f);
            float var = s2 * (1.0f / 128.0f) - m * m;
            float inv = rsqrtf(var + 1e-5f);
#pragma unroll
            for (int t = 0; t < 8; t++) {
                int c = (h + 4 * t) * 4;
                __half2 lo = __floats2half2_rn((v[t].x - m) * inv * wv[c]     + bv[c],
                                               (v[t].y - m) * inv * wv[c + 1] + bv[c + 1]);
                __half2 hi = __floats2half2_rn((v[t].z - m) * inv * wv[c + 2] + bv[c + 2],
                                               (v[t].w - m) * inv * wv[c + 3] + bv[c + 3]);
                *(__half2*)(sAh + r * STHA + c)     = lo;
                *(__half2*)(sAh + r * STHA + c + 2) = hi;
            }
        }
    }
    __syncthreads();

    int wm = (warp >> 2) * 64, wn = (warp & 3) * 32;
    int qr = lane >> 2, qc = lane & 3;

#pragma unroll 1
    for (int w = 0; w < 5; w++) {
        float acc[4][4][4] = {};
#pragma unroll 1
        for (int c = 0; c < 4; c++) {
            cp_wait<1>();
            pair_bar(barid);
            gemm_c32h(sAh, WBh + (c & 1) * WBH, acc, wm, wn, lane, c * 32);
            pair_bar(barid);
            if (c < 2)       ldW_pair(c & 1, w, c + 2);
            else if (w < 4)  ldW_pair(c & 1, w + 1, c - 2);
            cp_commit();
        }

        if (w == 4) {
#pragma unroll
            for (int mt = 0; mt < 4; mt++)
#pragma unroll
                for (int nt = 0; nt < 4; nt++) {
                    int rm0 = wm + mt * 16 + qr, rm1 = rm0 + 8;
                    int cn = wn + nt * 8 + qc * 2;
                    size_t r0 = (size_t)(i * 768 + k0 + rm0) * 128 + cn;
                    size_t r1 = (size_t)(i * 768 + k0 + rm1) * 128 + cn;
                    *(__half2*)&g_G[r0] = __floats2half2_rn(
                        1.0f / (1.0f + __expf(-acc[mt][nt][0])),
                        1.0f / (1.0f + __expf(-acc[mt][nt][1])));
                    *(__half2*)&g_G[r1] = __floats2half2_rn(
                        1.0f / (1.0f + __expf(-acc[mt][nt][2])),
                        1.0f / (1.0f + __expf(-acc[mt][nt][3])));
                }
        } else {
            bool isA = (w < 2);
#pragma unroll
            for (int mt = 0; mt < 4; mt++)
#pragma unroll
                for (int nt = 0; nt < 4; nt++) {
                    int rm0 = wm + mt * 16 + qr, rm1 = rm0 + 8;
                    int chl = (wn >> 1) + nt * 4 + qc;
                    float v0 = acc[mt][nt][1] * (1.0f / (1.0f + __expf(-acc[mt][nt][0])));
                    float v1 = acc[mt][nt][3] * (1.0f / (1.0f + __expf(-acc[mt][nt][2])));
                    if (isA) { v0 *= msk[rm0]; v1 *= msk[rm1]; }
                    int ch = w * 64 + chl;
                    __half* dst = (ch < 128) ? (g_A + (size_t)ch * NN)
                                             : (g_B + (size_t)(ch - 128) * NN);
                    dst[i * 768 + k0 + rm0] = __float2half_rn(v0);
                    dst[i * 768 + k0 + rm1] = __float2half_rn(v1);
                }
        }
    }
}

// ---------------- kernel 2: batched einsum  t_d = A_d @ B_d^T (fp16 HMMA) --------
__global__ void __launch_bounds__(128, 2) bgemm_kernel() {
    extern __shared__ __half smh[];
    int jt = blockIdx.x, it = blockIdx.y, d = blockIdx.z;
    int tid = threadIdx.x;
    const __half* Ab = g_A + (size_t)d * NN + (size_t)(it * 128) * 768;
    const __half* Bb = g_B + (size_t)d * NN + (size_t)(jt * 128) * 768;

    auto ld = [&](int s, int kc) {
        __half* S = smh + s * STG_H;
#pragma unroll
        for (int t = 0; t < 8; t++) {
            int idx = t * 128 + tid;
            int r = idx >> 2, c = (idx & 3) * 8;
            const __half* g = (r < 128) ? Ab + (size_t)r * 768 + kc + c
                                        : Bb + (size_t)(r - 128) * 768 + kc + c;
            cpa(S + r * STH + c, g);
        }
    };

    int wid = tid >> 5, lane = tid & 31;
    int wm = (wid >> 1) * 64, wn = (wid & 1) * 64;
    int qr = lane >> 2, qc = lane & 3;
    float acc[4][8][4] = {};

    ld(0, 0);  cp_commit();
    ld(1, 32); cp_commit();
#pragma unroll 1
    for (int c = 0; c < 24; c++) {
        cp_wait<1>();
        __syncthreads();
        int kn = (c + 2) * 32;
        if (kn < 768) ld((c + 2) % 3, kn);
        cp_commit();
        __half* S = smh + (c % 3) * STG_H;
        gemm64h(S, S + 128 * STH, acc, wm, wn, lane);
    }

    __half* outp = g_T + (size_t)d * NN;
#pragma unroll
    for (int mt = 0; mt < 4; mt++)
#pragma unroll
        for (int nt = 0; nt < 8; nt++) {
            int rm0 = it * 128 + wm + mt * 16 + qr;
            int cn  = jt * 128 + wn + nt * 8 + qc * 2;
            *(__half2*)&outp[(size_t)rm0 * 768 + cn]       = __floats2half2_rn(acc[mt][nt][0], acc[mt][nt][1]);
            *(__half2*)&outp[(size_t)(rm0 + 8) * 768 + cn] = __floats2half2_rn(acc[mt][nt][2], acc[mt][nt][3]);
        }
}

// ---------------- kernel 3: LN(t) folded into fp16 GEMM + gate -------------------
// One block = 64 j x 128 e. t fp16 [d][j] in smem; A operand via ldmatrix.trans.
// W' fp16 (stride STHA). out = gate * (inv*(t@W') - inv*m*S + C).
__global__ void __launch_bounds__(256, 3) final_kernel(float* __restrict__ out) {
    extern __shared__ __half smh[];
    __half* sT = smh;                        // [128 d][72 j] halves
    __half* sW = smh + 9216;                 // [128 e][STHA] halves
    float*  fr = (float*)(smh + 9216 + 17408);
    float* sS   = fr;                        // 128
    float* sC   = fr + 128;                  // 128
    float* smm  = fr + 256;                  // 64
    float* sinv = fr + 320;                  // 64
    float* sred = fr + 384;                  // 512
    int jt = blockIdx.x;
    int i  = blockIdx.y;
    int j0 = jt * 64;
    int tid = threadIdx.x;

    const __half* Tg = g_T + (size_t)i * 768 + j0;
#pragma unroll
    for (int t = 0; t < 4; t++) {            // 128 rows x 64 halves = 8 x 16B per row
        int idx = t * 256 + tid;
        int dd = idx >> 3, c8 = (idx & 7) * 8;
        cpa(sT + dd * 72 + c8, Tg + (size_t)dd * NN + c8);
    }
#pragma unroll
    for (int t = 0; t < 8; t++) {            // 128 rows x 128 halves = 16 x 16B per row
        int idx = t * 256 + tid;
        int r = idx >> 4, c8 = (idx & 15) * 8;
        cpa(sW + r * STHA + c8, g_Pw + (size_t)r * 128 + c8);
    }
    if (tid < 128) { sS[tid] = g_S[tid]; sC[tid] = g_C[tid]; }
    cp_commit();
    cp_wait<0>();
    __syncthreads();

    // stats pass over fp16 t
    {
        int h2 = tid >> 6, j = tid & 63;
        float s = 0.0f, s2 = 0.0f;
#pragma unroll 8
        for (int kk = 0; kk < 32; kk++) {
            int dd = h2 * 32 + kk;
            float v = __half2float(sT[dd * 72 + j]);
            s += v; s2 += v * v;
        }
        sred[h2 * 64 + j] = s;
        sred[256 + h2 * 64 + j] = s2;
    }
    __syncthreads();
    if (tid < 64) {
        float s  = sred[tid] + sred[64 + tid] + sred[128 + tid] + sred[192 + tid];
        float s2 = sred[256 + tid] + sred[320 + tid] + sred[384 + tid] + sred[448 + tid];
        float m   = s * (1.0f / 128.0f);
        float var = s2 * (1.0f / 128.0f) - m * m;
        smm[tid]  = m;
        sinv[tid] = rsqrtf(var + 1e-5f);
    }
    __syncthreads();

    int warp = tid >> 5, lane = tid & 31;
    int wm = (warp & 3) * 16, wn = (warp >> 2) * 64;
    int qr = lane >> 2, qc = lane & 3;
    int lr = lane & 7, grp = lane >> 3;
    float acc[8][4] = {};

    uint32_t tb = (uint32_t)__cvta_generic_to_shared(sT);
    uint32_t bb = (uint32_t)__cvta_generic_to_shared(sW);
    // A (trans): m0 (k0-7, j wm..+7) | m1 (k0-7, j+8) | m2 (k8-15, j) | m3 (k8-15, j+8)
    uint32_t aoff = tb + (uint32_t)(((lr + (grp >> 1) * 8) * 72 + wm + (grp & 1) * 8) * 2);
    uint32_t boff = bb + (uint32_t)((wn + lr + (grp >> 1) * 8) * STHA * 2 + (grp & 1) * 16);

#pragma unroll
    for (int kp = 0; kp < 8; kp++) {         // k steps of 16
        unsigned af[4];
        ldsm4t(af, aoff + (uint32_t)(kp * 16 * 72 * 2));
        unsigned bf[4][4];
#pragma unroll
        for (int np = 0; np < 4; np++)
            ldsm4(bf[np], boff + (uint32_t)(np * 16 * STHA * 2 + kp * 32));
#pragma unroll
        for (int nt = 0; nt < 8; nt++)
            mma16h(acc[nt], af, &bf[nt >> 1][(nt & 1) * 2]);
    }

    int rj = wm + qr;
    float inv0 = sinv[rj],     mb0 = -inv0 * smm[rj];
    float inv1 = sinv[rj + 8], mb1 = -inv1 * smm[rj + 8];
#pragma unroll
    for (int nt = 0; nt < 8; nt++) {
        int e = wn + nt * 8 + qc * 2;
        float S0 = sS[e], S1 = sS[e + 1];
        float C0 = sC[e], C1 = sC[e + 1];
        size_t ro0 = (size_t)(i * 768 + j0 + rj) * 128 + e;
        size_t ro1 = ro0 + 8 * 128;
        float2 gt0 = __half22float2(*(const __half2*)&g_G[ro0]);
        float2 gt1 = __half22float2(*(const __half2*)&g_G[ro1]);
        *(float2*)&out[ro0] = make_float2(gt0.x * (inv0 * acc[nt][0] + mb0 * S0 + C0),
                                          gt0.y * (inv0 * acc[nt][1] + mb0 * S1 + C1));
        *(float2*)&out[ro1] = make_float2(gt1.x * (inv1 * acc[nt][2] + mb1 * S0 + C0),
                                          gt1.y * (inv1 * acc[nt][3] + mb1 * S1 + C1));
    }
}

// ---------------- launch ---------------------------------------------------------
extern "C" void kernel_launch(void* const* d_in, const int* in_sizes, int n_in,
                              void* d_out, int out_size) {
    const float* x    = (const float*)d_in[0];
    const float* mask = (const float*)d_in[1];
    const float* niw  = (const float*)d_in[2];
    const float* nib  = (const float*)d_in[3];
    const float* giw  = (const float*)d_in[4];
    const float* piw  = (const float*)d_in[5];
    const float* now  = (const float*)d_in[6];
    const float* nob  = (const float*)d_in[7];
    const float* gow  = (const float*)d_in[8];
    const float* pwo  = (const float*)d_in[9];
    float* out = (float*)d_out;

    size_t sm_proj  = (size_t)(17408 + 2 * WBH) * 2 + 384 * 4;   // 56832 B
    size_t sm_bgemm = (size_t)(3 * STG_H) * 2;                   // 61440 B
    size_t sm_final = (size_t)(9216 + 17408) * 2 + 896 * 4;      // 56832 B
    cudaFuncSetAttribute(proj_kernel,  cudaFuncAttributeMaxDynamicSharedMemorySize, (int)sm_proj);
    cudaFuncSetAttribute(bgemm_kernel, cudaFuncAttributeMaxDynamicSharedMemorySize, (int)sm_bgemm);
    cudaFuncSetAttribute(final_kernel, cudaFuncAttributeMaxDynamicSharedMemorySize, (int)sm_final);

    prep_w_kernel<<<64, 256>>>(giw, piw, gow, pwo, now, nob);
    proj_kernel<<<4608, 256, sm_proj>>>(x, mask, niw, nib);
    bgemm_kernel<<<dim3(6, 6, 128), 128, sm_bgemm>>>();
    final_kernel<<<dim3(12, 768), 256, sm_final>>>(out);
}